// round 6
// baseline (speedup 1.0000x reference)
#include <cuda_runtime.h>
#include <cstdint>
#include <math.h>

#define B_  4
#define H_  16
#define N_  2048
#define Dh_ 64
#define DIM_ 1024
#define M_  (B_*N_)          // 8192
#define ELEMS (B_*H_*N_*Dh_) // 8388608

__device__ __align__(16) float g_q[ELEMS];
__device__ __align__(16) float g_k[ELEMS];
__device__ __align__(16) float g_v[ELEMS];
__device__ __align__(16) float g_o[ELEMS];

// f32 -> tf32 (round-to-nearest on 10-bit mantissa)
__device__ __forceinline__ uint32_t f2tf(float f) {
    uint32_t u;
    asm("cvt.rna.tf32.f32 %0, %1;" : "=r"(u) : "f"(f));
    return u;
}
__device__ __forceinline__ float f2tf_f(float f) {
    return __uint_as_float(f2tf(f));
}
__device__ __forceinline__ uint32_t smem_u32(const void* p) {
    uint32_t a;
    asm("{ .reg .u64 t; cvta.to.shared.u64 t, %1; cvt.u32.u64 %0, t; }"
        : "=r"(a) : "l"(p));
    return a;
}

#define MMA_TF32(c, a, b) \
    asm volatile("mma.sync.aligned.m16n8k8.row.col.f32.tf32.tf32.f32 " \
        "{%0,%1,%2,%3},{%4,%5,%6,%7},{%8,%9},{%0,%1,%2,%3};" \
        : "+f"((c)[0]), "+f"((c)[1]), "+f"((c)[2]), "+f"((c)[3]) \
        : "r"((a)[0]), "r"((a)[1]), "r"((a)[2]), "r"((a)[3]), \
          "r"((b)[0]), "r"((b)[1]))

// ---------------------------------------------------------------------------
// tf32 mma GEMM with FRAGMENT-PACKED smem tiles.
// BM=128, BN=128, BK=16, 8 warps (4M x 2N), warp tile 32x64.
// A packed: seg = (rowgrp16 * 2 + kss), entry [lane][vec] vec={a0,a1,a2,a3}
// B packed: seg = (colpair16 * 2 + kss), entry [lane][vec]
//           vec = {(k,c),(k+4,c),(k,c+8),(k+4,c+8)}  (feeds 2 MMAs)
// Segment pitch 132 words -> producer scatter hits distinct banks,
// consumer LDS.128 conflict-free.
// ---------------------------------------------------------------------------
#define SEGP 132
#define TILE_FLOATS (16 * SEGP)   // 2112 per stage per operand

template<int MODE>
__global__ void __launch_bounds__(256, 2)
mma_gemm(const float* __restrict__ A, const float* __restrict__ W,
         float* __restrict__ Cout, const float* __restrict__ bias, int Ncols)
{
    __shared__ float Apk[2][TILE_FLOATS];
    __shared__ float Bpk[2][TILE_FLOATS];

    const int tid = threadIdx.x;
    const int wid = tid >> 5, lane = tid & 31;
    const int m0 = blockIdx.y * 128;
    const int n0 = blockIdx.x * 128;
    const int warp_row = (wid & 3) * 32;
    const int warp_col = (wid >> 2) * 64;

    const int lm = tid >> 1;            // A row 0..127
    const int lq = tid & 1;             // A k half
    const int bk = tid >> 4;            // B k row 0..15
    const int bc = tid & 15;            // B col group

    // precomputed producer scatter bases
    const int a_grp = lm >> 4;
    const int a_l4 = lm & 7;
    const int a_fh = (lm >> 3) & 1;

    float acc[2][8][4];
    #pragma unroll
    for (int f = 0; f < 2; f++)
        #pragma unroll
        for (int g = 0; g < 8; g++)
            #pragma unroll
            for (int i = 0; i < 4; i++) acc[f][g][i] = 0.f;

    float4 a_st[2], b_st[2];

    auto ldg_tile = [&](int t) {
        const int k0 = t * 16;
        #pragma unroll
        for (int it = 0; it < 2; it++) {
            const int kk = (lq * 2 + it) * 4;
            if (MODE == 2) {
                int gm = m0 + lm;
                int b = gm >> 11, nn = gm & 2047;
                int k = k0 + kk, h = k >> 6, d = k & 63;
                a_st[it] = *(const float4*)&g_o[(((size_t)((b << 4) + h)) * N_ + nn) * Dh_ + d];
            } else {
                a_st[it] = *(const float4*)&A[(size_t)(m0 + lm) * DIM_ + k0 + kk];
            }
        }
        #pragma unroll
        for (int it = 0; it < 2; it++) {
            const int nn = it * 64 + bc * 4;
            b_st[it] = *(const float4*)&W[(size_t)(k0 + bk) * Ncols + n0 + nn];
        }
    };

    auto sts_tile = [&](int p) {
        // A scatter: value (row lm, k = (lq*2+it)*4 + j)
        #pragma unroll
        for (int it = 0; it < 2; it++) {
            const float va[4] = {a_st[it].x, a_st[it].y, a_st[it].z, a_st[it].w};
            #pragma unroll
            for (int j = 0; j < 4; j++) {
                const int k = (lq * 2 + it) * 4 + j;
                const int kss = k >> 3, khalf = (k >> 2) & 1, lkk = k & 3;
                const int idx = (a_grp * 2 + kss) * SEGP
                              + (a_l4 * 4 + lkk) * 4 + (a_fh + 2 * khalf);
                Apk[p][idx] = f2tf_f(va[j]);
            }
        }
        // B scatter: value (k = bk, col = it*64 + bc*4 + j)
        const int kss = bk >> 3, khalf = (bk >> 2) & 1, lkk = bk & 3;
        #pragma unroll
        for (int it = 0; it < 2; it++) {
            const float vb[4] = {b_st[it].x, b_st[it].y, b_st[it].z, b_st[it].w};
            #pragma unroll
            for (int j = 0; j < 4; j++) {
                const int col = it * 64 + bc * 4 + j;
                const int pair = col >> 4;
                const int cc = col & 15;
                const int gsub = cc >> 3, l4b = cc & 7;
                const int idx = (pair * 2 + kss) * SEGP
                              + (l4b * 4 + lkk) * 4 + (gsub * 2 + khalf);
                Bpk[p][idx] = f2tf_f(vb[j]);
            }
        }
    };

    ldg_tile(0);
    sts_tile(0);
    __syncthreads();

    const int a_seg0 = ((wid & 3) * 2) * 2;      // grp = (wid&3)*2 + f
    const int b_pair0 = (wid >> 2) * 4;          // pairs p0..p0+3

    for (int t = 0; t < DIM_ / 16; t++) {
        const int p = t & 1;
        if (t + 1 < DIM_ / 16) ldg_tile(t + 1);

        #pragma unroll
        for (int kss = 0; kss < 2; kss++) {
            uint32_t af[2][4];
            #pragma unroll
            for (int f = 0; f < 2; f++) {
                float4 a4 = *(const float4*)&Apk[p][((a_seg0 + f * 2) + kss) * SEGP + lane * 4];
                af[f][0] = __float_as_uint(a4.x);
                af[f][1] = __float_as_uint(a4.y);
                af[f][2] = __float_as_uint(a4.z);
                af[f][3] = __float_as_uint(a4.w);
            }
            #pragma unroll
            for (int pl = 0; pl < 4; pl++) {
                float4 b4 = *(const float4*)&Bpk[p][((b_pair0 + pl) * 2 + kss) * SEGP + lane * 4];
                uint32_t b0[2], b1[2];
                b0[0] = __float_as_uint(b4.x);
                b0[1] = __float_as_uint(b4.y);
                b1[0] = __float_as_uint(b4.z);
                b1[1] = __float_as_uint(b4.w);
                MMA_TF32(acc[0][2 * pl],     af[0], b0);
                MMA_TF32(acc[0][2 * pl + 1], af[0], b1);
                MMA_TF32(acc[1][2 * pl],     af[1], b0);
                MMA_TF32(acc[1][2 * pl + 1], af[1], b1);
            }
        }
        if (t + 1 < DIM_ / 16) sts_tile(p ^ 1);
        __syncthreads();
    }

    // epilogue (unchanged)
    const int l4 = lane >> 2, lk = lane & 3;
    const int r0 = m0 + warp_row + l4;
    const int c0 = n0 + warp_col + lk * 2;
    #pragma unroll
    for (int f = 0; f < 2; f++) {
        #pragma unroll
        for (int g = 0; g < 8; g++) {
            const int n = c0 + g * 8;
            #pragma unroll
            for (int half = 0; half < 2; half++) {
                const int m = r0 + f * 16 + half * 8;
                float2 v;
                v.x = acc[f][g][half * 2 + 0];
                v.y = acc[f][g][half * 2 + 1];
                if (MODE == 2) {
                    v.x += bias[n];
                    v.y += bias[n + 1];
                    *(float2*)&Cout[(size_t)m * DIM_ + n] = v;
                } else {
                    const int b = m >> 11, nn = m & 2047;
                    if (MODE == 0) {
                        v.x = f2tf_f(v.x * 0.125f);
                        v.y = f2tf_f(v.y * 0.125f);
                        const int h = n >> 6, d = n & 63;
                        *(float2*)&g_q[(((size_t)((b << 4) + h)) * N_ + nn) * Dh_ + d] = v;
                    } else {
                        v.x = f2tf_f(v.x);
                        v.y = f2tf_f(v.y);
                        float* dst = (n < 1024) ? g_k : g_v;
                        const int cc = n & 1023;
                        const int h = cc >> 6, d = cc & 63;
                        *(float2*)&dst[(((size_t)((b << 4) + h)) * N_ + nn) * Dh_ + d] = v;
                    }
                }
            }
        }
    }
}

// ---------------------------------------------------------------------------
// Flash attention v2 (unchanged from R5)
// ---------------------------------------------------------------------------
#define KSP 68
#define VSP 72
#define KS_ST (64*KSP)
#define VS_ST (64*VSP)
#define SMV  (2*KS_ST)
#define SMP  (SMV + 2*VS_ST)
#define FL2_FLOATS (SMP + 8*512)
#define FL2_BYTES  (FL2_FLOATS*4)

__global__ void __launch_bounds__(256, 2) flash2_k()
{
    extern __shared__ __align__(16) float sm[];
    const int tid = threadIdx.x;
    const int bh = blockIdx.y;
    const int rb = gridDim.x - 1 - blockIdx.x;
    const int m0 = rb * 128;

    const float* qb = g_q + (size_t)bh * N_ * Dh_;
    const float* kb = g_k + (size_t)bh * N_ * Dh_;
    const float* vb = g_v + (size_t)bh * N_ * Dh_;
    float* ob = g_o + (size_t)bh * N_ * Dh_;

    const int wid = tid >> 5, lane = tid & 31;
    const int l4 = lane >> 2, lk = lane & 3;
    const int R0 = m0 + wid * 16;

    const uint32_t smb = smem_u32(sm);
    float* Pw = sm + SMP + wid * 512;

    uint32_t aq[8][4];
    {
        const float* q0 = qb + (size_t)(R0 + l4) * Dh_;
        const float* q1 = qb + (size_t)(R0 + l4 + 8) * Dh_;
        #pragma unroll
        for (int ks = 0; ks < 8; ks++) {
            const int d = ks * 8 + lk;
            aq[ks][0] = __float_as_uint(q0[d]);
            aq[ks][1] = __float_as_uint(q1[d]);
            aq[ks][2] = __float_as_uint(q0[d + 4]);
            aq[ks][3] = __float_as_uint(q1[d + 4]);
        }
    }

    float o[8][4];
    #pragma unroll
    for (int dg = 0; dg < 8; dg++)
        #pragma unroll
        for (int i = 0; i < 4; i++) o[dg][i] = 0.f;
    float mr0 = -1e30f, mr1 = -1e30f, lr0 = 0.f, lr1 = 0.f;

    const int ntiles = 2 * rb + 2;
    const int jr = tid >> 2;
    const int cb = tid & 3;

    auto load_tile = [&](int t, int s) {
        const int j0 = t * 64;
        const float* krow = kb + (size_t)(j0 + jr) * Dh_;
        const float* vrow = vb + (size_t)(j0 + jr) * Dh_;
        const uint32_t kd0 = smb + (uint32_t)(s * KS_ST + jr * KSP) * 4;
        const uint32_t vd0 = smb + (uint32_t)(SMV + s * VS_ST + jr * VSP) * 4;
        #pragma unroll
        for (int i = 0; i < 4; i++) {
            const int d4 = (cb + i * 4) * 4;
            asm volatile("cp.async.cg.shared.global [%0], [%1], 16;"
                         :: "r"(kd0 + d4 * 4), "l"(krow + d4));
            asm volatile("cp.async.cg.shared.global [%0], [%1], 16;"
                         :: "r"(vd0 + d4 * 4), "l"(vrow + d4));
        }
    };

    load_tile(0, 0);
    asm volatile("cp.async.commit_group;" ::: "memory");
    load_tile(1, 1);
    asm volatile("cp.async.commit_group;" ::: "memory");

    const int row0 = R0 + l4;
    const int row1 = R0 + l4 + 8;

    for (int t = 0; t < ntiles; t++) {
        const int s = t & 1;
        asm volatile("cp.async.wait_group 1;" ::: "memory");
        __syncthreads();

        if (t * 64 <= R0 + 15) {
            const float* Ksm = sm + s * KS_ST;
            const float* Vsm = sm + SMV + s * VS_ST;
            #pragma unroll
            for (int jc = 0; jc < 2; jc++) {
                const int j0c = t * 64 + jc * 32;
                if (j0c > R0 + 15) break;

                float s4[4][4];
                #pragma unroll
                for (int jg = 0; jg < 4; jg++)
                    #pragma unroll
                    for (int i = 0; i < 4; i++) s4[jg][i] = 0.f;
                #pragma unroll
                for (int ks = 0; ks < 8; ks++) {
                    const int d = ks * 8 + lk;
                    #pragma unroll
                    for (int jg = 0; jg < 4; jg++) {
                        const int krow_s = (jc * 32 + jg * 8 + l4) * KSP;
                        uint32_t bq[2];
                        bq[0] = __float_as_uint(Ksm[krow_s + d]);
                        bq[1] = __float_as_uint(Ksm[krow_s + d + 4]);
                        MMA_TF32(s4[jg], aq[ks], bq);
                    }
                }

                if (j0c + 31 > R0) {
                    #pragma unroll
                    for (int jg = 0; jg < 4; jg++) {
                        const int jb = j0c + jg * 8 + 2 * lk;
                        if (jb     > row0) s4[jg][0] = -1e30f;
                        if (jb + 1 > row0) s4[jg][1] = -1e30f;
                        if (jb     > row1) s4[jg][2] = -1e30f;
                        if (jb + 1 > row1) s4[jg][3] = -1e30f;
                    }
                }

                float mx0 = -1e30f, mx1 = -1e30f;
                #pragma unroll
                for (int jg = 0; jg < 4; jg++) {
                    mx0 = fmaxf(mx0, fmaxf(s4[jg][0], s4[jg][1]));
                    mx1 = fmaxf(mx1, fmaxf(s4[jg][2], s4[jg][3]));
                }
                mx0 = fmaxf(mx0, __shfl_xor_sync(0xffffffffu, mx0, 1));
                mx0 = fmaxf(mx0, __shfl_xor_sync(0xffffffffu, mx0, 2));
                mx1 = fmaxf(mx1, __shfl_xor_sync(0xffffffffu, mx1, 1));
                mx1 = fmaxf(mx1, __shfl_xor_sync(0xffffffffu, mx1, 2));

                const float mn0 = fmaxf(mr0, mx0);
                const float mn1 = fmaxf(mr1, mx1);
                const float a0 = __expf(mr0 - mn0);
                const float a1 = __expf(mr1 - mn1);
                mr0 = mn0; mr1 = mn1;

                float sum0 = 0.f, sum1 = 0.f;
                float p[4][4];
                #pragma unroll
                for (int jg = 0; jg < 4; jg++) {
                    p[jg][0] = f2tf_f(__expf(s4[jg][0] - mn0));
                    p[jg][1] = f2tf_f(__expf(s4[jg][1] - mn0));
                    p[jg][2] = f2tf_f(__expf(s4[jg][2] - mn1));
                    p[jg][3] = f2tf_f(__expf(s4[jg][3] - mn1));
                    sum0 += p[jg][0] + p[jg][1];
                    sum1 += p[jg][2] + p[jg][3];
                }
                sum0 += __shfl_xor_sync(0xffffffffu, sum0, 1);
                sum0 += __shfl_xor_sync(0xffffffffu, sum0, 2);
                sum1 += __shfl_xor_sync(0xffffffffu, sum1, 1);
                sum1 += __shfl_xor_sync(0xffffffffu, sum1, 2);
                lr0 = lr0 * a0 + sum0;
                lr1 = lr1 * a1 + sum1;

                #pragma unroll
                for (int dg = 0; dg < 8; dg++) {
                    o[dg][0] *= a0; o[dg][1] *= a0;
                    o[dg][2] *= a1; o[dg][3] *= a1;
                }

                #pragma unroll
                for (int jg = 0; jg < 4; jg++) {
                    const int c0 = 2 * lk;
                    const int la = l4 * 4 + (c0 & 3);
                    const int rx = (c0 & 4) ? 2 : 0;
                    Pw[jg * 128 + la * 4 + rx]     = p[jg][0];
                    Pw[jg * 128 + la * 4 + rx + 1] = p[jg][2];
                    const int c1 = c0 + 1;
                    const int lb = l4 * 4 + (c1 & 3);
                    const int ry = (c1 & 4) ? 2 : 0;
                    Pw[jg * 128 + lb * 4 + ry]     = p[jg][1];
                    Pw[jg * 128 + lb * 4 + ry + 1] = p[jg][3];
                }
                __syncwarp();

                #pragma unroll
                for (int ksp = 0; ksp < 4; ksp++) {
                    float4 pa4 = *(const float4*)&Pw[ksp * 128 + lane * 4];
                    uint32_t pa[4];
                    pa[0] = __float_as_uint(pa4.x);
                    pa[1] = __float_as_uint(pa4.y);
                    pa[2] = __float_as_uint(pa4.z);
                    pa[3] = __float_as_uint(pa4.w);
                    const int vr = (jc * 32 + ksp * 8 + lk) * VSP;
                    #pragma unroll
                    for (int dg = 0; dg < 8; dg++) {
                        const int vc = dg * 8 + l4;
                        uint32_t bv[2];
                        bv[0] = __float_as_uint(Vsm[vr + vc]);
                        bv[1] = __float_as_uint(Vsm[vr + 4 * VSP + vc]);
                        MMA_TF32(o[dg], pa, bv);
                    }
                }
                __syncwarp();
            }
        }
        __syncthreads();
        if (t + 2 < ntiles) load_tile(t + 2, s);
        asm volatile("cp.async.commit_group;" ::: "memory");
    }

    const float inv0 = 1.0f / lr0;
    const float inv1 = 1.0f / lr1;
    #pragma unroll
    for (int dg = 0; dg < 8; dg++) {
        const int col = dg * 8 + 2 * lk;
        float2 v0, v1;
        v0.x = o[dg][0] * inv0; v0.y = o[dg][1] * inv0;
        v1.x = o[dg][2] * inv1; v1.y = o[dg][3] * inv1;
        *(float2*)&ob[(size_t)row0 * Dh_ + col] = v0;
        *(float2*)&ob[(size_t)row1 * Dh_ + col] = v1;
    }
}

// ---------------------------------------------------------------------------
extern "C" void kernel_launch(void* const* d_in, const int* in_sizes, int n_in,
                              void* d_out, int out_size)
{
    const float* x   = (const float*)d_in[0];
    const float* Wq  = (const float*)d_in[1];
    const float* Wkv = (const float*)d_in[2];
    const float* Wo  = (const float*)d_in[3];
    const float* bo  = (const float*)d_in[4];
    float* out = (float*)d_out;

    static bool attr_done = false;
    if (!attr_done) {
        cudaFuncSetAttribute(flash2_k, cudaFuncAttributeMaxDynamicSharedMemorySize,
                             FL2_BYTES);
        attr_done = true;
    }

    dim3 blk(256);
    mma_gemm<0><<<dim3(DIM_ / 128, M_ / 128), blk>>>(x, Wq, nullptr, nullptr, DIM_);
    mma_gemm<1><<<dim3(2 * DIM_ / 128, M_ / 128), blk>>>(x, Wkv, nullptr, nullptr, 2 * DIM_);
    flash2_k<<<dim3(N_ / 128, B_ * H_), blk, FL2_BYTES>>>();
    mma_gemm<2><<<dim3(DIM_ / 128, M_ / 128), blk>>>(nullptr, Wo, out, bo, DIM_);
}

// round 7
// speedup vs baseline: 1.0561x; 1.0561x over previous
#include <cuda_runtime.h>
#include <cstdint>
#include <math.h>

#define B_  4
#define H_  16
#define N_  2048
#define Dh_ 64
#define DIM_ 1024
#define M_  (B_*N_)          // 8192
#define ELEMS (B_*H_*N_*Dh_) // 8388608

__device__ __align__(16) float g_q[ELEMS];
__device__ __align__(16) float g_k[ELEMS];
__device__ __align__(16) float g_v[ELEMS];
__device__ __align__(16) float g_o[ELEMS];

// f32 -> tf32 (round-to-nearest on 10-bit mantissa)
__device__ __forceinline__ uint32_t f2tf(float f) {
    uint32_t u;
    asm("cvt.rna.tf32.f32 %0, %1;" : "=r"(u) : "f"(f));
    return u;
}
__device__ __forceinline__ float f2tf_f(float f) {
    return __uint_as_float(f2tf(f));
}
__device__ __forceinline__ uint32_t smem_u32(const void* p) {
    uint32_t a;
    asm("{ .reg .u64 t; cvta.to.shared.u64 t, %1; cvt.u32.u64 %0, t; }"
        : "=r"(a) : "l"(p));
    return a;
}

#define MMA_TF32(c, a, b) \
    asm volatile("mma.sync.aligned.m16n8k8.row.col.f32.tf32.tf32.f32 " \
        "{%0,%1,%2,%3},{%4,%5,%6,%7},{%8,%9},{%0,%1,%2,%3};" \
        : "+f"((c)[0]), "+f"((c)[1]), "+f"((c)[2]), "+f"((c)[3]) \
        : "r"((a)[0]), "r"((a)[1]), "r"((a)[2]), "r"((a)[3]), \
          "r"((b)[0]), "r"((b)[1]))

// ---------------------------------------------------------------------------
// tf32 mma GEMM, cp.async 3-stage pipeline, cvt at fragment load.
// BM=128, BN=128, BK=16, 8 warps (4M x 2N), warp tile 32x64.
// A smem [m][k] pitch 20 (rows 16B-aligned, fragment reads conflict-free)
// B smem [k][n] pitch 136 (8*kb bank skew, conflict-free)
// MODE 0: A=x, scatter*0.125 -> g_q (tf32-rounded)
// MODE 1: A=x, scatter -> g_k/g_v (tf32-rounded)
// MODE 2: A=gather(g_o head-major), +bias -> Cout
// ---------------------------------------------------------------------------
#define APIT 20
#define BPIT 136
#define A_ST (128*APIT)                 // 2560 floats
#define B_ST (16*BPIT)                  // 2176 floats
#define STAGE_F (A_ST + B_ST)           // 4736 floats (18944 B, 16B-mult)
#define G_SMEM (3 * STAGE_F * 4)        // 56832 bytes

template<int MODE>
__global__ void __launch_bounds__(256, 2)
gemm2(const float* __restrict__ A, const float* __restrict__ W,
      float* __restrict__ Cout, const float* __restrict__ bias, int Ncols)
{
    extern __shared__ __align__(16) float gsm[];
    const int tid = threadIdx.x;
    const int wid = tid >> 5, lane = tid & 31;
    const int m0 = blockIdx.y * 128;
    const int n0 = blockIdx.x * 128;
    const int warp_row = (wid & 3) * 32;
    const int warp_col = (wid >> 2) * 64;
    const int l4 = lane >> 2, lk = lane & 3;
    const uint32_t smb = smem_u32(gsm);

    float acc[2][8][4];
    #pragma unroll
    for (int f = 0; f < 2; f++)
        #pragma unroll
        for (int g = 0; g < 8; g++)
            #pragma unroll
            for (int i = 0; i < 4; i++) acc[f][g][i] = 0.f;

    // producer: per thread 2 A-chunks + 2 B-chunks of 16B per stage
    const int a_r0 = tid >> 2;          // A rows a_r0, a_r0+64
    const int a_qd = (tid & 3) * 4;     // A k-offset
    const int b_k0 = tid >> 5;          // B k-rows b_k0, b_k0+8
    const int b_c4 = (tid & 31) * 4;    // B col offset

    auto load_stage = [&](int t, int s) {
        const int k0 = t * 16;
        const uint32_t abase = smb + (uint32_t)(s * STAGE_F) * 4;
        const uint32_t bbase = abase + A_ST * 4;
        #pragma unroll
        for (int h = 0; h < 2; h++) {
            const int r = a_r0 + h * 64;
            const float* gp;
            if (MODE == 2) {
                const int gm = m0 + r;
                const int b = gm >> 11, nn = gm & 2047;
                const int k = k0 + a_qd, hh = k >> 6, d = k & 63;
                gp = g_o + (((size_t)((b << 4) + hh)) * N_ + nn) * Dh_ + d;
            } else {
                gp = A + (size_t)(m0 + r) * DIM_ + k0 + a_qd;
            }
            asm volatile("cp.async.cg.shared.global [%0], [%1], 16;"
                         :: "r"(abase + (uint32_t)(r * APIT + a_qd) * 4), "l"(gp));
        }
        #pragma unroll
        for (int h = 0; h < 2; h++) {
            const int kr = b_k0 + h * 8;
            const float* gp = W + (size_t)(k0 + kr) * Ncols + n0 + b_c4;
            asm volatile("cp.async.cg.shared.global [%0], [%1], 16;"
                         :: "r"(bbase + (uint32_t)(kr * BPIT + b_c4) * 4), "l"(gp));
        }
        asm volatile("cp.async.commit_group;" ::: "memory");
    };

    load_stage(0, 0);
    load_stage(1, 1);

    int sidx = 0;
    for (int t = 0; t < DIM_ / 16; t++) {
        asm volatile("cp.async.wait_group 1;" ::: "memory");
        __syncthreads();

        if (t + 2 < DIM_ / 16) {
            int s2 = sidx + 2; if (s2 >= 3) s2 -= 3;
            load_stage(t + 2, s2);
        } else {
            asm volatile("cp.async.commit_group;" ::: "memory");
        }

        const float* As_ = gsm + sidx * STAGE_F;
        const float* Bs_ = As_ + A_ST;
        #pragma unroll
        for (int kss = 0; kss < 2; kss++) {
            const int kb = kss * 8 + lk;
            uint32_t af[2][4];
            #pragma unroll
            for (int f = 0; f < 2; f++) {
                const int rowb = warp_row + f * 16 + l4;
                af[f][0] = f2tf(As_[rowb * APIT + kb]);
                af[f][1] = f2tf(As_[(rowb + 8) * APIT + kb]);
                af[f][2] = f2tf(As_[rowb * APIT + kb + 4]);
                af[f][3] = f2tf(As_[(rowb + 8) * APIT + kb + 4]);
            }
            #pragma unroll
            for (int g = 0; g < 8; g++) {
                const int col = warp_col + g * 8 + l4;
                uint32_t bf[2];
                bf[0] = f2tf(Bs_[kb * BPIT + col]);
                bf[1] = f2tf(Bs_[(kb + 4) * BPIT + col]);
                MMA_TF32(acc[0][g], af[0], bf);
                MMA_TF32(acc[1][g], af[1], bf);
            }
        }
        if (++sidx >= 3) sidx -= 3;
    }

    // epilogue
    const int r0 = m0 + warp_row + l4;
    const int c0 = n0 + warp_col + lk * 2;
    #pragma unroll
    for (int f = 0; f < 2; f++) {
        #pragma unroll
        for (int g = 0; g < 8; g++) {
            const int n = c0 + g * 8;
            #pragma unroll
            for (int half = 0; half < 2; half++) {
                const int m = r0 + f * 16 + half * 8;
                float2 v;
                v.x = acc[f][g][half * 2 + 0];
                v.y = acc[f][g][half * 2 + 1];
                if (MODE == 2) {
                    v.x += bias[n];
                    v.y += bias[n + 1];
                    *(float2*)&Cout[(size_t)m * DIM_ + n] = v;
                } else {
                    const int b = m >> 11, nn = m & 2047;
                    if (MODE == 0) {
                        v.x = f2tf_f(v.x * 0.125f);
                        v.y = f2tf_f(v.y * 0.125f);
                        const int h = n >> 6, d = n & 63;
                        *(float2*)&g_q[(((size_t)((b << 4) + h)) * N_ + nn) * Dh_ + d] = v;
                    } else {
                        v.x = f2tf_f(v.x);
                        v.y = f2tf_f(v.y);
                        float* dst = (n < 1024) ? g_k : g_v;
                        const int cc = n & 1023;
                        const int h = cc >> 6, d = cc & 63;
                        *(float2*)&dst[(((size_t)((b << 4) + h)) * N_ + nn) * Dh_ + d] = v;
                    }
                }
            }
        }
    }
}

// ---------------------------------------------------------------------------
// Flash attention v2 (unchanged from R5 best)
// ---------------------------------------------------------------------------
#define KSP 68
#define VSP 72
#define KS_ST (64*KSP)
#define VS_ST (64*VSP)
#define SMV  (2*KS_ST)
#define SMP  (SMV + 2*VS_ST)
#define FL2_FLOATS (SMP + 8*512)
#define FL2_BYTES  (FL2_FLOATS*4)

__global__ void __launch_bounds__(256, 2) flash2_k()
{
    extern __shared__ __align__(16) float sm[];
    const int tid = threadIdx.x;
    const int bh = blockIdx.y;
    const int rb = gridDim.x - 1 - blockIdx.x;
    const int m0 = rb * 128;

    const float* qb = g_q + (size_t)bh * N_ * Dh_;
    const float* kb = g_k + (size_t)bh * N_ * Dh_;
    const float* vb = g_v + (size_t)bh * N_ * Dh_;
    float* ob = g_o + (size_t)bh * N_ * Dh_;

    const int wid = tid >> 5, lane = tid & 31;
    const int l4 = lane >> 2, lk = lane & 3;
    const int R0 = m0 + wid * 16;

    const uint32_t smb = smem_u32(sm);
    float* Pw = sm + SMP + wid * 512;

    uint32_t aq[8][4];
    {
        const float* q0 = qb + (size_t)(R0 + l4) * Dh_;
        const float* q1 = qb + (size_t)(R0 + l4 + 8) * Dh_;
        #pragma unroll
        for (int ks = 0; ks < 8; ks++) {
            const int d = ks * 8 + lk;
            aq[ks][0] = __float_as_uint(q0[d]);
            aq[ks][1] = __float_as_uint(q1[d]);
            aq[ks][2] = __float_as_uint(q0[d + 4]);
            aq[ks][3] = __float_as_uint(q1[d + 4]);
        }
    }

    float o[8][4];
    #pragma unroll
    for (int dg = 0; dg < 8; dg++)
        #pragma unroll
        for (int i = 0; i < 4; i++) o[dg][i] = 0.f;
    float mr0 = -1e30f, mr1 = -1e30f, lr0 = 0.f, lr1 = 0.f;

    const int ntiles = 2 * rb + 2;
    const int jr = tid >> 2;
    const int cb = tid & 3;

    auto load_tile = [&](int t, int s) {
        const int j0 = t * 64;
        const float* krow = kb + (size_t)(j0 + jr) * Dh_;
        const float* vrow = vb + (size_t)(j0 + jr) * Dh_;
        const uint32_t kd0 = smb + (uint32_t)(s * KS_ST + jr * KSP) * 4;
        const uint32_t vd0 = smb + (uint32_t)(SMV + s * VS_ST + jr * VSP) * 4;
        #pragma unroll
        for (int i = 0; i < 4; i++) {
            const int d4 = (cb + i * 4) * 4;
            asm volatile("cp.async.cg.shared.global [%0], [%1], 16;"
                         :: "r"(kd0 + d4 * 4), "l"(krow + d4));
            asm volatile("cp.async.cg.shared.global [%0], [%1], 16;"
                         :: "r"(vd0 + d4 * 4), "l"(vrow + d4));
        }
    };

    load_tile(0, 0);
    asm volatile("cp.async.commit_group;" ::: "memory");
    load_tile(1, 1);
    asm volatile("cp.async.commit_group;" ::: "memory");

    const int row0 = R0 + l4;
    const int row1 = R0 + l4 + 8;

    for (int t = 0; t < ntiles; t++) {
        const int s = t & 1;
        asm volatile("cp.async.wait_group 1;" ::: "memory");
        __syncthreads();

        if (t * 64 <= R0 + 15) {
            const float* Ksm = sm + s * KS_ST;
            const float* Vsm = sm + SMV + s * VS_ST;
            #pragma unroll
            for (int jc = 0; jc < 2; jc++) {
                const int j0c = t * 64 + jc * 32;
                if (j0c > R0 + 15) break;

                float s4[4][4];
                #pragma unroll
                for (int jg = 0; jg < 4; jg++)
                    #pragma unroll
                    for (int i = 0; i < 4; i++) s4[jg][i] = 0.f;
                #pragma unroll
                for (int ks = 0; ks < 8; ks++) {
                    const int d = ks * 8 + lk;
                    #pragma unroll
                    for (int jg = 0; jg < 4; jg++) {
                        const int krow_s = (jc * 32 + jg * 8 + l4) * KSP;
                        uint32_t bq[2];
                        bq[0] = __float_as_uint(Ksm[krow_s + d]);
                        bq[1] = __float_as_uint(Ksm[krow_s + d + 4]);
                        MMA_TF32(s4[jg], aq[ks], bq);
                    }
                }

                if (j0c + 31 > R0) {
                    #pragma unroll
                    for (int jg = 0; jg < 4; jg++) {
                        const int jb = j0c + jg * 8 + 2 * lk;
                        if (jb     > row0) s4[jg][0] = -1e30f;
                        if (jb + 1 > row0) s4[jg][1] = -1e30f;
                        if (jb     > row1) s4[jg][2] = -1e30f;
                        if (jb + 1 > row1) s4[jg][3] = -1e30f;
                    }
                }

                float mx0 = -1e30f, mx1 = -1e30f;
                #pragma unroll
                for (int jg = 0; jg < 4; jg++) {
                    mx0 = fmaxf(mx0, fmaxf(s4[jg][0], s4[jg][1]));
                    mx1 = fmaxf(mx1, fmaxf(s4[jg][2], s4[jg][3]));
                }
                mx0 = fmaxf(mx0, __shfl_xor_sync(0xffffffffu, mx0, 1));
                mx0 = fmaxf(mx0, __shfl_xor_sync(0xffffffffu, mx0, 2));
                mx1 = fmaxf(mx1, __shfl_xor_sync(0xffffffffu, mx1, 1));
                mx1 = fmaxf(mx1, __shfl_xor_sync(0xffffffffu, mx1, 2));

                const float mn0 = fmaxf(mr0, mx0);
                const float mn1 = fmaxf(mr1, mx1);
                const float a0 = __expf(mr0 - mn0);
                const float a1 = __expf(mr1 - mn1);
                mr0 = mn0; mr1 = mn1;

                float sum0 = 0.f, sum1 = 0.f;
                float p[4][4];
                #pragma unroll
                for (int jg = 0; jg < 4; jg++) {
                    p[jg][0] = f2tf_f(__expf(s4[jg][0] - mn0));
                    p[jg][1] = f2tf_f(__expf(s4[jg][1] - mn0));
                    p[jg][2] = f2tf_f(__expf(s4[jg][2] - mn1));
                    p[jg][3] = f2tf_f(__expf(s4[jg][3] - mn1));
                    sum0 += p[jg][0] + p[jg][1];
                    sum1 += p[jg][2] + p[jg][3];
                }
                sum0 += __shfl_xor_sync(0xffffffffu, sum0, 1);
                sum0 += __shfl_xor_sync(0xffffffffu, sum0, 2);
                sum1 += __shfl_xor_sync(0xffffffffu, sum1, 1);
                sum1 += __shfl_xor_sync(0xffffffffu, sum1, 2);
                lr0 = lr0 * a0 + sum0;
                lr1 = lr1 * a1 + sum1;

                #pragma unroll
                for (int dg = 0; dg < 8; dg++) {
                    o[dg][0] *= a0; o[dg][1] *= a0;
                    o[dg][2] *= a1; o[dg][3] *= a1;
                }

                #pragma unroll
                for (int jg = 0; jg < 4; jg++) {
                    const int c0 = 2 * lk;
                    const int la = l4 * 4 + (c0 & 3);
                    const int rx = (c0 & 4) ? 2 : 0;
                    Pw[jg * 128 + la * 4 + rx]     = p[jg][0];
                    Pw[jg * 128 + la * 4 + rx + 1] = p[jg][2];
                    const int c1 = c0 + 1;
                    const int lb = l4 * 4 + (c1 & 3);
                    const int ry = (c1 & 4) ? 2 : 0;
                    Pw[jg * 128 + lb * 4 + ry]     = p[jg][1];
                    Pw[jg * 128 + lb * 4 + ry + 1] = p[jg][3];
                }
                __syncwarp();

                #pragma unroll
                for (int ksp = 0; ksp < 4; ksp++) {
                    float4 pa4 = *(const float4*)&Pw[ksp * 128 + lane * 4];
                    uint32_t pa[4];
                    pa[0] = __float_as_uint(pa4.x);
                    pa[1] = __float_as_uint(pa4.y);
                    pa[2] = __float_as_uint(pa4.z);
                    pa[3] = __float_as_uint(pa4.w);
                    const int vr = (jc * 32 + ksp * 8 + lk) * VSP;
                    #pragma unroll
                    for (int dg = 0; dg < 8; dg++) {
                        const int vc = dg * 8 + l4;
                        uint32_t bv[2];
                        bv[0] = __float_as_uint(Vsm[vr + vc]);
                        bv[1] = __float_as_uint(Vsm[vr + 4 * VSP + vc]);
                        MMA_TF32(o[dg], pa, bv);
                    }
                }
                __syncwarp();
            }
        }
        __syncthreads();
        if (t + 2 < ntiles) load_tile(t + 2, s);
        asm volatile("cp.async.commit_group;" ::: "memory");
    }

    const float inv0 = 1.0f / lr0;
    const float inv1 = 1.0f / lr1;
    #pragma unroll
    for (int dg = 0; dg < 8; dg++) {
        const int col = dg * 8 + 2 * lk;
        float2 v0, v1;
        v0.x = o[dg][0] * inv0; v0.y = o[dg][1] * inv0;
        v1.x = o[dg][2] * inv1; v1.y = o[dg][3] * inv1;
        *(float2*)&ob[(size_t)row0 * Dh_ + col] = v0;
        *(float2*)&ob[(size_t)row1 * Dh_ + col] = v1;
    }
}

// ---------------------------------------------------------------------------
extern "C" void kernel_launch(void* const* d_in, const int* in_sizes, int n_in,
                              void* d_out, int out_size)
{
    const float* x   = (const float*)d_in[0];
    const float* Wq  = (const float*)d_in[1];
    const float* Wkv = (const float*)d_in[2];
    const float* Wo  = (const float*)d_in[3];
    const float* bo  = (const float*)d_in[4];
    float* out = (float*)d_out;

    static bool attr_done = false;
    if (!attr_done) {
        cudaFuncSetAttribute(gemm2<0>, cudaFuncAttributeMaxDynamicSharedMemorySize, G_SMEM);
        cudaFuncSetAttribute(gemm2<1>, cudaFuncAttributeMaxDynamicSharedMemorySize, G_SMEM);
        cudaFuncSetAttribute(gemm2<2>, cudaFuncAttributeMaxDynamicSharedMemorySize, G_SMEM);
        cudaFuncSetAttribute(flash2_k, cudaFuncAttributeMaxDynamicSharedMemorySize, FL2_BYTES);
        attr_done = true;
    }

    dim3 blk(256);
    gemm2<0><<<dim3(DIM_ / 128, M_ / 128), blk, G_SMEM>>>(x, Wq, nullptr, nullptr, DIM_);
    gemm2<1><<<dim3(2 * DIM_ / 128, M_ / 128), blk, G_SMEM>>>(x, Wkv, nullptr, nullptr, 2 * DIM_);
    flash2_k<<<dim3(N_ / 128, B_ * H_), blk, FL2_BYTES>>>();
    gemm2<2><<<dim3(DIM_ / 128, M_ / 128), blk, G_SMEM>>>(nullptr, Wo, out, bo, DIM_);
}

// round 10
// speedup vs baseline: 1.0986x; 1.0403x over previous
#include <cuda_runtime.h>
#include <cstdint>
#include <math.h>

#define B_  4
#define H_  16
#define N_  2048
#define Dh_ 64
#define DIM_ 1024
#define M_  (B_*N_)          // 8192
#define ELEMS (B_*H_*N_*Dh_) // 8388608

__device__ __align__(16) float g_q[ELEMS];
__device__ __align__(16) float g_k[ELEMS];
__device__ __align__(16) float g_v[ELEMS];
__device__ __align__(16) float g_o[ELEMS];
// fragment-packed, tf32-pre-rounded weights
__device__ __align__(16) float g_wqp[DIM_ * DIM_];
__device__ __align__(16) float g_wkvp[DIM_ * 2 * DIM_];
__device__ __align__(16) float g_wop[DIM_ * DIM_];

__device__ __forceinline__ uint32_t f2tf(float f) {
    uint32_t u;
    asm("cvt.rna.tf32.f32 %0, %1;" : "=r"(u) : "f"(f));
    return u;
}
__device__ __forceinline__ float f2tf_f(float f) {
    return __uint_as_float(f2tf(f));
}
__device__ __forceinline__ uint32_t smem_u32(const void* p) {
    uint32_t a;
    asm("{ .reg .u64 t; cvta.to.shared.u64 t, %1; cvt.u32.u64 %0, t; }"
        : "=r"(a) : "l"(p));
    return a;
}

#define MMA_TF32(c, a, b) \
    asm volatile("mma.sync.aligned.m16n8k8.row.col.f32.tf32.tf32.f32 " \
        "{%0,%1,%2,%3},{%4,%5,%6,%7},{%8,%9},{%0,%1,%2,%3};" \
        : "+f"((c)[0]), "+f"((c)[1]), "+f"((c)[2]), "+f"((c)[3]) \
        : "r"((a)[0]), "r"((a)[1]), "r"((a)[2]), "r"((a)[3]), \
          "r"((b)[0]), "r"((b)[1]))

// ---------------------------------------------------------------------------
// Weight pack: layout ((ntile*64 + ktile)*16 + seg)*128 + lane*4 + j
//   seg = pair*2 + kss, lane = l4*4 + lk
//   j: 0=(k,c) 1=(k+4,c) 2=(k,c+8) 3=(k+4,c+8)
//   c = ntile*128 + pair*16 + l4,  k = ktile*16 + kss*8 + lk
// WHICH selects dst INSIDE device code (device-global symbols must not be
// passed as kernel args from host: host shadow address + ATS = silent
// writes to host memory).
// ---------------------------------------------------------------------------
template<int WHICH>
__global__ void __launch_bounds__(256) pack_w_k(const float* __restrict__ W)
{
    float* dst = (WHICH == 0) ? g_wqp : (WHICH == 1) ? g_wkvp : g_wop;
    const int Ncols = (WHICH == 1) ? 2 * DIM_ : DIM_;
    const int t = blockIdx.x * 256 + threadIdx.x;
    const int lane = t & 31, seg = (t >> 5) & 15;
    const int ktile = (t >> 9) & 63, ntile = t >> 15;
    const int pair = seg >> 1, kss = seg & 1;
    const int l4 = lane >> 2, lk = lane & 3;
    const int k = ktile * 16 + kss * 8 + lk;
    const int c = ntile * 128 + pair * 16 + l4;
    float4 v;
    v.x = f2tf_f(W[(size_t)k * Ncols + c]);
    v.y = f2tf_f(W[(size_t)(k + 4) * Ncols + c]);
    v.z = f2tf_f(W[(size_t)k * Ncols + c + 8]);
    v.w = f2tf_f(W[(size_t)(k + 4) * Ncols + c + 8]);
    reinterpret_cast<float4*>(dst)[t] = v;
}

// ---------------------------------------------------------------------------
// GEMM: R7-proven A path (pitch-20 cp.async, scalar LDS + cvt) + packed B.
// BM=128, BN=128, BK=16, 8 warps (4M x 2N).
// MODE 0: A=x, B=g_wqp,  scatter*0.125 -> g_q (tf32)
// MODE 1: A=x, B=g_wkvp, scatter -> g_k/g_v (tf32)
// MODE 2: A=gather(g_o head-major), B=g_wop, +bias -> Cout
// ---------------------------------------------------------------------------
#define APIT 20
#define A_STF (128*APIT)            // 2560 floats
#define B_STF 2048                  // packed B tile floats
#define STGF  (A_STF + B_STF)       // 4608 floats = 18432 B (16B mult)
#define G_SMEM (3 * STGF * 4)       // 55296 bytes

template<int MODE>
__global__ void __launch_bounds__(256, 2)
gemm2b(const float* __restrict__ A, float* __restrict__ Cout,
       const float* __restrict__ bias)
{
    extern __shared__ __align__(16) float gsm[];
    const float* Bp = (MODE == 0) ? g_wqp : (MODE == 1) ? g_wkvp : g_wop;

    const int tid = threadIdx.x;
    const int wid = tid >> 5, lane = tid & 31;
    const int mtile = blockIdx.y, ntile = blockIdx.x;
    const int m0 = mtile * 128, n0 = ntile * 128;
    const int warp_row = (wid & 3) * 32;
    const int l4 = lane >> 2, lk = lane & 3;
    const uint32_t smb = smem_u32(gsm);

    float acc[2][8][4];
    #pragma unroll
    for (int f = 0; f < 2; f++)
        #pragma unroll
        for (int g = 0; g < 8; g++)
            #pragma unroll
            for (int i = 0; i < 4; i++) acc[f][g][i] = 0.f;

    const int a_r0 = tid >> 2;          // A rows a_r0, a_r0+64
    const int a_qd = (tid & 3) * 4;     // A k-offset

    auto load_stage = [&](int t, int s) {
        const int k0 = t * 16;
        const uint32_t abase = smb + (uint32_t)(s * STGF) * 4;
        const uint32_t bbase = abase + A_STF * 4;
        #pragma unroll
        for (int h = 0; h < 2; h++) {
            const int r = a_r0 + h * 64;
            const float* gp;
            if (MODE == 2) {
                const int gm = m0 + r;
                const int b = gm >> 11, nn = gm & 2047;
                const int k = k0 + a_qd, hh = k >> 6, d = k & 63;
                gp = g_o + (((size_t)((b << 4) + hh)) * N_ + nn) * Dh_ + d;
            } else {
                gp = A + (size_t)(m0 + r) * DIM_ + k0 + a_qd;
            }
            asm volatile("cp.async.cg.shared.global [%0], [%1], 16;"
                         :: "r"(abase + (uint32_t)(r * APIT + a_qd) * 4), "l"(gp));
        }
        const float* bsrc = Bp + ((size_t)(ntile * 64 + t)) * 2048;
        #pragma unroll
        for (int i = 0; i < 2; i++) {
            const int off = (tid + i * 256) * 4;
            asm volatile("cp.async.cg.shared.global [%0], [%1], 16;"
                         :: "r"(bbase + (uint32_t)off * 4), "l"(bsrc + off));
        }
        asm volatile("cp.async.commit_group;" ::: "memory");
    };

    load_stage(0, 0);
    load_stage(1, 1);

    const int b_pair0 = (wid >> 2) * 4;

    int sidx = 0;
    for (int t = 0; t < 64; t++) {
        asm volatile("cp.async.wait_group 1;" ::: "memory");
        __syncthreads();

        if (t + 2 < 64) {
            int s2 = sidx + 2; if (s2 >= 3) s2 -= 3;
            load_stage(t + 2, s2);
        } else {
            asm volatile("cp.async.commit_group;" ::: "memory");
        }

        const float* As_ = gsm + sidx * STGF;
        const float* Bs_ = As_ + A_STF;
        #pragma unroll
        for (int kss = 0; kss < 2; kss++) {
            const int kb = kss * 8 + lk;
            uint32_t af[2][4];
            #pragma unroll
            for (int f = 0; f < 2; f++) {
                const int rowb = warp_row + f * 16 + l4;
                af[f][0] = f2tf(As_[rowb * APIT + kb]);
                af[f][1] = f2tf(As_[(rowb + 8) * APIT + kb]);
                af[f][2] = f2tf(As_[rowb * APIT + kb + 4]);
                af[f][3] = f2tf(As_[(rowb + 8) * APIT + kb + 4]);
            }
            #pragma unroll
            for (int pl = 0; pl < 4; pl++) {
                float4 b4 = *(const float4*)&Bs_[((b_pair0 + pl) * 2 + kss) * 128 + lane * 4];
                uint32_t b0[2], b1[2];
                b0[0] = __float_as_uint(b4.x);
                b0[1] = __float_as_uint(b4.y);
                b1[0] = __float_as_uint(b4.z);
                b1[1] = __float_as_uint(b4.w);
                MMA_TF32(acc[0][2 * pl],     af[0], b0);
                MMA_TF32(acc[0][2 * pl + 1], af[0], b1);
                MMA_TF32(acc[1][2 * pl],     af[1], b0);
                MMA_TF32(acc[1][2 * pl + 1], af[1], b1);
            }
        }
        if (++sidx >= 3) sidx -= 3;
    }

    // epilogue (R7 verbatim)
    const int r0 = m0 + warp_row + l4;
    const int c0 = n0 + (wid >> 2) * 64 + lk * 2;
    #pragma unroll
    for (int f = 0; f < 2; f++) {
        #pragma unroll
        for (int g = 0; g < 8; g++) {
            const int n = c0 + g * 8;
            #pragma unroll
            for (int half = 0; half < 2; half++) {
                const int m = r0 + f * 16 + half * 8;
                float2 v;
                v.x = acc[f][g][half * 2 + 0];
                v.y = acc[f][g][half * 2 + 1];
                if (MODE == 2) {
                    v.x += bias[n];
                    v.y += bias[n + 1];
                    *(float2*)&Cout[(size_t)m * DIM_ + n] = v;
                } else {
                    const int b = m >> 11, nn = m & 2047;
                    if (MODE == 0) {
                        v.x = f2tf_f(v.x * 0.125f);
                        v.y = f2tf_f(v.y * 0.125f);
                        const int h = n >> 6, d = n & 63;
                        *(float2*)&g_q[(((size_t)((b << 4) + h)) * N_ + nn) * Dh_ + d] = v;
                    } else {
                        v.x = f2tf_f(v.x);
                        v.y = f2tf_f(v.y);
                        float* dst = (n < 1024) ? g_k : g_v;
                        const int cc = n & 1023;
                        const int h = cc >> 6, d = cc & 63;
                        *(float2*)&dst[(((size_t)((b << 4) + h)) * N_ + nn) * Dh_ + d] = v;
                    }
                }
            }
        }
    }
}

// ---------------------------------------------------------------------------
// Flash attention v2 (exact R5/R7 proven version)
// ---------------------------------------------------------------------------
#define KSP 68
#define VSP 72
#define KS_ST (64*KSP)
#define VS_ST (64*VSP)
#define SMV  (2*KS_ST)
#define SMP  (SMV + 2*VS_ST)
#define FL2_FLOATS (SMP + 8*512)
#define FL2_BYTES  (FL2_FLOATS*4)

__global__ void __launch_bounds__(256, 2) flash2_k()
{
    extern __shared__ __align__(16) float sm[];
    const int tid = threadIdx.x;
    const int bh = blockIdx.y;
    const int rb = gridDim.x - 1 - blockIdx.x;
    const int m0 = rb * 128;

    const float* qb = g_q + (size_t)bh * N_ * Dh_;
    const float* kb = g_k + (size_t)bh * N_ * Dh_;
    const float* vb = g_v + (size_t)bh * N_ * Dh_;
    float* ob = g_o + (size_t)bh * N_ * Dh_;

    const int wid = tid >> 5, lane = tid & 31;
    const int l4 = lane >> 2, lk = lane & 3;
    const int R0 = m0 + wid * 16;

    const uint32_t smb = smem_u32(sm);
    float* Pw = sm + SMP + wid * 512;

    uint32_t aq[8][4];
    {
        const float* q0 = qb + (size_t)(R0 + l4) * Dh_;
        const float* q1 = qb + (size_t)(R0 + l4 + 8) * Dh_;
        #pragma unroll
        for (int ks = 0; ks < 8; ks++) {
            const int d = ks * 8 + lk;
            aq[ks][0] = __float_as_uint(q0[d]);
            aq[ks][1] = __float_as_uint(q1[d]);
            aq[ks][2] = __float_as_uint(q0[d + 4]);
            aq[ks][3] = __float_as_uint(q1[d + 4]);
        }
    }

    float o[8][4];
    #pragma unroll
    for (int dg = 0; dg < 8; dg++)
        #pragma unroll
        for (int i = 0; i < 4; i++) o[dg][i] = 0.f;
    float mr0 = -1e30f, mr1 = -1e30f, lr0 = 0.f, lr1 = 0.f;

    const int ntiles = 2 * rb + 2;
    const int jr = tid >> 2;
    const int cb = tid & 3;

    auto load_tile = [&](int t, int s) {
        const int j0 = t * 64;
        const float* krow = kb + (size_t)(j0 + jr) * Dh_;
        const float* vrow = vb + (size_t)(j0 + jr) * Dh_;
        const uint32_t kd0 = smb + (uint32_t)(s * KS_ST + jr * KSP) * 4;
        const uint32_t vd0 = smb + (uint32_t)(SMV + s * VS_ST + jr * VSP) * 4;
        #pragma unroll
        for (int i = 0; i < 4; i++) {
            const int d4 = (cb + i * 4) * 4;
            asm volatile("cp.async.cg.shared.global [%0], [%1], 16;"
                         :: "r"(kd0 + d4 * 4), "l"(krow + d4));
            asm volatile("cp.async.cg.shared.global [%0], [%1], 16;"
                         :: "r"(vd0 + d4 * 4), "l"(vrow + d4));
        }
    };

    load_tile(0, 0);
    asm volatile("cp.async.commit_group;" ::: "memory");
    load_tile(1, 1);
    asm volatile("cp.async.commit_group;" ::: "memory");

    const int row0 = R0 + l4;
    const int row1 = R0 + l4 + 8;

    for (int t = 0; t < ntiles; t++) {
        const int s = t & 1;
        asm volatile("cp.async.wait_group 1;" ::: "memory");
        __syncthreads();

        if (t * 64 <= R0 + 15) {
            const float* Ksm = sm + s * KS_ST;
            const float* Vsm = sm + SMV + s * VS_ST;
            #pragma unroll
            for (int jc = 0; jc < 2; jc++) {
                const int j0c = t * 64 + jc * 32;
                if (j0c > R0 + 15) break;

                float s4[4][4];
                #pragma unroll
                for (int jg = 0; jg < 4; jg++)
                    #pragma unroll
                    for (int i = 0; i < 4; i++) s4[jg][i] = 0.f;
                #pragma unroll
                for (int ks = 0; ks < 8; ks++) {
                    const int d = ks * 8 + lk;
                    #pragma unroll
                    for (int jg = 0; jg < 4; jg++) {
                        const int krow_s = (jc * 32 + jg * 8 + l4) * KSP;
                        uint32_t bq[2];
                        bq[0] = __float_as_uint(Ksm[krow_s + d]);
                        bq[1] = __float_as_uint(Ksm[krow_s + d + 4]);
                        MMA_TF32(s4[jg], aq[ks], bq);
                    }
                }

                if (j0c + 31 > R0) {
                    #pragma unroll
                    for (int jg = 0; jg < 4; jg++) {
                        const int jb = j0c + jg * 8 + 2 * lk;
                        if (jb     > row0) s4[jg][0] = -1e30f;
                        if (jb + 1 > row0) s4[jg][1] = -1e30f;
                        if (jb     > row1) s4[jg][2] = -1e30f;
                        if (jb + 1 > row1) s4[jg][3] = -1e30f;
                    }
                }

                float mx0 = -1e30f, mx1 = -1e30f;
                #pragma unroll
                for (int jg = 0; jg < 4; jg++) {
                    mx0 = fmaxf(mx0, fmaxf(s4[jg][0], s4[jg][1]));
                    mx1 = fmaxf(mx1, fmaxf(s4[jg][2], s4[jg][3]));
                }
                mx0 = fmaxf(mx0, __shfl_xor_sync(0xffffffffu, mx0, 1));
                mx0 = fmaxf(mx0, __shfl_xor_sync(0xffffffffu, mx0, 2));
                mx1 = fmaxf(mx1, __shfl_xor_sync(0xffffffffu, mx1, 1));
                mx1 = fmaxf(mx1, __shfl_xor_sync(0xffffffffu, mx1, 2));

                const float mn0 = fmaxf(mr0, mx0);
                const float mn1 = fmaxf(mr1, mx1);
                const float a0 = __expf(mr0 - mn0);
                const float a1 = __expf(mr1 - mn1);
                mr0 = mn0; mr1 = mn1;

                float sum0 = 0.f, sum1 = 0.f;
                float p[4][4];
                #pragma unroll
                for (int jg = 0; jg < 4; jg++) {
                    p[jg][0] = f2tf_f(__expf(s4[jg][0] - mn0));
                    p[jg][1] = f2tf_f(__expf(s4[jg][1] - mn0));
                    p[jg][2] = f2tf_f(__expf(s4[jg][2] - mn1));
                    p[jg][3] = f2tf_f(__expf(s4[jg][3] - mn1));
                    sum0 += p[jg][0] + p[jg][1];
                    sum1 += p[jg][2] + p[jg][3];
                }
                sum0 += __shfl_xor_sync(0xffffffffu, sum0, 1);
                sum0 += __shfl_xor_sync(0xffffffffu, sum0, 2);
                sum1 += __shfl_xor_sync(0xffffffffu, sum1, 1);
                sum1 += __shfl_xor_sync(0xffffffffu, sum1, 2);
                lr0 = lr0 * a0 + sum0;
                lr1 = lr1 * a1 + sum1;

                #pragma unroll
                for (int dg = 0; dg < 8; dg++) {
                    o[dg][0] *= a0; o[dg][1] *= a0;
                    o[dg][2] *= a1; o[dg][3] *= a1;
                }

                #pragma unroll
                for (int jg = 0; jg < 4; jg++) {
                    const int c0 = 2 * lk;
                    const int la = l4 * 4 + (c0 & 3);
                    const int rx = (c0 & 4) ? 2 : 0;
                    Pw[jg * 128 + la * 4 + rx]     = p[jg][0];
                    Pw[jg * 128 + la * 4 + rx + 1] = p[jg][2];
                    const int c1 = c0 + 1;
                    const int lb = l4 * 4 + (c1 & 3);
                    const int ry = (c1 & 4) ? 2 : 0;
                    Pw[jg * 128 + lb * 4 + ry]     = p[jg][1];
                    Pw[jg * 128 + lb * 4 + ry + 1] = p[jg][3];
                }
                __syncwarp();

                #pragma unroll
                for (int ksp = 0; ksp < 4; ksp++) {
                    float4 pa4 = *(const float4*)&Pw[ksp * 128 + lane * 4];
                    uint32_t pa[4];
                    pa[0] = __float_as_uint(pa4.x);
                    pa[1] = __float_as_uint(pa4.y);
                    pa[2] = __float_as_uint(pa4.z);
                    pa[3] = __float_as_uint(pa4.w);
                    const int vr = (jc * 32 + ksp * 8 + lk) * VSP;
                    #pragma unroll
                    for (int dg = 0; dg < 8; dg++) {
                        const int vc = dg * 8 + l4;
                        uint32_t bv[2];
                        bv[0] = __float_as_uint(Vsm[vr + vc]);
                        bv[1] = __float_as_uint(Vsm[vr + 4 * VSP + vc]);
                        MMA_TF32(o[dg], pa, bv);
                    }
                }
                __syncwarp();
            }
        }
        __syncthreads();
        if (t + 2 < ntiles) load_tile(t + 2, s);
        asm volatile("cp.async.commit_group;" ::: "memory");
    }

    const float inv0 = 1.0f / lr0;
    const float inv1 = 1.0f / lr1;
    #pragma unroll
    for (int dg = 0; dg < 8; dg++) {
        const int col = dg * 8 + 2 * lk;
        float2 v0, v1;
        v0.x = o[dg][0] * inv0; v0.y = o[dg][1] * inv0;
        v1.x = o[dg][2] * inv1; v1.y = o[dg][3] * inv1;
        *(float2*)&ob[(size_t)row0 * Dh_ + col] = v0;
        *(float2*)&ob[(size_t)row1 * Dh_ + col] = v1;
    }
}

// ---------------------------------------------------------------------------
extern "C" void kernel_launch(void* const* d_in, const int* in_sizes, int n_in,
                              void* d_out, int out_size)
{
    const float* x   = (const float*)d_in[0];
    const float* Wq  = (const float*)d_in[1];
    const float* Wkv = (const float*)d_in[2];
    const float* Wo  = (const float*)d_in[3];
    const float* bo  = (const float*)d_in[4];
    float* out = (float*)d_out;

    static bool attr_done = false;
    if (!attr_done) {
        cudaFuncSetAttribute(gemm2b<0>, cudaFuncAttributeMaxDynamicSharedMemorySize, G_SMEM);
        cudaFuncSetAttribute(gemm2b<1>, cudaFuncAttributeMaxDynamicSharedMemorySize, G_SMEM);
        cudaFuncSetAttribute(gemm2b<2>, cudaFuncAttributeMaxDynamicSharedMemorySize, G_SMEM);
        cudaFuncSetAttribute(flash2_k, cudaFuncAttributeMaxDynamicSharedMemorySize, FL2_BYTES);
        attr_done = true;
    }

    dim3 blk(256);
    pack_w_k<0><<<1024, blk>>>(Wq);
    pack_w_k<1><<<2048, blk>>>(Wkv);
    pack_w_k<2><<<1024, blk>>>(Wo);
    gemm2b<0><<<dim3(8, 64), blk, G_SMEM>>>(x, nullptr, nullptr);
    gemm2b<1><<<dim3(16, 64), blk, G_SMEM>>>(x, nullptr, nullptr);
    flash2_k<<<dim3(N_ / 128, B_ * H_), blk, FL2_BYTES>>>();
    gemm2b<2><<<dim3(8, 64), blk, G_SMEM>>>(nullptr, out, bo);
}

// round 11
// speedup vs baseline: 1.2060x; 1.0978x over previous
#include <cuda_runtime.h>
#include <cstdint>
#include <math.h>

#define B_  4
#define H_  16
#define N_  2048
#define Dh_ 64
#define DIM_ 1024
#define M_  (B_*N_)          // 8192
#define ELEMS (B_*H_*N_*Dh_) // 8388608

__device__ __align__(16) float g_q[ELEMS];
__device__ __align__(16) float g_k[ELEMS];
__device__ __align__(16) float g_v[ELEMS];
__device__ __align__(16) float g_o[ELEMS];
// fragment-packed, tf32-pre-rounded operands
__device__ __align__(16) float g_xp[M_ * DIM_];
__device__ __align__(16) float g_wqp[DIM_ * DIM_];
__device__ __align__(16) float g_wkvp[DIM_ * 2 * DIM_];
__device__ __align__(16) float g_wop[DIM_ * DIM_];

__device__ __forceinline__ uint32_t f2tf(float f) {
    uint32_t u;
    asm("cvt.rna.tf32.f32 %0, %1;" : "=r"(u) : "f"(f));
    return u;
}
__device__ __forceinline__ float f2tf_f(float f) {
    return __uint_as_float(f2tf(f));
}
__device__ __forceinline__ uint32_t smem_u32(const void* p) {
    uint32_t a;
    asm("{ .reg .u64 t; cvta.to.shared.u64 t, %1; cvt.u32.u64 %0, t; }"
        : "=r"(a) : "l"(p));
    return a;
}

#define MMA_TF32(c, a, b) \
    asm volatile("mma.sync.aligned.m16n8k8.row.col.f32.tf32.tf32.f32 " \
        "{%0,%1,%2,%3},{%4,%5,%6,%7},{%8,%9},{%0,%1,%2,%3};" \
        : "+f"((c)[0]), "+f"((c)[1]), "+f"((c)[2]), "+f"((c)[3]) \
        : "r"((a)[0]), "r"((a)[1]), "r"((a)[2]), "r"((a)[3]), \
          "r"((b)[0]), "r"((b)[1]))

// ---------------------------------------------------------------------------
// A pack (x): ((mtile*64 + ktile)*16 + seg)*128 + lane*4 + j
//   seg = grp*2 + kss, lane = l4*4 + lk
//   j: 0=(r,k) 1=(r+8,k) 2=(r,k+4) 3=(r+8,k+4)
//   r = mtile*128 + grp*16 + l4,  k = ktile*16 + kss*8 + lk
// dst referenced from device code only (host-shadow symbol trap).
// ---------------------------------------------------------------------------
__global__ void __launch_bounds__(256) pack_x_k(const float* __restrict__ x)
{
    const int t = blockIdx.x * 256 + threadIdx.x;     // 0..2097151
    const int lane = t & 31, seg = (t >> 5) & 15;
    const int ktile = (t >> 9) & 63, mtile = t >> 15;
    const int grp = seg >> 1, kss = seg & 1;
    const int l4 = lane >> 2, lk = lane & 3;
    const int r = mtile * 128 + grp * 16 + l4;
    const int k = ktile * 16 + kss * 8 + lk;
    float4 v;
    v.x = f2tf_f(x[(size_t)r * DIM_ + k]);
    v.y = f2tf_f(x[(size_t)(r + 8) * DIM_ + k]);
    v.z = f2tf_f(x[(size_t)r * DIM_ + k + 4]);
    v.w = f2tf_f(x[(size_t)(r + 8) * DIM_ + k + 4]);
    reinterpret_cast<float4*>(g_xp)[t] = v;
}

// ---------------------------------------------------------------------------
// Weight pack: ((ntile*64 + ktile)*16 + seg)*128 + lane*4 + j
//   seg = pair*2 + kss; j: 0=(k,c) 1=(k+4,c) 2=(k,c+8) 3=(k+4,c+8)
//   c = ntile*128 + pair*16 + l4,  k = ktile*16 + kss*8 + lk
// ---------------------------------------------------------------------------
template<int WHICH>
__global__ void __launch_bounds__(256) pack_w_k(const float* __restrict__ W)
{
    float* dst = (WHICH == 0) ? g_wqp : (WHICH == 1) ? g_wkvp : g_wop;
    const int Ncols = (WHICH == 1) ? 2 * DIM_ : DIM_;
    const int t = blockIdx.x * 256 + threadIdx.x;
    const int lane = t & 31, seg = (t >> 5) & 15;
    const int ktile = (t >> 9) & 63, ntile = t >> 15;
    const int pair = seg >> 1, kss = seg & 1;
    const int l4 = lane >> 2, lk = lane & 3;
    const int k = ktile * 16 + kss * 8 + lk;
    const int c = ntile * 128 + pair * 16 + l4;
    float4 v;
    v.x = f2tf_f(W[(size_t)k * Ncols + c]);
    v.y = f2tf_f(W[(size_t)(k + 4) * Ncols + c]);
    v.z = f2tf_f(W[(size_t)k * Ncols + c + 8]);
    v.w = f2tf_f(W[(size_t)(k + 4) * Ncols + c + 8]);
    reinterpret_cast<float4*>(dst)[t] = v;
}

// ---------------------------------------------------------------------------
// GEMM: packed A (modes 0/1) or g_o-gather A (mode 2) + packed B.
// BM=128, BN=128, BK=16, 8 warps (4M x 2N).
// ---------------------------------------------------------------------------
#define APIT 20
#define B_STF 2048

template<int MODE>
__global__ void __launch_bounds__(256, 2)
gemm3(float* __restrict__ Cout, const float* __restrict__ bias)
{
    constexpr int A_STF = (MODE == 2) ? 128 * APIT : 2048;
    constexpr int STGF = A_STF + B_STF;
    extern __shared__ __align__(16) float gsm[];
    const float* Bp = (MODE == 0) ? g_wqp : (MODE == 1) ? g_wkvp : g_wop;

    const int tid = threadIdx.x;
    const int wid = tid >> 5, lane = tid & 31;
    const int mtile = blockIdx.y, ntile = blockIdx.x;
    const int m0 = mtile * 128, n0 = ntile * 128;
    const int warp_row = (wid & 3) * 32;
    const int l4 = lane >> 2, lk = lane & 3;
    const uint32_t smb = smem_u32(gsm);

    float acc[2][8][4];
    #pragma unroll
    for (int f = 0; f < 2; f++)
        #pragma unroll
        for (int g = 0; g < 8; g++)
            #pragma unroll
            for (int i = 0; i < 4; i++) acc[f][g][i] = 0.f;

    const int a_r0 = tid >> 2;          // MODE 2 gather rows
    const int a_qd = (tid & 3) * 4;

    auto load_stage = [&](int t, int s) {
        const uint32_t abase = smb + (uint32_t)(s * STGF) * 4;
        const uint32_t bbase = abase + A_STF * 4;
        if (MODE == 2) {
            const int k0 = t * 16;
            #pragma unroll
            for (int h = 0; h < 2; h++) {
                const int r = a_r0 + h * 64;
                const int gm = m0 + r;
                const int b = gm >> 11, nn = gm & 2047;
                const int k = k0 + a_qd, hh = k >> 6, d = k & 63;
                const float* gp = g_o + (((size_t)((b << 4) + hh)) * N_ + nn) * Dh_ + d;
                asm volatile("cp.async.cg.shared.global [%0], [%1], 16;"
                             :: "r"(abase + (uint32_t)(r * APIT + a_qd) * 4), "l"(gp));
            }
        } else {
            const float* asrc = g_xp + ((size_t)(mtile * 64 + t)) * 2048;
            #pragma unroll
            for (int i = 0; i < 2; i++) {
                const int off = (tid + i * 256) * 4;
                asm volatile("cp.async.cg.shared.global [%0], [%1], 16;"
                             :: "r"(abase + (uint32_t)off * 4), "l"(asrc + off));
            }
        }
        const float* bsrc = Bp + ((size_t)(ntile * 64 + t)) * 2048;
        #pragma unroll
        for (int i = 0; i < 2; i++) {
            const int off = (tid + i * 256) * 4;
            asm volatile("cp.async.cg.shared.global [%0], [%1], 16;"
                         :: "r"(bbase + (uint32_t)off * 4), "l"(bsrc + off));
        }
        asm volatile("cp.async.commit_group;" ::: "memory");
    };

    load_stage(0, 0);
    load_stage(1, 1);

    const int a_seg0 = (wid & 3) * 4;   // seg = (wid&3)*4 + f*2 + kss
    const int b_pair0 = (wid >> 2) * 4;

    int sidx = 0;
    for (int t = 0; t < 64; t++) {
        asm volatile("cp.async.wait_group 1;" ::: "memory");
        __syncthreads();

        if (t + 2 < 64) {
            int s2 = sidx + 2; if (s2 >= 3) s2 -= 3;
            load_stage(t + 2, s2);
        } else {
            asm volatile("cp.async.commit_group;" ::: "memory");
        }

        const float* As_ = gsm + sidx * STGF;
        const float* Bs_ = As_ + A_STF;
        #pragma unroll
        for (int kss = 0; kss < 2; kss++) {
            uint32_t af[2][4];
            if (MODE == 2) {
                const int kb = kss * 8 + lk;
                #pragma unroll
                for (int f = 0; f < 2; f++) {
                    const int rowb = warp_row + f * 16 + l4;
                    af[f][0] = f2tf(As_[rowb * APIT + kb]);
                    af[f][1] = f2tf(As_[(rowb + 8) * APIT + kb]);
                    af[f][2] = f2tf(As_[rowb * APIT + kb + 4]);
                    af[f][3] = f2tf(As_[(rowb + 8) * APIT + kb + 4]);
                }
            } else {
                #pragma unroll
                for (int f = 0; f < 2; f++) {
                    float4 a4 = *(const float4*)&As_[(a_seg0 + f * 2 + kss) * 128 + lane * 4];
                    af[f][0] = __float_as_uint(a4.x);
                    af[f][1] = __float_as_uint(a4.y);
                    af[f][2] = __float_as_uint(a4.z);
                    af[f][3] = __float_as_uint(a4.w);
                }
            }
            #pragma unroll
            for (int pl = 0; pl < 4; pl++) {
                float4 b4 = *(const float4*)&Bs_[((b_pair0 + pl) * 2 + kss) * 128 + lane * 4];
                uint32_t b0[2], b1[2];
                b0[0] = __float_as_uint(b4.x);
                b0[1] = __float_as_uint(b4.y);
                b1[0] = __float_as_uint(b4.z);
                b1[1] = __float_as_uint(b4.w);
                MMA_TF32(acc[0][2 * pl],     af[0], b0);
                MMA_TF32(acc[0][2 * pl + 1], af[0], b1);
                MMA_TF32(acc[1][2 * pl],     af[1], b0);
                MMA_TF32(acc[1][2 * pl + 1], af[1], b1);
            }
        }
        if (++sidx >= 3) sidx -= 3;
    }

    // epilogue (R10 verbatim)
    const int r0 = m0 + warp_row + l4;
    const int c0 = n0 + (wid >> 2) * 64 + lk * 2;
    #pragma unroll
    for (int f = 0; f < 2; f++) {
        #pragma unroll
        for (int g = 0; g < 8; g++) {
            const int n = c0 + g * 8;
            #pragma unroll
            for (int half = 0; half < 2; half++) {
                const int m = r0 + f * 16 + half * 8;
                float2 v;
                v.x = acc[f][g][half * 2 + 0];
                v.y = acc[f][g][half * 2 + 1];
                if (MODE == 2) {
                    v.x += bias[n];
                    v.y += bias[n + 1];
                    *(float2*)&Cout[(size_t)m * DIM_ + n] = v;
                } else {
                    const int b = m >> 11, nn = m & 2047;
                    if (MODE == 0) {
                        v.x = f2tf_f(v.x * 0.125f);
                        v.y = f2tf_f(v.y * 0.125f);
                        const int h = n >> 6, d = n & 63;
                        *(float2*)&g_q[(((size_t)((b << 4) + h)) * N_ + nn) * Dh_ + d] = v;
                    } else {
                        v.x = f2tf_f(v.x);
                        v.y = f2tf_f(v.y);
                        float* dst = (n < 1024) ? g_k : g_v;
                        const int cc = n & 1023;
                        const int h = cc >> 6, d = cc & 63;
                        *(float2*)&dst[(((size_t)((b << 4) + h)) * N_ + nn) * Dh_ + d] = v;
                    }
                }
            }
        }
    }
}

#define G_SMEM01 (3 * (2048 + B_STF) * 4)          // 49152
#define G_SMEM2  (3 * (128 * APIT + B_STF) * 4)    // 55296

// ---------------------------------------------------------------------------
// Flash attention v2 (exact R5/R7/R10 proven version)
// ---------------------------------------------------------------------------
#define KSP 68
#define VSP 72
#define KS_ST (64*KSP)
#define VS_ST (64*VSP)
#define SMV  (2*KS_ST)
#define SMP  (SMV + 2*VS_ST)
#define FL2_FLOATS (SMP + 8*512)
#define FL2_BYTES  (FL2_FLOATS*4)

__global__ void __launch_bounds__(256, 2) flash2_k()
{
    extern __shared__ __align__(16) float sm[];
    const int tid = threadIdx.x;
    const int bh = blockIdx.y;
    const int rb = gridDim.x - 1 - blockIdx.x;
    const int m0 = rb * 128;

    const float* qb = g_q + (size_t)bh * N_ * Dh_;
    const float* kb = g_k + (size_t)bh * N_ * Dh_;
    const float* vb = g_v + (size_t)bh * N_ * Dh_;
    float* ob = g_o + (size_t)bh * N_ * Dh_;

    const int wid = tid >> 5, lane = tid & 31;
    const int l4 = lane >> 2, lk = lane & 3;
    const int R0 = m0 + wid * 16;

    const uint32_t smb = smem_u32(sm);
    float* Pw = sm + SMP + wid * 512;

    uint32_t aq[8][4];
    {
        const float* q0 = qb + (size_t)(R0 + l4) * Dh_;
        const float* q1 = qb + (size_t)(R0 + l4 + 8) * Dh_;
        #pragma unroll
        for (int ks = 0; ks < 8; ks++) {
            const int d = ks * 8 + lk;
            aq[ks][0] = __float_as_uint(q0[d]);
            aq[ks][1] = __float_as_uint(q1[d]);
            aq[ks][2] = __float_as_uint(q0[d + 4]);
            aq[ks][3] = __float_as_uint(q1[d + 4]);
        }
    }

    float o[8][4];
    #pragma unroll
    for (int dg = 0; dg < 8; dg++)
        #pragma unroll
        for (int i = 0; i < 4; i++) o[dg][i] = 0.f;
    float mr0 = -1e30f, mr1 = -1e30f, lr0 = 0.f, lr1 = 0.f;

    const int ntiles = 2 * rb + 2;
    const int jr = tid >> 2;
    const int cb = tid & 3;

    auto load_tile = [&](int t, int s) {
        const int j0 = t * 64;
        const float* krow = kb + (size_t)(j0 + jr) * Dh_;
        const float* vrow = vb + (size_t)(j0 + jr) * Dh_;
        const uint32_t kd0 = smb + (uint32_t)(s * KS_ST + jr * KSP) * 4;
        const uint32_t vd0 = smb + (uint32_t)(SMV + s * VS_ST + jr * VSP) * 4;
        #pragma unroll
        for (int i = 0; i < 4; i++) {
            const int d4 = (cb + i * 4) * 4;
            asm volatile("cp.async.cg.shared.global [%0], [%1], 16;"
                         :: "r"(kd0 + d4 * 4), "l"(krow + d4));
            asm volatile("cp.async.cg.shared.global [%0], [%1], 16;"
                         :: "r"(vd0 + d4 * 4), "l"(vrow + d4));
        }
    };

    load_tile(0, 0);
    asm volatile("cp.async.commit_group;" ::: "memory");
    load_tile(1, 1);
    asm volatile("cp.async.commit_group;" ::: "memory");

    const int row0 = R0 + l4;
    const int row1 = R0 + l4 + 8;

    for (int t = 0; t < ntiles; t++) {
        const int s = t & 1;
        asm volatile("cp.async.wait_group 1;" ::: "memory");
        __syncthreads();

        if (t * 64 <= R0 + 15) {
            const float* Ksm = sm + s * KS_ST;
            const float* Vsm = sm + SMV + s * VS_ST;
            #pragma unroll
            for (int jc = 0; jc < 2; jc++) {
                const int j0c = t * 64 + jc * 32;
                if (j0c > R0 + 15) break;

                float s4[4][4];
                #pragma unroll
                for (int jg = 0; jg < 4; jg++)
                    #pragma unroll
                    for (int i = 0; i < 4; i++) s4[jg][i] = 0.f;
                #pragma unroll
                for (int ks = 0; ks < 8; ks++) {
                    const int d = ks * 8 + lk;
                    #pragma unroll
                    for (int jg = 0; jg < 4; jg++) {
                        const int krow_s = (jc * 32 + jg * 8 + l4) * KSP;
                        uint32_t bq[2];
                        bq[0] = __float_as_uint(Ksm[krow_s + d]);
                        bq[1] = __float_as_uint(Ksm[krow_s + d + 4]);
                        MMA_TF32(s4[jg], aq[ks], bq);
                    }
                }

                if (j0c + 31 > R0) {
                    #pragma unroll
                    for (int jg = 0; jg < 4; jg++) {
                        const int jb = j0c + jg * 8 + 2 * lk;
                        if (jb     > row0) s4[jg][0] = -1e30f;
                        if (jb + 1 > row0) s4[jg][1] = -1e30f;
                        if (jb     > row1) s4[jg][2] = -1e30f;
                        if (jb + 1 > row1) s4[jg][3] = -1e30f;
                    }
                }

                float mx0 = -1e30f, mx1 = -1e30f;
                #pragma unroll
                for (int jg = 0; jg < 4; jg++) {
                    mx0 = fmaxf(mx0, fmaxf(s4[jg][0], s4[jg][1]));
                    mx1 = fmaxf(mx1, fmaxf(s4[jg][2], s4[jg][3]));
                }
                mx0 = fmaxf(mx0, __shfl_xor_sync(0xffffffffu, mx0, 1));
                mx0 = fmaxf(mx0, __shfl_xor_sync(0xffffffffu, mx0, 2));
                mx1 = fmaxf(mx1, __shfl_xor_sync(0xffffffffu, mx1, 1));
                mx1 = fmaxf(mx1, __shfl_xor_sync(0xffffffffu, mx1, 2));

                const float mn0 = fmaxf(mr0, mx0);
                const float mn1 = fmaxf(mr1, mx1);
                const float a0 = __expf(mr0 - mn0);
                const float a1 = __expf(mr1 - mn1);
                mr0 = mn0; mr1 = mn1;

                float sum0 = 0.f, sum1 = 0.f;
                float p[4][4];
                #pragma unroll
                for (int jg = 0; jg < 4; jg++) {
                    p[jg][0] = f2tf_f(__expf(s4[jg][0] - mn0));
                    p[jg][1] = f2tf_f(__expf(s4[jg][1] - mn0));
                    p[jg][2] = f2tf_f(__expf(s4[jg][2] - mn1));
                    p[jg][3] = f2tf_f(__expf(s4[jg][3] - mn1));
                    sum0 += p[jg][0] + p[jg][1];
                    sum1 += p[jg][2] + p[jg][3];
                }
                sum0 += __shfl_xor_sync(0xffffffffu, sum0, 1);
                sum0 += __shfl_xor_sync(0xffffffffu, sum0, 2);
                sum1 += __shfl_xor_sync(0xffffffffu, sum1, 1);
                sum1 += __shfl_xor_sync(0xffffffffu, sum1, 2);
                lr0 = lr0 * a0 + sum0;
                lr1 = lr1 * a1 + sum1;

                #pragma unroll
                for (int dg = 0; dg < 8; dg++) {
                    o[dg][0] *= a0; o[dg][1] *= a0;
                    o[dg][2] *= a1; o[dg][3] *= a1;
                }

                #pragma unroll
                for (int jg = 0; jg < 4; jg++) {
                    const int c0 = 2 * lk;
                    const int la = l4 * 4 + (c0 & 3);
                    const int rx = (c0 & 4) ? 2 : 0;
                    Pw[jg * 128 + la * 4 + rx]     = p[jg][0];
                    Pw[jg * 128 + la * 4 + rx + 1] = p[jg][2];
                    const int c1 = c0 + 1;
                    const int lb = l4 * 4 + (c1 & 3);
                    const int ry = (c1 & 4) ? 2 : 0;
                    Pw[jg * 128 + lb * 4 + ry]     = p[jg][1];
                    Pw[jg * 128 + lb * 4 + ry + 1] = p[jg][3];
                }
                __syncwarp();

                #pragma unroll
                for (int ksp = 0; ksp < 4; ksp++) {
                    float4 pa4 = *(const float4*)&Pw[ksp * 128 + lane * 4];
                    uint32_t pa[4];
                    pa[0] = __float_as_uint(pa4.x);
                    pa[1] = __float_as_uint(pa4.y);
                    pa[2] = __float_as_uint(pa4.z);
                    pa[3] = __float_as_uint(pa4.w);
                    const int vr = (jc * 32 + ksp * 8 + lk) * VSP;
                    #pragma unroll
                    for (int dg = 0; dg < 8; dg++) {
                        const int vc = dg * 8 + l4;
                        uint32_t bv[2];
                        bv[0] = __float_as_uint(Vsm[vr + vc]);
                        bv[1] = __float_as_uint(Vsm[vr + 4 * VSP + vc]);
                        MMA_TF32(o[dg], pa, bv);
                    }
                }
                __syncwarp();
            }
        }
        __syncthreads();
        if (t + 2 < ntiles) load_tile(t + 2, s);
        asm volatile("cp.async.commit_group;" ::: "memory");
    }

    const float inv0 = 1.0f / lr0;
    const float inv1 = 1.0f / lr1;
    #pragma unroll
    for (int dg = 0; dg < 8; dg++) {
        const int col = dg * 8 + 2 * lk;
        float2 v0, v1;
        v0.x = o[dg][0] * inv0; v0.y = o[dg][1] * inv0;
        v1.x = o[dg][2] * inv1; v1.y = o[dg][3] * inv1;
        *(float2*)&ob[(size_t)row0 * Dh_ + col] = v0;
        *(float2*)&ob[(size_t)row1 * Dh_ + col] = v1;
    }
}

// ---------------------------------------------------------------------------
extern "C" void kernel_launch(void* const* d_in, const int* in_sizes, int n_in,
                              void* d_out, int out_size)
{
    const float* x   = (const float*)d_in[0];
    const float* Wq  = (const float*)d_in[1];
    const float* Wkv = (const float*)d_in[2];
    const float* Wo  = (const float*)d_in[3];
    const float* bo  = (const float*)d_in[4];
    float* out = (float*)d_out;

    static bool attr_done = false;
    if (!attr_done) {
        cudaFuncSetAttribute(gemm3<0>, cudaFuncAttributeMaxDynamicSharedMemorySize, G_SMEM01);
        cudaFuncSetAttribute(gemm3<1>, cudaFuncAttributeMaxDynamicSharedMemorySize, G_SMEM01);
        cudaFuncSetAttribute(gemm3<2>, cudaFuncAttributeMaxDynamicSharedMemorySize, G_SMEM2);
        cudaFuncSetAttribute(flash2_k, cudaFuncAttributeMaxDynamicSharedMemorySize, FL2_BYTES);
        attr_done = true;
    }

    dim3 blk(256);
    pack_x_k<<<8192, blk>>>(x);
    pack_w_k<0><<<1024, blk>>>(Wq);
    pack_w_k<1><<<2048, blk>>>(Wkv);
    pack_w_k<2><<<1024, blk>>>(Wo);
    gemm3<0><<<dim3(8, 64), blk, G_SMEM01>>>(nullptr, nullptr);
    gemm3<1><<<dim3(16, 64), blk, G_SMEM01>>>(nullptr, nullptr);
    flash2_k<<<dim3(N_ / 128, B_ * H_), blk, FL2_BYTES>>>();
    gemm3<2><<<dim3(8, 64), blk, G_SMEM2>>>(out, bo);
}

// round 12
// speedup vs baseline: 1.3287x; 1.1018x over previous
#include <cuda_runtime.h>
#include <cstdint>
#include <math.h>

#define B_  4
#define H_  16
#define N_  2048
#define Dh_ 64
#define DIM_ 1024
#define M_  (B_*N_)          // 8192
#define ELEMS (B_*H_*N_*Dh_) // 8388608

__device__ __align__(16) float g_o[ELEMS];
// fragment-packed, tf32-pre-rounded operands
__device__ __align__(16) float g_xp[M_ * DIM_];
__device__ __align__(16) float g_wqp[DIM_ * DIM_];
__device__ __align__(16) float g_wkvp[DIM_ * 2 * DIM_];
__device__ __align__(16) float g_wop[DIM_ * DIM_];
// flash operands, fragment-packed by projection epilogues
__device__ __align__(16) float g_qp[ELEMS];  // A-frag per (bh, rowgrp16)
__device__ __align__(16) float g_kp[ELEMS];  // B-frag per (bh, tile64): k=d, c=j
__device__ __align__(16) float g_vp[ELEMS];  // B-frag per (bh, tile64): k=j, c=d

__device__ __forceinline__ uint32_t f2tf(float f) {
    uint32_t u;
    asm("cvt.rna.tf32.f32 %0, %1;" : "=r"(u) : "f"(f));
    return u;
}
__device__ __forceinline__ float f2tf_f(float f) {
    return __uint_as_float(f2tf(f));
}
__device__ __forceinline__ uint32_t smem_u32(const void* p) {
    uint32_t a;
    asm("{ .reg .u64 t; cvta.to.shared.u64 t, %1; cvt.u32.u64 %0, t; }"
        : "=r"(a) : "l"(p));
    return a;
}

#define MMA_TF32(c, a, b) \
    asm volatile("mma.sync.aligned.m16n8k8.row.col.f32.tf32.tf32.f32 " \
        "{%0,%1,%2,%3},{%4,%5,%6,%7},{%8,%9},{%0,%1,%2,%3};" \
        : "+f"((c)[0]), "+f"((c)[1]), "+f"((c)[2]), "+f"((c)[3]) \
        : "r"((a)[0]), "r"((a)[1]), "r"((a)[2]), "r"((a)[3]), \
          "r"((b)[0]), "r"((b)[1]))

// ---------------------------------------------------------------------------
// x pack (A-fragments): ((mtile*64 + ktile)*16 + seg)*128 + lane*4 + j
// ---------------------------------------------------------------------------
__global__ void __launch_bounds__(256) pack_x_k(const float* __restrict__ x)
{
    const int t = blockIdx.x * 256 + threadIdx.x;
    const int lane = t & 31, seg = (t >> 5) & 15;
    const int ktile = (t >> 9) & 63, mtile = t >> 15;
    const int grp = seg >> 1, kss = seg & 1;
    const int l4 = lane >> 2, lk = lane & 3;
    const int r = mtile * 128 + grp * 16 + l4;
    const int k = ktile * 16 + kss * 8 + lk;
    float4 v;
    v.x = f2tf_f(x[(size_t)r * DIM_ + k]);
    v.y = f2tf_f(x[(size_t)(r + 8) * DIM_ + k]);
    v.z = f2tf_f(x[(size_t)r * DIM_ + k + 4]);
    v.w = f2tf_f(x[(size_t)(r + 8) * DIM_ + k + 4]);
    reinterpret_cast<float4*>(g_xp)[t] = v;
}

// ---------------------------------------------------------------------------
// Weight pack (B-fragments): ((ntile*64 + ktile)*16 + seg)*128 + lane*4 + j
// ---------------------------------------------------------------------------
template<int WHICH>
__global__ void __launch_bounds__(256) pack_w_k(const float* __restrict__ W)
{
    float* dst = (WHICH == 0) ? g_wqp : (WHICH == 1) ? g_wkvp : g_wop;
    const int Ncols = (WHICH == 1) ? 2 * DIM_ : DIM_;
    const int t = blockIdx.x * 256 + threadIdx.x;
    const int lane = t & 31, seg = (t >> 5) & 15;
    const int ktile = (t >> 9) & 63, ntile = t >> 15;
    const int pair = seg >> 1, kss = seg & 1;
    const int l4 = lane >> 2, lk = lane & 3;
    const int k = ktile * 16 + kss * 8 + lk;
    const int c = ntile * 128 + pair * 16 + l4;
    float4 v;
    v.x = f2tf_f(W[(size_t)k * Ncols + c]);
    v.y = f2tf_f(W[(size_t)(k + 4) * Ncols + c]);
    v.z = f2tf_f(W[(size_t)k * Ncols + c + 8]);
    v.w = f2tf_f(W[(size_t)(k + 4) * Ncols + c + 8]);
    reinterpret_cast<float4*>(dst)[t] = v;
}

// ---------------------------------------------------------------------------
// GEMM: packed A (modes 0/1) or g_o-gather A (mode 2) + packed B.
// MODE 0 epilogue -> g_qp (A-frag layout per (bh, rowgrp16))
// MODE 1 epilogue -> g_kp / g_vp (B-frag layout per (bh, tile64))
// MODE 2 epilogue -> Cout + bias
// ---------------------------------------------------------------------------
#define APIT 20
#define B_STF 2048

template<int MODE>
__global__ void __launch_bounds__(256, 2)
gemm3(float* __restrict__ Cout, const float* __restrict__ bias)
{
    constexpr int A_STF = (MODE == 2) ? 128 * APIT : 2048;
    constexpr int STGF = A_STF + B_STF;
    extern __shared__ __align__(16) float gsm[];
    const float* Bp = (MODE == 0) ? g_wqp : (MODE == 1) ? g_wkvp : g_wop;

    const int tid = threadIdx.x;
    const int wid = tid >> 5, lane = tid & 31;
    const int mtile = blockIdx.y, ntile = blockIdx.x;
    const int m0 = mtile * 128, n0 = ntile * 128;
    const int warp_row = (wid & 3) * 32;
    const int l4 = lane >> 2, lk = lane & 3;
    const uint32_t smb = smem_u32(gsm);

    float acc[2][8][4];
    #pragma unroll
    for (int f = 0; f < 2; f++)
        #pragma unroll
        for (int g = 0; g < 8; g++)
            #pragma unroll
            for (int i = 0; i < 4; i++) acc[f][g][i] = 0.f;

    const int a_r0 = tid >> 2;
    const int a_qd = (tid & 3) * 4;

    auto load_stage = [&](int t, int s) {
        const uint32_t abase = smb + (uint32_t)(s * STGF) * 4;
        const uint32_t bbase = abase + A_STF * 4;
        if (MODE == 2) {
            const int k0 = t * 16;
            #pragma unroll
            for (int h = 0; h < 2; h++) {
                const int r = a_r0 + h * 64;
                const int gm = m0 + r;
                const int b = gm >> 11, nn = gm & 2047;
                const int k = k0 + a_qd, hh = k >> 6, d = k & 63;
                const float* gp = g_o + (((size_t)((b << 4) + hh)) * N_ + nn) * Dh_ + d;
                asm volatile("cp.async.cg.shared.global [%0], [%1], 16;"
                             :: "r"(abase + (uint32_t)(r * APIT + a_qd) * 4), "l"(gp));
            }
        } else {
            const float* asrc = g_xp + ((size_t)(mtile * 64 + t)) * 2048;
            #pragma unroll
            for (int i = 0; i < 2; i++) {
                const int off = (tid + i * 256) * 4;
                asm volatile("cp.async.cg.shared.global [%0], [%1], 16;"
                             :: "r"(abase + (uint32_t)off * 4), "l"(asrc + off));
            }
        }
        const float* bsrc = Bp + ((size_t)(ntile * 64 + t)) * 2048;
        #pragma unroll
        for (int i = 0; i < 2; i++) {
            const int off = (tid + i * 256) * 4;
            asm volatile("cp.async.cg.shared.global [%0], [%1], 16;"
                         :: "r"(bbase + (uint32_t)off * 4), "l"(bsrc + off));
        }
        asm volatile("cp.async.commit_group;" ::: "memory");
    };

    load_stage(0, 0);
    load_stage(1, 1);

    const int a_seg0 = (wid & 3) * 4;
    const int b_pair0 = (wid >> 2) * 4;

    int sidx = 0;
    for (int t = 0; t < 64; t++) {
        asm volatile("cp.async.wait_group 1;" ::: "memory");
        __syncthreads();

        if (t + 2 < 64) {
            int s2 = sidx + 2; if (s2 >= 3) s2 -= 3;
            load_stage(t + 2, s2);
        } else {
            asm volatile("cp.async.commit_group;" ::: "memory");
        }

        const float* As_ = gsm + sidx * STGF;
        const float* Bs_ = As_ + A_STF;
        #pragma unroll
        for (int kss = 0; kss < 2; kss++) {
            uint32_t af[2][4];
            if (MODE == 2) {
                const int kb = kss * 8 + lk;
                #pragma unroll
                for (int f = 0; f < 2; f++) {
                    const int rowb = warp_row + f * 16 + l4;
                    af[f][0] = f2tf(As_[rowb * APIT + kb]);
                    af[f][1] = f2tf(As_[(rowb + 8) * APIT + kb]);
                    af[f][2] = f2tf(As_[rowb * APIT + kb + 4]);
                    af[f][3] = f2tf(As_[(rowb + 8) * APIT + kb + 4]);
                }
            } else {
                #pragma unroll
                for (int f = 0; f < 2; f++) {
                    float4 a4 = *(const float4*)&As_[(a_seg0 + f * 2 + kss) * 128 + lane * 4];
                    af[f][0] = __float_as_uint(a4.x);
                    af[f][1] = __float_as_uint(a4.y);
                    af[f][2] = __float_as_uint(a4.z);
                    af[f][3] = __float_as_uint(a4.w);
                }
            }
            #pragma unroll
            for (int pl = 0; pl < 4; pl++) {
                float4 b4 = *(const float4*)&Bs_[((b_pair0 + pl) * 2 + kss) * 128 + lane * 4];
                uint32_t b0[2], b1[2];
                b0[0] = __float_as_uint(b4.x);
                b0[1] = __float_as_uint(b4.y);
                b1[0] = __float_as_uint(b4.z);
                b1[1] = __float_as_uint(b4.w);
                MMA_TF32(acc[0][2 * pl],     af[0], b0);
                MMA_TF32(acc[0][2 * pl + 1], af[0], b1);
                MMA_TF32(acc[1][2 * pl],     af[1], b0);
                MMA_TF32(acc[1][2 * pl + 1], af[1], b1);
            }
        }
        if (++sidx >= 3) sidx -= 3;
    }

    // epilogue
    const int r0 = m0 + warp_row + l4;
    const int c0 = n0 + (wid >> 2) * 64 + lk * 2;
    #pragma unroll
    for (int f = 0; f < 2; f++) {
        #pragma unroll
        for (int g = 0; g < 8; g++) {
            const int n = c0 + g * 8;
            #pragma unroll
            for (int half = 0; half < 2; half++) {
                const int m = r0 + f * 16 + half * 8;
                float2 v;
                v.x = acc[f][g][half * 2 + 0];
                v.y = acc[f][g][half * 2 + 1];
                if (MODE == 2) {
                    v.x += bias[n];
                    v.y += bias[n + 1];
                    *(float2*)&Cout[(size_t)m * DIM_ + n] = v;
                } else {
                    const int b = m >> 11, nn = m & 2047;
                    if (MODE == 0) {
                        // Q -> A-fragment pack: ((bh*128+grp)*8+ks)*128 + lane*4 + slot
                        const float vx = f2tf_f(v.x * 0.125f);
                        const float vy = f2tf_f(v.y * 0.125f);
                        const int h = n >> 6, d = n & 63;
                        const size_t segb = ((size_t)(((b << 4) + h) * 128 + (nn >> 4))) * 8;
                        const int l4q = nn & 7, rhalf = (nn >> 3) & 1;
                        {
                            const int ks = d >> 3, lkq = d & 3, dh = (d >> 2) & 1;
                            g_qp[(segb + ks) * 128 + (l4q * 4 + lkq) * 4 + rhalf + 2 * dh] = vx;
                        }
                        {
                            const int d1 = d + 1;
                            const int ks = d1 >> 3, lkq = d1 & 3, dh = (d1 >> 2) & 1;
                            g_qp[(segb + ks) * 128 + (l4q * 4 + lkq) * 4 + rhalf + 2 * dh] = vy;
                        }
                    } else {
                        const float vx = f2tf_f(v.x);
                        const float vy = f2tf_f(v.y);
                        const int cc = n & 1023;
                        const int h = cc >> 6, d = cc & 63;
                        const int bh = (b << 4) + h;
                        const int tile = nn >> 6, c = nn & 63;
                        const size_t tb = ((size_t)(bh * 32 + tile)) * 32;
                        if (n < 1024) {
                            // K -> B-frag: k=d, col=c(token)
                            const int pair = c >> 4, l4b = c & 7, gsub = (c >> 3) & 1;
                            {
                                const int kss = d >> 3, lkk = d & 3, kh = (d >> 2) & 1;
                                g_kp[(tb + pair * 8 + kss) * 128 + (l4b * 4 + lkk) * 4 + gsub * 2 + kh] = vx;
                            }
                            {
                                const int d1 = d + 1;
                                const int kss = d1 >> 3, lkk = d1 & 3, kh = (d1 >> 2) & 1;
                                g_kp[(tb + pair * 8 + kss) * 128 + (l4b * 4 + lkk) * 4 + gsub * 2 + kh] = vy;
                            }
                        } else {
                            // V -> B-frag: k=c(token), col=d
                            const int kss = c >> 3, lkk = c & 3, kh = (c >> 2) & 1;
                            {
                                const int pair = d >> 4, l4b = d & 7, gsub = (d >> 3) & 1;
                                g_vp[(tb + pair * 8 + kss) * 128 + (l4b * 4 + lkk) * 4 + gsub * 2 + kh] = vx;
                            }
                            {
                                const int d1 = d + 1;
                                const int pair = d1 >> 4, l4b = d1 & 7, gsub = (d1 >> 3) & 1;
                                g_vp[(tb + pair * 8 + kss) * 128 + (l4b * 4 + lkk) * 4 + gsub * 2 + kh] = vy;
                            }
                        }
                    }
                }
            }
        }
    }
}

#define G_SMEM01 (3 * (2048 + B_STF) * 4)          // 49152
#define G_SMEM2  (3 * (128 * APIT + B_STF) * 4)    // 55296

// ---------------------------------------------------------------------------
// Flash attention v3: fragment-packed Q/K/V.
// K/V tiles cp.async'd as contiguous 16KB blocks; all fragment loads LDS.128.
// ---------------------------------------------------------------------------
#define TS_F 4096                      // one K or V tile, floats
#define SMV  (2*TS_F)
#define SMP  (SMV + 2*TS_F)            // 16384
#define FL2_FLOATS (SMP + 8*512)       // 20480
#define FL2_BYTES  (FL2_FLOATS*4)      // 81920

__global__ void __launch_bounds__(256, 2) flash2_k()
{
    extern __shared__ __align__(16) float sm[];
    const int tid = threadIdx.x;
    const int bh = blockIdx.y;
    const int rb = gridDim.x - 1 - blockIdx.x;
    const int m0 = rb * 128;

    float* ob = g_o + (size_t)bh * N_ * Dh_;

    const int wid = tid >> 5, lane = tid & 31;
    const int l4 = lane >> 2, lk = lane & 3;
    const int R0 = m0 + wid * 16;

    const uint32_t smb = smem_u32(sm);
    float* Pw = sm + SMP + wid * 512;

    // Q A-fragments: 8 x LDG.128 from packed layout
    uint32_t aq[8][4];
    {
        const float4* qsrc = (const float4*)(g_qp
            + ((size_t)(bh * 128 + (R0 >> 4))) * 8 * 128);
        #pragma unroll
        for (int ks = 0; ks < 8; ks++) {
            float4 a4 = qsrc[ks * 32 + lane];
            aq[ks][0] = __float_as_uint(a4.x);
            aq[ks][1] = __float_as_uint(a4.y);
            aq[ks][2] = __float_as_uint(a4.z);
            aq[ks][3] = __float_as_uint(a4.w);
        }
    }

    float o[8][4];
    #pragma unroll
    for (int dg = 0; dg < 8; dg++)
        #pragma unroll
        for (int i = 0; i < 4; i++) o[dg][i] = 0.f;
    float mr0 = -1e30f, mr1 = -1e30f, lr0 = 0.f, lr1 = 0.f;

    const int ntiles = 2 * rb + 2;

    auto load_tile = [&](int t, int s) {
        const float* ksrc = g_kp + ((size_t)(bh * 32 + t)) * TS_F;
        const float* vsrc = g_vp + ((size_t)(bh * 32 + t)) * TS_F;
        const uint32_t kd = smb + (uint32_t)(s * TS_F) * 4;
        const uint32_t vd = smb + (uint32_t)(SMV + s * TS_F) * 4;
        #pragma unroll
        for (int i = 0; i < 4; i++) {
            const int off = (tid + i * 256) * 4;
            asm volatile("cp.async.cg.shared.global [%0], [%1], 16;"
                         :: "r"(kd + (uint32_t)off * 4), "l"(ksrc + off));
            asm volatile("cp.async.cg.shared.global [%0], [%1], 16;"
                         :: "r"(vd + (uint32_t)off * 4), "l"(vsrc + off));
        }
    };

    load_tile(0, 0);
    asm volatile("cp.async.commit_group;" ::: "memory");
    load_tile(1, 1);
    asm volatile("cp.async.commit_group;" ::: "memory");

    const int row0 = R0 + l4;
    const int row1 = R0 + l4 + 8;

    for (int t = 0; t < ntiles; t++) {
        const int s = t & 1;
        asm volatile("cp.async.wait_group 1;" ::: "memory");
        __syncthreads();

        if (t * 64 <= R0 + 15) {
            const float* Ksm = sm + s * TS_F;
            const float* Vsm = sm + SMV + s * TS_F;
            #pragma unroll
            for (int jc = 0; jc < 2; jc++) {
                const int j0c = t * 64 + jc * 32;
                if (j0c > R0 + 15) break;

                // ---- S = Q K^T, packed B-frags (LDS.128 feeds 2 MMAs) ----
                float s4[4][4];
                #pragma unroll
                for (int jg = 0; jg < 4; jg++)
                    #pragma unroll
                    for (int i = 0; i < 4; i++) s4[jg][i] = 0.f;
                #pragma unroll
                for (int ks = 0; ks < 8; ks++) {
                    #pragma unroll
                    for (int pr = 0; pr < 2; pr++) {
                        float4 b4 = *(const float4*)&Ksm[((jc * 2 + pr) * 8 + ks) * 128 + lane * 4];
                        uint32_t b0[2], b1[2];
                        b0[0] = __float_as_uint(b4.x);
                        b0[1] = __float_as_uint(b4.y);
                        b1[0] = __float_as_uint(b4.z);
                        b1[1] = __float_as_uint(b4.w);
                        MMA_TF32(s4[2 * pr],     aq[ks], b0);
                        MMA_TF32(s4[2 * pr + 1], aq[ks], b1);
                    }
                }

                if (j0c + 31 > R0) {
                    #pragma unroll
                    for (int jg = 0; jg < 4; jg++) {
                        const int jb = j0c + jg * 8 + 2 * lk;
                        if (jb     > row0) s4[jg][0] = -1e30f;
                        if (jb + 1 > row0) s4[jg][1] = -1e30f;
                        if (jb     > row1) s4[jg][2] = -1e30f;
                        if (jb + 1 > row1) s4[jg][3] = -1e30f;
                    }
                }

                float mx0 = -1e30f, mx1 = -1e30f;
                #pragma unroll
                for (int jg = 0; jg < 4; jg++) {
                    mx0 = fmaxf(mx0, fmaxf(s4[jg][0], s4[jg][1]));
                    mx1 = fmaxf(mx1, fmaxf(s4[jg][2], s4[jg][3]));
                }
                mx0 = fmaxf(mx0, __shfl_xor_sync(0xffffffffu, mx0, 1));
                mx0 = fmaxf(mx0, __shfl_xor_sync(0xffffffffu, mx0, 2));
                mx1 = fmaxf(mx1, __shfl_xor_sync(0xffffffffu, mx1, 1));
                mx1 = fmaxf(mx1, __shfl_xor_sync(0xffffffffu, mx1, 2));

                const float mn0 = fmaxf(mr0, mx0);
                const float mn1 = fmaxf(mr1, mx1);
                const float a0 = __expf(mr0 - mn0);
                const float a1 = __expf(mr1 - mn1);
                mr0 = mn0; mr1 = mn1;

                float sum0 = 0.f, sum1 = 0.f;
                float p[4][4];
                #pragma unroll
                for (int jg = 0; jg < 4; jg++) {
                    p[jg][0] = f2tf_f(__expf(s4[jg][0] - mn0));
                    p[jg][1] = f2tf_f(__expf(s4[jg][1] - mn0));
                    p[jg][2] = f2tf_f(__expf(s4[jg][2] - mn1));
                    p[jg][3] = f2tf_f(__expf(s4[jg][3] - mn1));
                    sum0 += p[jg][0] + p[jg][1];
                    sum1 += p[jg][2] + p[jg][3];
                }
                sum0 += __shfl_xor_sync(0xffffffffu, sum0, 1);
                sum0 += __shfl_xor_sync(0xffffffffu, sum0, 2);
                sum1 += __shfl_xor_sync(0xffffffffu, sum1, 1);
                sum1 += __shfl_xor_sync(0xffffffffu, sum1, 2);
                lr0 = lr0 * a0 + sum0;
                lr1 = lr1 * a1 + sum1;

                #pragma unroll
                for (int dg = 0; dg < 8; dg++) {
                    o[dg][0] *= a0; o[dg][1] *= a0;
                    o[dg][2] *= a1; o[dg][3] *= a1;
                }

                // ---- pack P into A-fragment layout (unchanged) ----
                #pragma unroll
                for (int jg = 0; jg < 4; jg++) {
                    const int c0 = 2 * lk;
                    const int la = l4 * 4 + (c0 & 3);
                    const int rx = (c0 & 4) ? 2 : 0;
                    Pw[jg * 128 + la * 4 + rx]     = p[jg][0];
                    Pw[jg * 128 + la * 4 + rx + 1] = p[jg][2];
                    const int c1 = c0 + 1;
                    const int lb = l4 * 4 + (c1 & 3);
                    const int ry = (c1 & 4) ? 2 : 0;
                    Pw[jg * 128 + lb * 4 + ry]     = p[jg][1];
                    Pw[jg * 128 + lb * 4 + ry + 1] = p[jg][3];
                }
                __syncwarp();

                // ---- O += P V, packed V B-frags ----
                #pragma unroll
                for (int ksp = 0; ksp < 4; ksp++) {
                    float4 pa4 = *(const float4*)&Pw[ksp * 128 + lane * 4];
                    uint32_t pa[4];
                    pa[0] = __float_as_uint(pa4.x);
                    pa[1] = __float_as_uint(pa4.y);
                    pa[2] = __float_as_uint(pa4.z);
                    pa[3] = __float_as_uint(pa4.w);
                    const int kssj = jc * 4 + ksp;
                    #pragma unroll
                    for (int pd = 0; pd < 4; pd++) {
                        float4 b4 = *(const float4*)&Vsm[(pd * 8 + kssj) * 128 + lane * 4];
                        uint32_t b0[2], b1[2];
                        b0[0] = __float_as_uint(b4.x);
                        b0[1] = __float_as_uint(b4.y);
                        b1[0] = __float_as_uint(b4.z);
                        b1[1] = __float_as_uint(b4.w);
                        MMA_TF32(o[2 * pd],     pa, b0);
                        MMA_TF32(o[2 * pd + 1], pa, b1);
                    }
                }
                __syncwarp();
            }
        }
        __syncthreads();
        if (t + 2 < ntiles) load_tile(t + 2, s);
        asm volatile("cp.async.commit_group;" ::: "memory");
    }

    const float inv0 = 1.0f / lr0;
    const float inv1 = 1.0f / lr1;
    #pragma unroll
    for (int dg = 0; dg < 8; dg++) {
        const int col = dg * 8 + 2 * lk;
        float2 v0, v1;
        v0.x = o[dg][0] * inv0; v0.y = o[dg][1] * inv0;
        v1.x = o[dg][2] * inv1; v1.y = o[dg][3] * inv1;
        *(float2*)&ob[(size_t)row0 * Dh_ + col] = v0;
        *(float2*)&ob[(size_t)row1 * Dh_ + col] = v1;
    }
}

// ---------------------------------------------------------------------------
extern "C" void kernel_launch(void* const* d_in, const int* in_sizes, int n_in,
                              void* d_out, int out_size)
{
    const float* x   = (const float*)d_in[0];
    const float* Wq  = (const float*)d_in[1];
    const float* Wkv = (const float*)d_in[2];
    const float* Wo  = (const float*)d_in[3];
    const float* bo  = (const float*)d_in[4];
    float* out = (float*)d_out;

    static bool attr_done = false;
    if (!attr_done) {
        cudaFuncSetAttribute(gemm3<0>, cudaFuncAttributeMaxDynamicSharedMemorySize, G_SMEM01);
        cudaFuncSetAttribute(gemm3<1>, cudaFuncAttributeMaxDynamicSharedMemorySize, G_SMEM01);
        cudaFuncSetAttribute(gemm3<2>, cudaFuncAttributeMaxDynamicSharedMemorySize, G_SMEM2);
        cudaFuncSetAttribute(flash2_k, cudaFuncAttributeMaxDynamicSharedMemorySize, FL2_BYTES);
        attr_done = true;
    }

    dim3 blk(256);
    pack_x_k<<<8192, blk>>>(x);
    pack_w_k<0><<<1024, blk>>>(Wq);
    pack_w_k<1><<<2048, blk>>>(Wkv);
    pack_w_k<2><<<1024, blk>>>(Wo);
    gemm3<0><<<dim3(8, 64), blk, G_SMEM01>>>(nullptr, nullptr);
    gemm3<1><<<dim3(16, 64), blk, G_SMEM01>>>(nullptr, nullptr);
    flash2_k<<<dim3(N_ / 128, B_ * H_), blk, FL2_BYTES>>>();
    gemm3<2><<<dim3(8, 64), blk, G_SMEM2>>>(out, bo);
}

// round 13
// speedup vs baseline: 1.3627x; 1.0255x over previous
#include <cuda_runtime.h>
#include <cstdint>
#include <math.h>

#define B_  4
#define H_  16
#define N_  2048
#define Dh_ 64
#define DIM_ 1024
#define M_  (B_*N_)          // 8192
#define ELEMS (B_*H_*N_*Dh_) // 8388608

__device__ __align__(16) float g_o[ELEMS];
// fragment-packed, tf32-pre-rounded operands
__device__ __align__(16) float g_xp[M_ * DIM_];
__device__ __align__(16) float g_wqp[DIM_ * DIM_];
__device__ __align__(16) float g_wkvp[DIM_ * 2 * DIM_];
__device__ __align__(16) float g_wop[DIM_ * DIM_];
// flash operands, fragment-packed by projection epilogues
__device__ __align__(16) float g_qp[ELEMS];
__device__ __align__(16) float g_kp[ELEMS];
__device__ __align__(16) float g_vp[ELEMS];

__device__ __forceinline__ uint32_t f2tf(float f) {
    uint32_t u;
    asm("cvt.rna.tf32.f32 %0, %1;" : "=r"(u) : "f"(f));
    return u;
}
__device__ __forceinline__ float f2tf_f(float f) {
    return __uint_as_float(f2tf(f));
}
__device__ __forceinline__ uint32_t smem_u32(const void* p) {
    uint32_t a;
    asm("{ .reg .u64 t; cvta.to.shared.u64 t, %1; cvt.u32.u64 %0, t; }"
        : "=r"(a) : "l"(p));
    return a;
}

#define MMA_TF32(c, a, b) \
    asm volatile("mma.sync.aligned.m16n8k8.row.col.f32.tf32.tf32.f32 " \
        "{%0,%1,%2,%3},{%4,%5,%6,%7},{%8,%9},{%0,%1,%2,%3};" \
        : "+f"((c)[0]), "+f"((c)[1]), "+f"((c)[2]), "+f"((c)[3]) \
        : "r"((a)[0]), "r"((a)[1]), "r"((a)[2]), "r"((a)[3]), \
          "r"((b)[0]), "r"((b)[1]))

// ---------------------------------------------------------------------------
// x pack (A-fragments): ((mtile*64 + ktile)*16 + seg)*128 + lane*4 + j
// ---------------------------------------------------------------------------
__global__ void __launch_bounds__(256) pack_x_k(const float* __restrict__ x)
{
    const int t = blockIdx.x * 256 + threadIdx.x;
    const int lane = t & 31, seg = (t >> 5) & 15;
    const int ktile = (t >> 9) & 63, mtile = t >> 15;
    const int grp = seg >> 1, kss = seg & 1;
    const int l4 = lane >> 2, lk = lane & 3;
    const int r = mtile * 128 + grp * 16 + l4;
    const int k = ktile * 16 + kss * 8 + lk;
    float4 v;
    v.x = f2tf_f(x[(size_t)r * DIM_ + k]);
    v.y = f2tf_f(x[(size_t)(r + 8) * DIM_ + k]);
    v.z = f2tf_f(x[(size_t)r * DIM_ + k + 4]);
    v.w = f2tf_f(x[(size_t)(r + 8) * DIM_ + k + 4]);
    reinterpret_cast<float4*>(g_xp)[t] = v;
}

// ---------------------------------------------------------------------------
// Weight pack (B-fragments): ((ntile*64 + ktile)*16 + seg)*128 + lane*4 + j
// ---------------------------------------------------------------------------
template<int WHICH>
__global__ void __launch_bounds__(256) pack_w_k(const float* __restrict__ W)
{
    float* dst = (WHICH == 0) ? g_wqp : (WHICH == 1) ? g_wkvp : g_wop;
    const int Ncols = (WHICH == 1) ? 2 * DIM_ : DIM_;
    const int t = blockIdx.x * 256 + threadIdx.x;
    const int lane = t & 31, seg = (t >> 5) & 15;
    const int ktile = (t >> 9) & 63, ntile = t >> 15;
    const int pair = seg >> 1, kss = seg & 1;
    const int l4 = lane >> 2, lk = lane & 3;
    const int k = ktile * 16 + kss * 8 + lk;
    const int c = ntile * 128 + pair * 16 + l4;
    float4 v;
    v.x = f2tf_f(W[(size_t)k * Ncols + c]);
    v.y = f2tf_f(W[(size_t)(k + 4) * Ncols + c]);
    v.z = f2tf_f(W[(size_t)k * Ncols + c + 8]);
    v.w = f2tf_f(W[(size_t)(k + 4) * Ncols + c + 8]);
    reinterpret_cast<float4*>(dst)[t] = v;
}

// ---------------------------------------------------------------------------
// Merged projection GEMM (Q + KV), BK=32 stages, fully packed operands.
// grid (24, 64): ntile<8 -> Q path (B=g_wqp), else KV path (B=g_wkvp).
// ---------------------------------------------------------------------------
#define P_STGF 8192
#define P_SMEM (3 * P_STGF * 4)   // 98304

__global__ void __launch_bounds__(256, 2) proj_k()
{
    extern __shared__ __align__(16) float gsm[];
    const int tid = threadIdx.x;
    const int wid = tid >> 5, lane = tid & 31;
    const int mtile = blockIdx.y;
    const int ntile = blockIdx.x;            // 0..23
    const bool isq = ntile < 8;
    const int nb = isq ? ntile : ntile - 8;
    const float* Bp = isq ? g_wqp : g_wkvp;
    const int m0 = mtile * 128;
    const int n0 = nb * 128;
    const int warp_row = (wid & 3) * 32;
    const int l4 = lane >> 2, lk = lane & 3;
    const uint32_t smb = smem_u32(gsm);

    float acc[2][8][4];
    #pragma unroll
    for (int f = 0; f < 2; f++)
        #pragma unroll
        for (int g = 0; g < 8; g++)
            #pragma unroll
            for (int i = 0; i < 4; i++) acc[f][g][i] = 0.f;

    auto load_stage = [&](int t, int s) {
        const uint32_t abase = smb + (uint32_t)(s * P_STGF) * 4;
        const uint32_t bbase = abase + 4096 * 4;
        const float* asrc = g_xp + ((size_t)(mtile * 64 + 2 * t)) * 2048;
        const float* bsrc = Bp + ((size_t)(nb * 64 + 2 * t)) * 2048;
        #pragma unroll
        for (int i = 0; i < 4; i++) {
            const int off = (tid + i * 256) * 4;
            asm volatile("cp.async.cg.shared.global [%0], [%1], 16;"
                         :: "r"(abase + (uint32_t)off * 4), "l"(asrc + off));
            asm volatile("cp.async.cg.shared.global [%0], [%1], 16;"
                         :: "r"(bbase + (uint32_t)off * 4), "l"(bsrc + off));
        }
        asm volatile("cp.async.commit_group;" ::: "memory");
    };

    load_stage(0, 0);
    load_stage(1, 1);

    const int a_seg0 = (wid & 3) * 4;
    const int b_pair0 = (wid >> 2) * 4;

    int sidx = 0;
    for (int t = 0; t < 32; t++) {
        asm volatile("cp.async.wait_group 1;" ::: "memory");
        __syncthreads();

        if (t + 2 < 32) {
            int s2 = sidx + 2; if (s2 >= 3) s2 -= 3;
            load_stage(t + 2, s2);
        } else {
            asm volatile("cp.async.commit_group;" ::: "memory");
        }

        const float* As_ = gsm + sidx * P_STGF;
        const float* Bs_ = As_ + 4096;
        #pragma unroll
        for (int kss = 0; kss < 4; kss++) {
            const int ktl = kss >> 1, k2 = kss & 1;
            uint32_t af[2][4];
            #pragma unroll
            for (int f = 0; f < 2; f++) {
                float4 a4 = *(const float4*)&As_[(ktl * 16 + a_seg0 + f * 2 + k2) * 128 + lane * 4];
                af[f][0] = __float_as_uint(a4.x);
                af[f][1] = __float_as_uint(a4.y);
                af[f][2] = __float_as_uint(a4.z);
                af[f][3] = __float_as_uint(a4.w);
            }
            #pragma unroll
            for (int pl = 0; pl < 4; pl++) {
                float4 b4 = *(const float4*)&Bs_[(ktl * 16 + (b_pair0 + pl) * 2 + k2) * 128 + lane * 4];
                uint32_t b0[2], b1[2];
                b0[0] = __float_as_uint(b4.x);
                b0[1] = __float_as_uint(b4.y);
                b1[0] = __float_as_uint(b4.z);
                b1[1] = __float_as_uint(b4.w);
                MMA_TF32(acc[0][2 * pl],     af[0], b0);
                MMA_TF32(acc[0][2 * pl + 1], af[0], b1);
                MMA_TF32(acc[1][2 * pl],     af[1], b0);
                MMA_TF32(acc[1][2 * pl + 1], af[1], b1);
            }
        }
        if (++sidx >= 3) sidx -= 3;
    }

    // epilogue: Q-pack or K/V-pack (identical math/rounding to R12)
    const int r0 = m0 + warp_row + l4;
    const int c0 = n0 + (wid >> 2) * 64 + lk * 2;
    #pragma unroll
    for (int f = 0; f < 2; f++) {
        #pragma unroll
        for (int g = 0; g < 8; g++) {
            const int n = c0 + g * 8;
            #pragma unroll
            for (int half = 0; half < 2; half++) {
                const int m = r0 + f * 16 + half * 8;
                float2 v;
                v.x = acc[f][g][half * 2 + 0];
                v.y = acc[f][g][half * 2 + 1];
                const int b = m >> 11, nn = m & 2047;
                if (isq) {
                    const float vx = f2tf_f(v.x * 0.125f);
                    const float vy = f2tf_f(v.y * 0.125f);
                    const int h = n >> 6, d = n & 63;
                    const size_t segb = ((size_t)(((b << 4) + h) * 128 + (nn >> 4))) * 8;
                    const int l4q = nn & 7, rhalf = (nn >> 3) & 1;
                    {
                        const int ks = d >> 3, lkq = d & 3, dh = (d >> 2) & 1;
                        g_qp[(segb + ks) * 128 + (l4q * 4 + lkq) * 4 + rhalf + 2 * dh] = vx;
                    }
                    {
                        const int d1 = d + 1;
                        const int ks = d1 >> 3, lkq = d1 & 3, dh = (d1 >> 2) & 1;
                        g_qp[(segb + ks) * 128 + (l4q * 4 + lkq) * 4 + rhalf + 2 * dh] = vy;
                    }
                } else {
                    const float vx = f2tf_f(v.x);
                    const float vy = f2tf_f(v.y);
                    const int cc = n & 1023;
                    const int h = cc >> 6, d = cc & 63;
                    const int bh = (b << 4) + h;
                    const int tile = nn >> 6, c = nn & 63;
                    const size_t tb = ((size_t)(bh * 32 + tile)) * 32;
                    if (n < 1024) {
                        const int pair = c >> 4, l4b = c & 7, gsub = (c >> 3) & 1;
                        {
                            const int kss = d >> 3, lkk = d & 3, kh = (d >> 2) & 1;
                            g_kp[(tb + pair * 8 + kss) * 128 + (l4b * 4 + lkk) * 4 + gsub * 2 + kh] = vx;
                        }
                        {
                            const int d1 = d + 1;
                            const int kss = d1 >> 3, lkk = d1 & 3, kh = (d1 >> 2) & 1;
                            g_kp[(tb + pair * 8 + kss) * 128 + (l4b * 4 + lkk) * 4 + gsub * 2 + kh] = vy;
                        }
                    } else {
                        const int kss = c >> 3, lkk = c & 3, kh = (c >> 2) & 1;
                        {
                            const int pair = d >> 4, l4b = d & 7, gsub = (d >> 3) & 1;
                            g_vp[(tb + pair * 8 + kss) * 128 + (l4b * 4 + lkk) * 4 + gsub * 2 + kh] = vx;
                        }
                        {
                            const int d1 = d + 1;
                            const int pair = d1 >> 4, l4b = d1 & 7, gsub = (d1 >> 3) & 1;
                            g_vp[(tb + pair * 8 + kss) * 128 + (l4b * 4 + lkk) * 4 + gsub * 2 + kh] = vy;
                        }
                    }
                }
            }
        }
    }
}

// ---------------------------------------------------------------------------
// Output GEMM: A=gather(g_o head-major, pitch-36 smem), B=g_wop packed, BK=32.
// ---------------------------------------------------------------------------
#define APIT2 36
#define O_A_STF (128 * APIT2)             // 4608
#define O_STGF (O_A_STF + 4096)           // 8704
#define O_SMEM (3 * O_STGF * 4)           // 104448

__global__ void __launch_bounds__(256, 2)
outg_k(float* __restrict__ Cout, const float* __restrict__ bias)
{
    extern __shared__ __align__(16) float gsm[];
    const int tid = threadIdx.x;
    const int wid = tid >> 5, lane = tid & 31;
    const int mtile = blockIdx.y, ntile = blockIdx.x;
    const int m0 = mtile * 128, n0 = ntile * 128;
    const int warp_row = (wid & 3) * 32;
    const int l4 = lane >> 2, lk = lane & 3;
    const uint32_t smb = smem_u32(gsm);

    float acc[2][8][4];
    #pragma unroll
    for (int f = 0; f < 2; f++)
        #pragma unroll
        for (int g = 0; g < 8; g++)
            #pragma unroll
            for (int i = 0; i < 4; i++) acc[f][g][i] = 0.f;

    const int a_r0 = tid >> 2;
    const int a_qd = (tid & 3) * 4;

    auto load_stage = [&](int t, int s) {
        const uint32_t abase = smb + (uint32_t)(s * O_STGF) * 4;
        const uint32_t bbase = abase + O_A_STF * 4;
        const int k0 = t * 32;
        #pragma unroll
        for (int h = 0; h < 2; h++) {
            const int r = a_r0 + h * 64;
            const int gm = m0 + r;
            const int b = gm >> 11, nn = gm & 2047;
            #pragma unroll
            for (int q = 0; q < 2; q++) {
                const int koff = a_qd + q * 16;
                const int k = k0 + koff, hh = k >> 6, d = k & 63;
                const float* gp = g_o + (((size_t)((b << 4) + hh)) * N_ + nn) * Dh_ + d;
                asm volatile("cp.async.cg.shared.global [%0], [%1], 16;"
                             :: "r"(abase + (uint32_t)(r * APIT2 + koff) * 4), "l"(gp));
            }
        }
        const float* bsrc = g_wop + ((size_t)(ntile * 64 + 2 * t)) * 2048;
        #pragma unroll
        for (int i = 0; i < 4; i++) {
            const int off = (tid + i * 256) * 4;
            asm volatile("cp.async.cg.shared.global [%0], [%1], 16;"
                         :: "r"(bbase + (uint32_t)off * 4), "l"(bsrc + off));
        }
        asm volatile("cp.async.commit_group;" ::: "memory");
    };

    load_stage(0, 0);
    load_stage(1, 1);

    const int b_pair0 = (wid >> 2) * 4;

    int sidx = 0;
    for (int t = 0; t < 32; t++) {
        asm volatile("cp.async.wait_group 1;" ::: "memory");
        __syncthreads();

        if (t + 2 < 32) {
            int s2 = sidx + 2; if (s2 >= 3) s2 -= 3;
            load_stage(t + 2, s2);
        } else {
            asm volatile("cp.async.commit_group;" ::: "memory");
        }

        const float* As_ = gsm + sidx * O_STGF;
        const float* Bs_ = As_ + O_A_STF;
        #pragma unroll
        for (int kss = 0; kss < 4; kss++) {
            const int kb = kss * 8 + lk;
            const int ktl = kss >> 1, k2 = kss & 1;
            uint32_t af[2][4];
            #pragma unroll
            for (int f = 0; f < 2; f++) {
                const int rowb = warp_row + f * 16 + l4;
                af[f][0] = f2tf(As_[rowb * APIT2 + kb]);
                af[f][1] = f2tf(As_[(rowb + 8) * APIT2 + kb]);
                af[f][2] = f2tf(As_[rowb * APIT2 + kb + 4]);
                af[f][3] = f2tf(As_[(rowb + 8) * APIT2 + kb + 4]);
            }
            #pragma unroll
            for (int pl = 0; pl < 4; pl++) {
                float4 b4 = *(const float4*)&Bs_[(ktl * 16 + (b_pair0 + pl) * 2 + k2) * 128 + lane * 4];
                uint32_t b0[2], b1[2];
                b0[0] = __float_as_uint(b4.x);
                b0[1] = __float_as_uint(b4.y);
                b1[0] = __float_as_uint(b4.z);
                b1[1] = __float_as_uint(b4.w);
                MMA_TF32(acc[0][2 * pl],     af[0], b0);
                MMA_TF32(acc[0][2 * pl + 1], af[0], b1);
                MMA_TF32(acc[1][2 * pl],     af[1], b0);
                MMA_TF32(acc[1][2 * pl + 1], af[1], b1);
            }
        }
        if (++sidx >= 3) sidx -= 3;
    }

    const int r0 = m0 + warp_row + l4;
    const int c0 = n0 + (wid >> 2) * 64 + lk * 2;
    #pragma unroll
    for (int f = 0; f < 2; f++) {
        #pragma unroll
        for (int g = 0; g < 8; g++) {
            const int n = c0 + g * 8;
            #pragma unroll
            for (int half = 0; half < 2; half++) {
                const int m = r0 + f * 16 + half * 8;
                float2 v;
                v.x = acc[f][g][half * 2 + 0] + bias[n];
                v.y = acc[f][g][half * 2 + 1] + bias[n + 1];
                *(float2*)&Cout[(size_t)m * DIM_ + n] = v;
            }
        }
    }
}

// ---------------------------------------------------------------------------
// Flash attention v3 (exact R12 proven version)
// ---------------------------------------------------------------------------
#define TS_F 4096
#define SMV  (2*TS_F)
#define SMP  (SMV + 2*TS_F)
#define FL2_FLOATS (SMP + 8*512)
#define FL2_BYTES  (FL2_FLOATS*4)

__global__ void __launch_bounds__(256, 2) flash2_k()
{
    extern __shared__ __align__(16) float sm[];
    const int tid = threadIdx.x;
    const int bh = blockIdx.y;
    const int rb = gridDim.x - 1 - blockIdx.x;
    const int m0 = rb * 128;

    float* ob = g_o + (size_t)bh * N_ * Dh_;

    const int wid = tid >> 5, lane = tid & 31;
    const int l4 = lane >> 2, lk = lane & 3;
    const int R0 = m0 + wid * 16;

    const uint32_t smb = smem_u32(sm);
    float* Pw = sm + SMP + wid * 512;

    uint32_t aq[8][4];
    {
        const float4* qsrc = (const float4*)(g_qp
            + ((size_t)(bh * 128 + (R0 >> 4))) * 8 * 128);
        #pragma unroll
        for (int ks = 0; ks < 8; ks++) {
            float4 a4 = qsrc[ks * 32 + lane];
            aq[ks][0] = __float_as_uint(a4.x);
            aq[ks][1] = __float_as_uint(a4.y);
            aq[ks][2] = __float_as_uint(a4.z);
            aq[ks][3] = __float_as_uint(a4.w);
        }
    }

    float o[8][4];
    #pragma unroll
    for (int dg = 0; dg < 8; dg++)
        #pragma unroll
        for (int i = 0; i < 4; i++) o[dg][i] = 0.f;
    float mr0 = -1e30f, mr1 = -1e30f, lr0 = 0.f, lr1 = 0.f;

    const int ntiles = 2 * rb + 2;

    auto load_tile = [&](int t, int s) {
        const float* ksrc = g_kp + ((size_t)(bh * 32 + t)) * TS_F;
        const float* vsrc = g_vp + ((size_t)(bh * 32 + t)) * TS_F;
        const uint32_t kd = smb + (uint32_t)(s * TS_F) * 4;
        const uint32_t vd = smb + (uint32_t)(SMV + s * TS_F) * 4;
        #pragma unroll
        for (int i = 0; i < 4; i++) {
            const int off = (tid + i * 256) * 4;
            asm volatile("cp.async.cg.shared.global [%0], [%1], 16;"
                         :: "r"(kd + (uint32_t)off * 4), "l"(ksrc + off));
            asm volatile("cp.async.cg.shared.global [%0], [%1], 16;"
                         :: "r"(vd + (uint32_t)off * 4), "l"(vsrc + off));
        }
    };

    load_tile(0, 0);
    asm volatile("cp.async.commit_group;" ::: "memory");
    load_tile(1, 1);
    asm volatile("cp.async.commit_group;" ::: "memory");

    const int row0 = R0 + l4;
    const int row1 = R0 + l4 + 8;

    for (int t = 0; t < ntiles; t++) {
        const int s = t & 1;
        asm volatile("cp.async.wait_group 1;" ::: "memory");
        __syncthreads();

        if (t * 64 <= R0 + 15) {
            const float* Ksm = sm + s * TS_F;
            const float* Vsm = sm + SMV + s * TS_F;
            #pragma unroll
            for (int jc = 0; jc < 2; jc++) {
                const int j0c = t * 64 + jc * 32;
                if (j0c > R0 + 15) break;

                float s4[4][4];
                #pragma unroll
                for (int jg = 0; jg < 4; jg++)
                    #pragma unroll
                    for (int i = 0; i < 4; i++) s4[jg][i] = 0.f;
                #pragma unroll
                for (int ks = 0; ks < 8; ks++) {
                    #pragma unroll
                    for (int pr = 0; pr < 2; pr++) {
                        float4 b4 = *(const float4*)&Ksm[((jc * 2 + pr) * 8 + ks) * 128 + lane * 4];
                        uint32_t b0[2], b1[2];
                        b0[0] = __float_as_uint(b4.x);
                        b0[1] = __float_as_uint(b4.y);
                        b1[0] = __float_as_uint(b4.z);
                        b1[1] = __float_as_uint(b4.w);
                        MMA_TF32(s4[2 * pr],     aq[ks], b0);
                        MMA_TF32(s4[2 * pr + 1], aq[ks], b1);
                    }
                }

                if (j0c + 31 > R0) {
                    #pragma unroll
                    for (int jg = 0; jg < 4; jg++) {
                        const int jb = j0c + jg * 8 + 2 * lk;
                        if (jb     > row0) s4[jg][0] = -1e30f;
                        if (jb + 1 > row0) s4[jg][1] = -1e30f;
                        if (jb     > row1) s4[jg][2] = -1e30f;
                        if (jb + 1 > row1) s4[jg][3] = -1e30f;
                    }
                }

                float mx0 = -1e30f, mx1 = -1e30f;
                #pragma unroll
                for (int jg = 0; jg < 4; jg++) {
                    mx0 = fmaxf(mx0, fmaxf(s4[jg][0], s4[jg][1]));
                    mx1 = fmaxf(mx1, fmaxf(s4[jg][2], s4[jg][3]));
                }
                mx0 = fmaxf(mx0, __shfl_xor_sync(0xffffffffu, mx0, 1));
                mx0 = fmaxf(mx0, __shfl_xor_sync(0xffffffffu, mx0, 2));
                mx1 = fmaxf(mx1, __shfl_xor_sync(0xffffffffu, mx1, 1));
                mx1 = fmaxf(mx1, __shfl_xor_sync(0xffffffffu, mx1, 2));

                const float mn0 = fmaxf(mr0, mx0);
                const float mn1 = fmaxf(mr1, mx1);
                const float a0 = __expf(mr0 - mn0);
                const float a1 = __expf(mr1 - mn1);
                mr0 = mn0; mr1 = mn1;

                float sum0 = 0.f, sum1 = 0.f;
                float p[4][4];
                #pragma unroll
                for (int jg = 0; jg < 4; jg++) {
                    p[jg][0] = f2tf_f(__expf(s4[jg][0] - mn0));
                    p[jg][1] = f2tf_f(__expf(s4[jg][1] - mn0));
                    p[jg][2] = f2tf_f(__expf(s4[jg][2] - mn1));
                    p[jg][3] = f2tf_f(__expf(s4[jg][3] - mn1));
                    sum0 += p[jg][0] + p[jg][1];
                    sum1 += p[jg][2] + p[jg][3];
                }
                sum0 += __shfl_xor_sync(0xffffffffu, sum0, 1);
                sum0 += __shfl_xor_sync(0xffffffffu, sum0, 2);
                sum1 += __shfl_xor_sync(0xffffffffu, sum1, 1);
                sum1 += __shfl_xor_sync(0xffffffffu, sum1, 2);
                lr0 = lr0 * a0 + sum0;
                lr1 = lr1 * a1 + sum1;

                #pragma unroll
                for (int dg = 0; dg < 8; dg++) {
                    o[dg][0] *= a0; o[dg][1] *= a0;
                    o[dg][2] *= a1; o[dg][3] *= a1;
                }

                #pragma unroll
                for (int jg = 0; jg < 4; jg++) {
                    const int c0 = 2 * lk;
                    const int la = l4 * 4 + (c0 & 3);
                    const int rx = (c0 & 4) ? 2 : 0;
                    Pw[jg * 128 + la * 4 + rx]     = p[jg][0];
                    Pw[jg * 128 + la * 4 + rx + 1] = p[jg][2];
                    const int c1 = c0 + 1;
                    const int lb = l4 * 4 + (c1 & 3);
                    const int ry = (c1 & 4) ? 2 : 0;
                    Pw[jg * 128 + lb * 4 + ry]     = p[jg][1];
                    Pw[jg * 128 + lb * 4 + ry + 1] = p[jg][3];
                }
                __syncwarp();

                #pragma unroll
                for (int ksp = 0; ksp < 4; ksp++) {
                    float4 pa4 = *(const float4*)&Pw[ksp * 128 + lane * 4];
                    uint32_t pa[4];
                    pa[0] = __float_as_uint(pa4.x);
                    pa[1] = __float_as_uint(pa4.y);
                    pa[2] = __float_as_uint(pa4.z);
                    pa[3] = __float_as_uint(pa4.w);
                    const int kssj = jc * 4 + ksp;
                    #pragma unroll
                    for (int pd = 0; pd < 4; pd++) {
                        float4 b4 = *(const float4*)&Vsm[(pd * 8 + kssj) * 128 + lane * 4];
                        uint32_t b0[2], b1[2];
                        b0[0] = __float_as_uint(b4.x);
                        b0[1] = __float_as_uint(b4.y);
                        b1[0] = __float_as_uint(b4.z);
                        b1[1] = __float_as_uint(b4.w);
                        MMA_TF32(o[2 * pd],     pa, b0);
                        MMA_TF32(o[2 * pd + 1], pa, b1);
                    }
                }
                __syncwarp();
            }
        }
        __syncthreads();
        if (t + 2 < ntiles) load_tile(t + 2, s);
        asm volatile("cp.async.commit_group;" ::: "memory");
    }

    const float inv0 = 1.0f / lr0;
    const float inv1 = 1.0f / lr1;
    #pragma unroll
    for (int dg = 0; dg < 8; dg++) {
        const int col = dg * 8 + 2 * lk;
        float2 v0, v1;
        v0.x = o[dg][0] * inv0; v0.y = o[dg][1] * inv0;
        v1.x = o[dg][2] * inv1; v1.y = o[dg][3] * inv1;
        *(float2*)&ob[(size_t)row0 * Dh_ + col] = v0;
        *(float2*)&ob[(size_t)row1 * Dh_ + col] = v1;
    }
}

// ---------------------------------------------------------------------------
extern "C" void kernel_launch(void* const* d_in, const int* in_sizes, int n_in,
                              void* d_out, int out_size)
{
    const float* x   = (const float*)d_in[0];
    const float* Wq  = (const float*)d_in[1];
    const float* Wkv = (const float*)d_in[2];
    const float* Wo  = (const float*)d_in[3];
    const float* bo  = (const float*)d_in[4];
    float* out = (float*)d_out;

    static bool attr_done = false;
    if (!attr_done) {
        cudaFuncSetAttribute(proj_k,   cudaFuncAttributeMaxDynamicSharedMemorySize, P_SMEM);
        cudaFuncSetAttribute(outg_k,   cudaFuncAttributeMaxDynamicSharedMemorySize, O_SMEM);
        cudaFuncSetAttribute(flash2_k, cudaFuncAttributeMaxDynamicSharedMemorySize, FL2_BYTES);
        attr_done = true;
    }

    dim3 blk(256);
    pack_x_k<<<8192, blk>>>(x);
    pack_w_k<0><<<1024, blk>>>(Wq);
    pack_w_k<1><<<2048, blk>>>(Wkv);
    pack_w_k<2><<<1024, blk>>>(Wo);
    proj_k<<<dim3(24, 64), blk, P_SMEM>>>();
    flash2_k<<<dim3(N_ / 128, B_ * H_), blk, FL2_BYTES>>>();
    outg_k<<<dim3(8, 64), blk, O_SMEM>>>(out, bo);
}

// round 14
// speedup vs baseline: 1.4291x; 1.0488x over previous
#include <cuda_runtime.h>
#include <cstdint>
#include <math.h>

#define B_  4
#define H_  16
#define N_  2048
#define Dh_ 64
#define DIM_ 1024
#define M_  (B_*N_)          // 8192
#define ELEMS (B_*H_*N_*Dh_) // 8388608

// fragment-packed, tf32-pre-rounded operands
__device__ __align__(16) float g_xp[M_ * DIM_];
__device__ __align__(16) float g_wqp[DIM_ * DIM_];
__device__ __align__(16) float g_wkvp[DIM_ * 2 * DIM_];
__device__ __align__(16) float g_wop[DIM_ * DIM_];
// flash operands, fragment-packed by projection epilogues
__device__ __align__(16) float g_qp[ELEMS];
__device__ __align__(16) float g_kp[ELEMS];
__device__ __align__(16) float g_vp[ELEMS];
// flash output, A-fragment packed for out-GEMM (g_xp layout over k=(h,d))
__device__ __align__(16) float g_op[ELEMS];

__device__ __forceinline__ uint32_t f2tf(float f) {
    uint32_t u;
    asm("cvt.rna.tf32.f32 %0, %1;" : "=r"(u) : "f"(f));
    return u;
}
__device__ __forceinline__ float f2tf_f(float f) {
    return __uint_as_float(f2tf(f));
}
__device__ __forceinline__ uint32_t smem_u32(const void* p) {
    uint32_t a;
    asm("{ .reg .u64 t; cvta.to.shared.u64 t, %1; cvt.u32.u64 %0, t; }"
        : "=r"(a) : "l"(p));
    return a;
}

#define MMA_TF32(c, a, b) \
    asm volatile("mma.sync.aligned.m16n8k8.row.col.f32.tf32.tf32.f32 " \
        "{%0,%1,%2,%3},{%4,%5,%6,%7},{%8,%9},{%0,%1,%2,%3};" \
        : "+f"((c)[0]), "+f"((c)[1]), "+f"((c)[2]), "+f"((c)[3]) \
        : "r"((a)[0]), "r"((a)[1]), "r"((a)[2]), "r"((a)[3]), \
          "r"((b)[0]), "r"((b)[1]))

// ---------------------------------------------------------------------------
// Fused pack kernel. Grid 12288 blocks:
//   [0, 8192)       : x  -> g_xp   (A-fragments)
//   [8192, 9216)    : Wq -> g_wqp  (B-fragments)
//   [9216, 11264)   : Wkv-> g_wkvp
//   [11264, 12288)  : Wo -> g_wop
// ---------------------------------------------------------------------------
__global__ void __launch_bounds__(256) pack_all_k(
    const float* __restrict__ x, const float* __restrict__ Wq,
    const float* __restrict__ Wkv, const float* __restrict__ Wo)
{
    const int bb = blockIdx.x;
    if (bb < 8192) {
        const int t = bb * 256 + threadIdx.x;
        const int lane = t & 31, seg = (t >> 5) & 15;
        const int ktile = (t >> 9) & 63, mtile = t >> 15;
        const int grp = seg >> 1, kss = seg & 1;
        const int l4 = lane >> 2, lk = lane & 3;
        const int r = mtile * 128 + grp * 16 + l4;
        const int k = ktile * 16 + kss * 8 + lk;
        float4 v;
        v.x = f2tf_f(x[(size_t)r * DIM_ + k]);
        v.y = f2tf_f(x[(size_t)(r + 8) * DIM_ + k]);
        v.z = f2tf_f(x[(size_t)r * DIM_ + k + 4]);
        v.w = f2tf_f(x[(size_t)(r + 8) * DIM_ + k + 4]);
        reinterpret_cast<float4*>(g_xp)[t] = v;
    } else {
        const float* W;
        float* dst;
        int Ncols, t;
        if (bb < 9216)       { W = Wq;  dst = g_wqp;  Ncols = DIM_;     t = (bb - 8192) * 256 + threadIdx.x; }
        else if (bb < 11264) { W = Wkv; dst = g_wkvp; Ncols = 2 * DIM_; t = (bb - 9216) * 256 + threadIdx.x; }
        else                 { W = Wo;  dst = g_wop;  Ncols = DIM_;     t = (bb - 11264) * 256 + threadIdx.x; }
        const int lane = t & 31, seg = (t >> 5) & 15;
        const int ktile = (t >> 9) & 63, ntile = t >> 15;
        const int pair = seg >> 1, kss = seg & 1;
        const int l4 = lane >> 2, lk = lane & 3;
        const int k = ktile * 16 + kss * 8 + lk;
        const int c = ntile * 128 + pair * 16 + l4;
        float4 v;
        v.x = f2tf_f(W[(size_t)k * Ncols + c]);
        v.y = f2tf_f(W[(size_t)(k + 4) * Ncols + c]);
        v.z = f2tf_f(W[(size_t)k * Ncols + c + 8]);
        v.w = f2tf_f(W[(size_t)(k + 4) * Ncols + c + 8]);
        reinterpret_cast<float4*>(dst)[t] = v;
    }
}

// ---------------------------------------------------------------------------
// Fully-packed GEMM core (shared by proj and out). BK=32, BM=BN=128,
// 8 warps (4M x 2N), 3-stage cp.async of contiguous packed blocks.
// ---------------------------------------------------------------------------
#define P_STGF 8192
#define P_SMEM (3 * P_STGF * 4)   // 98304

template<typename EPI>
__device__ __forceinline__ void gemm_core(
    const float* __restrict__ Ap, const float* __restrict__ Bp,
    int mtile, int ntile, float* gsm, EPI epi)
{
    const int tid = threadIdx.x;
    const int wid = tid >> 5, lane = tid & 31;
    const uint32_t smb = smem_u32(gsm);

    float acc[2][8][4];
    #pragma unroll
    for (int f = 0; f < 2; f++)
        #pragma unroll
        for (int g = 0; g < 8; g++)
            #pragma unroll
            for (int i = 0; i < 4; i++) acc[f][g][i] = 0.f;

    auto load_stage = [&](int t, int s) {
        const uint32_t abase = smb + (uint32_t)(s * P_STGF) * 4;
        const uint32_t bbase = abase + 4096 * 4;
        const float* asrc = Ap + ((size_t)(mtile * 64 + 2 * t)) * 2048;
        const float* bsrc = Bp + ((size_t)(ntile * 64 + 2 * t)) * 2048;
        #pragma unroll
        for (int i = 0; i < 4; i++) {
            const int off = (tid + i * 256) * 4;
            asm volatile("cp.async.cg.shared.global [%0], [%1], 16;"
                         :: "r"(abase + (uint32_t)off * 4), "l"(asrc + off));
            asm volatile("cp.async.cg.shared.global [%0], [%1], 16;"
                         :: "r"(bbase + (uint32_t)off * 4), "l"(bsrc + off));
        }
        asm volatile("cp.async.commit_group;" ::: "memory");
    };

    load_stage(0, 0);
    load_stage(1, 1);

    const int a_seg0 = (wid & 3) * 4;
    const int b_pair0 = (wid >> 2) * 4;

    int sidx = 0;
    for (int t = 0; t < 32; t++) {
        asm volatile("cp.async.wait_group 1;" ::: "memory");
        __syncthreads();

        if (t + 2 < 32) {
            int s2 = sidx + 2; if (s2 >= 3) s2 -= 3;
            load_stage(t + 2, s2);
        } else {
            asm volatile("cp.async.commit_group;" ::: "memory");
        }

        const float* As_ = gsm + sidx * P_STGF;
        const float* Bs_ = As_ + 4096;
        #pragma unroll
        for (int kss = 0; kss < 4; kss++) {
            const int ktl = kss >> 1, k2 = kss & 1;
            uint32_t af[2][4];
            #pragma unroll
            for (int f = 0; f < 2; f++) {
                float4 a4 = *(const float4*)&As_[(ktl * 16 + a_seg0 + f * 2 + k2) * 128 + lane * 4];
                af[f][0] = __float_as_uint(a4.x);
                af[f][1] = __float_as_uint(a4.y);
                af[f][2] = __float_as_uint(a4.z);
                af[f][3] = __float_as_uint(a4.w);
            }
            #pragma unroll
            for (int pl = 0; pl < 4; pl++) {
                float4 b4 = *(const float4*)&Bs_[(ktl * 16 + (b_pair0 + pl) * 2 + k2) * 128 + lane * 4];
                uint32_t b0[2], b1[2];
                b0[0] = __float_as_uint(b4.x);
                b0[1] = __float_as_uint(b4.y);
                b1[0] = __float_as_uint(b4.z);
                b1[1] = __float_as_uint(b4.w);
                MMA_TF32(acc[0][2 * pl],     af[0], b0);
                MMA_TF32(acc[0][2 * pl + 1], af[0], b1);
                MMA_TF32(acc[1][2 * pl],     af[1], b0);
                MMA_TF32(acc[1][2 * pl + 1], af[1], b1);
            }
        }
        if (++sidx >= 3) sidx -= 3;
    }
    epi(acc);
}

// ---------------------------------------------------------------------------
// Merged projection GEMM (Q + KV). grid (24, 64).
// ---------------------------------------------------------------------------
__global__ void __launch_bounds__(256, 2) proj_k()
{
    extern __shared__ __align__(16) float gsm[];
    const int tid = threadIdx.x;
    const int wid = tid >> 5, lane = tid & 31;
    const int mtile = blockIdx.y;
    const int ntile = blockIdx.x;
    const bool isq = ntile < 8;
    const int nb = isq ? ntile : ntile - 8;
    const int m0 = mtile * 128;
    const int n0 = nb * 128;
    const int warp_row = (wid & 3) * 32;
    const int l4 = lane >> 2, lk = lane & 3;

    gemm_core(g_xp, isq ? g_wqp : g_wkvp, mtile, nb, gsm,
        [&](float (&acc)[2][8][4]) {
            const int r0 = m0 + warp_row + l4;
            const int c0 = n0 + (wid >> 2) * 64 + lk * 2;
            #pragma unroll
            for (int f = 0; f < 2; f++) {
                #pragma unroll
                for (int g = 0; g < 8; g++) {
                    const int n = c0 + g * 8;
                    #pragma unroll
                    for (int half = 0; half < 2; half++) {
                        const int m = r0 + f * 16 + half * 8;
                        float2 v;
                        v.x = acc[f][g][half * 2 + 0];
                        v.y = acc[f][g][half * 2 + 1];
                        const int b = m >> 11, nn = m & 2047;
                        if (isq) {
                            const float vx = f2tf_f(v.x * 0.125f);
                            const float vy = f2tf_f(v.y * 0.125f);
                            const int h = n >> 6, d = n & 63;
                            const size_t segb = ((size_t)(((b << 4) + h) * 128 + (nn >> 4))) * 8;
                            const int l4q = nn & 7, rhalf = (nn >> 3) & 1;
                            {
                                const int ks = d >> 3, lkq = d & 3, dh = (d >> 2) & 1;
                                g_qp[(segb + ks) * 128 + (l4q * 4 + lkq) * 4 + rhalf + 2 * dh] = vx;
                            }
                            {
                                const int d1 = d + 1;
                                const int ks = d1 >> 3, lkq = d1 & 3, dh = (d1 >> 2) & 1;
                                g_qp[(segb + ks) * 128 + (l4q * 4 + lkq) * 4 + rhalf + 2 * dh] = vy;
                            }
                        } else {
                            const float vx = f2tf_f(v.x);
                            const float vy = f2tf_f(v.y);
                            const int cc = n & 1023;
                            const int h = cc >> 6, d = cc & 63;
                            const int bh = (b << 4) + h;
                            const int tile = nn >> 6, c = nn & 63;
                            const size_t tb = ((size_t)(bh * 32 + tile)) * 32;
                            if (n < 1024) {
                                const int pair = c >> 4, l4b = c & 7, gsub = (c >> 3) & 1;
                                {
                                    const int kss = d >> 3, lkk = d & 3, kh = (d >> 2) & 1;
                                    g_kp[(tb + pair * 8 + kss) * 128 + (l4b * 4 + lkk) * 4 + gsub * 2 + kh] = vx;
                                }
                                {
                                    const int d1 = d + 1;
                                    const int kss = d1 >> 3, lkk = d1 & 3, kh = (d1 >> 2) & 1;
                                    g_kp[(tb + pair * 8 + kss) * 128 + (l4b * 4 + lkk) * 4 + gsub * 2 + kh] = vy;
                                }
                            } else {
                                const int kss = c >> 3, lkk = c & 3, kh = (c >> 2) & 1;
                                {
                                    const int pair = d >> 4, l4b = d & 7, gsub = (d >> 3) & 1;
                                    g_vp[(tb + pair * 8 + kss) * 128 + (l4b * 4 + lkk) * 4 + gsub * 2 + kh] = vx;
                                }
                                {
                                    const int d1 = d + 1;
                                    const int pair = d1 >> 4, l4b = d1 & 7, gsub = (d1 >> 3) & 1;
                                    g_vp[(tb + pair * 8 + kss) * 128 + (l4b * 4 + lkk) * 4 + gsub * 2 + kh] = vy;
                                }
                            }
                        }
                    }
                }
            }
        });
}

// ---------------------------------------------------------------------------
// Output GEMM: A = g_op (packed by flash), B = g_wop. grid (8, 64).
// ---------------------------------------------------------------------------
__global__ void __launch_bounds__(256, 2)
outg_k(float* __restrict__ Cout, const float* __restrict__ bias)
{
    extern __shared__ __align__(16) float gsm[];
    const int tid = threadIdx.x;
    const int wid = tid >> 5, lane = tid & 31;
    const int mtile = blockIdx.y, ntile = blockIdx.x;
    const int m0 = mtile * 128, n0 = ntile * 128;
    const int warp_row = (wid & 3) * 32;
    const int l4 = lane >> 2, lk = lane & 3;

    gemm_core(g_op, g_wop, mtile, ntile, gsm,
        [&](float (&acc)[2][8][4]) {
            const int r0 = m0 + warp_row + l4;
            const int c0 = n0 + (wid >> 2) * 64 + lk * 2;
            #pragma unroll
            for (int f = 0; f < 2; f++) {
                #pragma unroll
                for (int g = 0; g < 8; g++) {
                    const int n = c0 + g * 8;
                    #pragma unroll
                    for (int half = 0; half < 2; half++) {
                        const int m = r0 + f * 16 + half * 8;
                        float2 v;
                        v.x = acc[f][g][half * 2 + 0] + bias[n];
                        v.y = acc[f][g][half * 2 + 1] + bias[n + 1];
                        *(float2*)&Cout[(size_t)m * DIM_ + n] = v;
                    }
                }
            }
        });
}

// ---------------------------------------------------------------------------
// Flash attention v3 (R12 core); epilogue scatters tf32-rounded O directly
// into g_op (A-fragment packed over m=token-row, k=(h,d)).
// ---------------------------------------------------------------------------
#define TS_F 4096
#define SMV  (2*TS_F)
#define SMP  (SMV + 2*TS_F)
#define FL2_FLOATS (SMP + 8*512)
#define FL2_BYTES  (FL2_FLOATS*4)

__global__ void __launch_bounds__(256, 2) flash2_k()
{
    extern __shared__ __align__(16) float sm[];
    const int tid = threadIdx.x;
    const int bh = blockIdx.y;
    const int rb = gridDim.x - 1 - blockIdx.x;
    const int m0 = rb * 128;

    const int wid = tid >> 5, lane = tid & 31;
    const int l4 = lane >> 2, lk = lane & 3;
    const int R0 = m0 + wid * 16;

    const uint32_t smb = smem_u32(sm);
    float* Pw = sm + SMP + wid * 512;

    uint32_t aq[8][4];
    {
        const float4* qsrc = (const float4*)(g_qp
            + ((size_t)(bh * 128 + (R0 >> 4))) * 8 * 128);
        #pragma unroll
        for (int ks = 0; ks < 8; ks++) {
            float4 a4 = qsrc[ks * 32 + lane];
            aq[ks][0] = __float_as_uint(a4.x);
            aq[ks][1] = __float_as_uint(a4.y);
            aq[ks][2] = __float_as_uint(a4.z);
            aq[ks][3] = __float_as_uint(a4.w);
        }
    }

    float o[8][4];
    #pragma unroll
    for (int dg = 0; dg < 8; dg++)
        #pragma unroll
        for (int i = 0; i < 4; i++) o[dg][i] = 0.f;
    float mr0 = -1e30f, mr1 = -1e30f, lr0 = 0.f, lr1 = 0.f;

    const int ntiles = 2 * rb + 2;

    auto load_tile = [&](int t, int s) {
        const float* ksrc = g_kp + ((size_t)(bh * 32 + t)) * TS_F;
        const float* vsrc = g_vp + ((size_t)(bh * 32 + t)) * TS_F;
        const uint32_t kd = smb + (uint32_t)(s * TS_F) * 4;
        const uint32_t vd = smb + (uint32_t)(SMV + s * TS_F) * 4;
        #pragma unroll
        for (int i = 0; i < 4; i++) {
            const int off = (tid + i * 256) * 4;
            asm volatile("cp.async.cg.shared.global [%0], [%1], 16;"
                         :: "r"(kd + (uint32_t)off * 4), "l"(ksrc + off));
            asm volatile("cp.async.cg.shared.global [%0], [%1], 16;"
                         :: "r"(vd + (uint32_t)off * 4), "l"(vsrc + off));
        }
    };

    load_tile(0, 0);
    asm volatile("cp.async.commit_group;" ::: "memory");
    load_tile(1, 1);
    asm volatile("cp.async.commit_group;" ::: "memory");

    const int row0 = R0 + l4;
    const int row1 = R0 + l4 + 8;

    for (int t = 0; t < ntiles; t++) {
        const int s = t & 1;
        asm volatile("cp.async.wait_group 1;" ::: "memory");
        __syncthreads();

        if (t * 64 <= R0 + 15) {
            const float* Ksm = sm + s * TS_F;
            const float* Vsm = sm + SMV + s * TS_F;
            #pragma unroll
            for (int jc = 0; jc < 2; jc++) {
                const int j0c = t * 64 + jc * 32;
                if (j0c > R0 + 15) break;

                float s4[4][4];
                #pragma unroll
                for (int jg = 0; jg < 4; jg++)
                    #pragma unroll
                    for (int i = 0; i < 4; i++) s4[jg][i] = 0.f;
                #pragma unroll
                for (int ks = 0; ks < 8; ks++) {
                    #pragma unroll
                    for (int pr = 0; pr < 2; pr++) {
                        float4 b4 = *(const float4*)&Ksm[((jc * 2 + pr) * 8 + ks) * 128 + lane * 4];
                        uint32_t b0[2], b1[2];
                        b0[0] = __float_as_uint(b4.x);
                        b0[1] = __float_as_uint(b4.y);
                        b1[0] = __float_as_uint(b4.z);
                        b1[1] = __float_as_uint(b4.w);
                        MMA_TF32(s4[2 * pr],     aq[ks], b0);
                        MMA_TF32(s4[2 * pr + 1], aq[ks], b1);
                    }
                }

                if (j0c + 31 > R0) {
                    #pragma unroll
                    for (int jg = 0; jg < 4; jg++) {
                        const int jb = j0c + jg * 8 + 2 * lk;
                        if (jb     > row0) s4[jg][0] = -1e30f;
                        if (jb + 1 > row0) s4[jg][1] = -1e30f;
                        if (jb     > row1) s4[jg][2] = -1e30f;
                        if (jb + 1 > row1) s4[jg][3] = -1e30f;
                    }
                }

                float mx0 = -1e30f, mx1 = -1e30f;
                #pragma unroll
                for (int jg = 0; jg < 4; jg++) {
                    mx0 = fmaxf(mx0, fmaxf(s4[jg][0], s4[jg][1]));
                    mx1 = fmaxf(mx1, fmaxf(s4[jg][2], s4[jg][3]));
                }
                mx0 = fmaxf(mx0, __shfl_xor_sync(0xffffffffu, mx0, 1));
                mx0 = fmaxf(mx0, __shfl_xor_sync(0xffffffffu, mx0, 2));
                mx1 = fmaxf(mx1, __shfl_xor_sync(0xffffffffu, mx1, 1));
                mx1 = fmaxf(mx1, __shfl_xor_sync(0xffffffffu, mx1, 2));

                const float mn0 = fmaxf(mr0, mx0);
                const float mn1 = fmaxf(mr1, mx1);
                const float a0 = __expf(mr0 - mn0);
                const float a1 = __expf(mr1 - mn1);
                mr0 = mn0; mr1 = mn1;

                float sum0 = 0.f, sum1 = 0.f;
                float p[4][4];
                #pragma unroll
                for (int jg = 0; jg < 4; jg++) {
                    p[jg][0] = f2tf_f(__expf(s4[jg][0] - mn0));
                    p[jg][1] = f2tf_f(__expf(s4[jg][1] - mn0));
                    p[jg][2] = f2tf_f(__expf(s4[jg][2] - mn1));
                    p[jg][3] = f2tf_f(__expf(s4[jg][3] - mn1));
                    sum0 += p[jg][0] + p[jg][1];
                    sum1 += p[jg][2] + p[jg][3];
                }
                sum0 += __shfl_xor_sync(0xffffffffu, sum0, 1);
                sum0 += __shfl_xor_sync(0xffffffffu, sum0, 2);
                sum1 += __shfl_xor_sync(0xffffffffu, sum1, 1);
                sum1 += __shfl_xor_sync(0xffffffffu, sum1, 2);
                lr0 = lr0 * a0 + sum0;
                lr1 = lr1 * a1 + sum1;

                #pragma unroll
                for (int dg = 0; dg < 8; dg++) {
                    o[dg][0] *= a0; o[dg][1] *= a0;
                    o[dg][2] *= a1; o[dg][3] *= a1;
                }

                #pragma unroll
                for (int jg = 0; jg < 4; jg++) {
                    const int c0 = 2 * lk;
                    const int la = l4 * 4 + (c0 & 3);
                    const int rx = (c0 & 4) ? 2 : 0;
                    Pw[jg * 128 + la * 4 + rx]     = p[jg][0];
                    Pw[jg * 128 + la * 4 + rx + 1] = p[jg][2];
                    const int c1 = c0 + 1;
                    const int lb = l4 * 4 + (c1 & 3);
                    const int ry = (c1 & 4) ? 2 : 0;
                    Pw[jg * 128 + lb * 4 + ry]     = p[jg][1];
                    Pw[jg * 128 + lb * 4 + ry + 1] = p[jg][3];
                }
                __syncwarp();

                #pragma unroll
                for (int ksp = 0; ksp < 4; ksp++) {
                    float4 pa4 = *(const float4*)&Pw[ksp * 128 + lane * 4];
                    uint32_t pa[4];
                    pa[0] = __float_as_uint(pa4.x);
                    pa[1] = __float_as_uint(pa4.y);
                    pa[2] = __float_as_uint(pa4.z);
                    pa[3] = __float_as_uint(pa4.w);
                    const int kssj = jc * 4 + ksp;
                    #pragma unroll
                    for (int pd = 0; pd < 4; pd++) {
                        float4 b4 = *(const float4*)&Vsm[(pd * 8 + kssj) * 128 + lane * 4];
                        uint32_t b0[2], b1[2];
                        b0[0] = __float_as_uint(b4.x);
                        b0[1] = __float_as_uint(b4.y);
                        b1[0] = __float_as_uint(b4.z);
                        b1[1] = __float_as_uint(b4.w);
                        MMA_TF32(o[2 * pd],     pa, b0);
                        MMA_TF32(o[2 * pd + 1], pa, b1);
                    }
                }
                __syncwarp();
            }
        }
        __syncthreads();
        if (t + 2 < ntiles) load_tile(t + 2, s);
        asm volatile("cp.async.commit_group;" ::: "memory");
    }

    // ---- epilogue: scatter tf32-rounded O into g_op (A-frag packed) ----
    const float inv0 = 1.0f / lr0;
    const float inv1 = 1.0f / lr1;
    const int bq = bh >> 4, hq = bh & 15;
    #pragma unroll
    for (int dg = 0; dg < 8; dg++) {
        #pragma unroll
        for (int half = 0; half < 2; half++) {
            const int row = half ? row1 : row0;
            const int m = (bq << 11) + row;
            const int mtile = m >> 7;
            const int seg_m = ((m >> 4) & 7) * 2;
            const int ln_m = (m & 7) * 4;
            const int j_m = (m >> 3) & 1;
            const float v0 = (half ? o[dg][2] * inv1 : o[dg][0] * inv0);
            const float v1 = (half ? o[dg][3] * inv1 : o[dg][1] * inv0);
            #pragma unroll
            for (int e = 0; e < 2; e++) {
                const int c = dg * 8 + 2 * lk + e;
                const int k = (hq << 6) + c;
                const int ktile = k >> 4;
                const int seg = seg_m + ((k >> 3) & 1);
                const int ln = ln_m + (k & 3);
                const int j = j_m + 2 * ((k >> 2) & 1);
                g_op[((size_t)(mtile * 64 + ktile) * 16 + seg) * 128 + ln * 4 + j]
                    = f2tf_f(e ? v1 : v0);
            }
        }
    }
}

// ---------------------------------------------------------------------------
extern "C" void kernel_launch(void* const* d_in, const int* in_sizes, int n_in,
                              void* d_out, int out_size)
{
    const float* x   = (const float*)d_in[0];
    const float* Wq  = (const float*)d_in[1];
    const float* Wkv = (const float*)d_in[2];
    const float* Wo  = (const float*)d_in[3];
    const float* bo  = (const float*)d_in[4];
    float* out = (float*)d_out;

    static bool attr_done = false;
    if (!attr_done) {
        cudaFuncSetAttribute(proj_k,   cudaFuncAttributeMaxDynamicSharedMemorySize, P_SMEM);
        cudaFuncSetAttribute(outg_k,   cudaFuncAttributeMaxDynamicSharedMemorySize, P_SMEM);
        cudaFuncSetAttribute(flash2_k, cudaFuncAttributeMaxDynamicSharedMemorySize, FL2_BYTES);
        attr_done = true;
    }

    dim3 blk(256);
    pack_all_k<<<12288, blk>>>(x, Wq, Wkv, Wo);
    proj_k<<<dim3(24, 64), blk, P_SMEM>>>();
    flash2_k<<<dim3(N_ / 128, B_ * H_), blk, FL2_BYTES>>>();
    outg_k<<<dim3(8, 64), blk, P_SMEM>>>(out, bo);
}

// round 15
// speedup vs baseline: 2.6205x; 1.8337x over previous
#include <cuda_runtime.h>
#include <cuda_fp16.h>
#include <cstdint>
#include <math.h>

#define B_  4
#define H_  16
#define N_  2048
#define Dh_ 64
#define DIM_ 1024
#define M_  (B_*N_)          // 8192
#define ELEMS (B_*H_*N_*Dh_) // 8388608

// fp16 fragment-packed operands (u32 = half2 along k)
__device__ __align__(16) __half g_xph[M_ * DIM_];
__device__ __align__(16) __half g_wqph[DIM_ * DIM_];
__device__ __align__(16) __half g_wkvph[DIM_ * 2 * DIM_];
__device__ __align__(16) __half g_woph[DIM_ * DIM_];
__device__ __align__(16) __half g_qph[ELEMS];
__device__ __align__(16) __half g_kph[ELEMS];
__device__ __align__(16) __half g_vph[ELEMS];
__device__ __align__(16) __half g_oph[ELEMS];

__device__ __forceinline__ uint32_t h2u(float a, float b) {
    __half2 h = __floats2half2_rn(a, b);
    return *reinterpret_cast<uint32_t*>(&h);
}
__device__ __forceinline__ uint32_t smem_u32(const void* p) {
    uint32_t a;
    asm("{ .reg .u64 t; cvta.to.shared.u64 t, %1; cvt.u32.u64 %0, t; }"
        : "=r"(a) : "l"(p));
    return a;
}

#define MMA_F16(c, a, b0v, b1v) \
    asm volatile("mma.sync.aligned.m16n8k16.row.col.f32.f16.f16.f32 " \
        "{%0,%1,%2,%3},{%4,%5,%6,%7},{%8,%9},{%0,%1,%2,%3};" \
        : "+f"((c)[0]), "+f"((c)[1]), "+f"((c)[2]), "+f"((c)[3]) \
        : "r"((a)[0]), "r"((a)[1]), "r"((a)[2]), "r"((a)[3]), \
          "r"(b0v), "r"(b1v))

// ---------------------------------------------------------------------------
// Fused pack kernel.
// A layout (x/O): u32idx = ((mtile*64+ktile)*8 + grp)*128 + lane*4 + j
//   lane=(l4,lk): j0=(r,2lk|2lk+1) j1=(r+8,..) j2=(r,2lk+8|+9) j3=(r+8,..)
//   r = mtile*128+grp*16+l4, kbase = ktile*16
// B layout (W):  u32idx = ((ntile*64+ktile)*8 + pair)*128 + lane*4 + j
//   j0=(2lk|2lk+1, c) j1=(2lk+8|+9, c) j2,j3 same at c+8; c = ntile*128+pair*16+l4
// Grid: x [0,4096), Wq [4096,4608), Wkv [4608,5632), Wo [5632,6144)
// ---------------------------------------------------------------------------
__global__ void __launch_bounds__(256) pack_all_k(
    const float* __restrict__ x, const float* __restrict__ Wq,
    const float* __restrict__ Wkv, const float* __restrict__ Wo)
{
    const int bb = blockIdx.x;
    if (bb < 4096) {
        const int t = bb * 256 + threadIdx.x;       // uint4 index
        const int lane = t & 31, grp = (t >> 5) & 7;
        const int ktile = (t >> 8) & 63, mtile = t >> 14;
        const int l4 = lane >> 2, lk = lane & 3;
        const int r = mtile * 128 + grp * 16 + l4;
        const int kb = ktile * 16 + 2 * lk;
        const float* x0 = x + (size_t)r * DIM_ + kb;
        const float* x1 = x + (size_t)(r + 8) * DIM_ + kb;
        uint4 v;
        v.x = h2u(x0[0], x0[1]);
        v.y = h2u(x1[0], x1[1]);
        v.z = h2u(x0[8], x0[9]);
        v.w = h2u(x1[8], x1[9]);
        reinterpret_cast<uint4*>(g_xph)[t] = v;
    } else {
        const float* W;
        __half* dst;
        int Nc, t;
        if (bb < 4608)      { W = Wq;  dst = g_wqph;  Nc = DIM_;     t = (bb - 4096) * 256 + threadIdx.x; }
        else if (bb < 5632) { W = Wkv; dst = g_wkvph; Nc = 2 * DIM_; t = (bb - 4608) * 256 + threadIdx.x; }
        else                { W = Wo;  dst = g_woph;  Nc = DIM_;     t = (bb - 5632) * 256 + threadIdx.x; }
        const int lane = t & 31, pair = (t >> 5) & 7;
        const int ktile = (t >> 8) & 63, ntile = t >> 14;
        const int l4 = lane >> 2, lk = lane & 3;
        const int k = ktile * 16 + 2 * lk;
        const int c = ntile * 128 + pair * 16 + l4;
        uint4 v;
        v.x = h2u(W[(size_t)k * Nc + c],           W[(size_t)(k + 1) * Nc + c]);
        v.y = h2u(W[(size_t)(k + 8) * Nc + c],     W[(size_t)(k + 9) * Nc + c]);
        v.z = h2u(W[(size_t)k * Nc + c + 8],       W[(size_t)(k + 1) * Nc + c + 8]);
        v.w = h2u(W[(size_t)(k + 8) * Nc + c + 8], W[(size_t)(k + 9) * Nc + c + 8]);
        reinterpret_cast<uint4*>(dst)[t] = v;
    }
}

// ---------------------------------------------------------------------------
// fp16 GEMM core: BM=BN=128, BK=64, 8 warps (4M x 2N), 3-stage cp.async.
// Stage = 4 k16-tiles of A (1024 uint4) + same of B.
// ---------------------------------------------------------------------------
#define P_STGU4 2048
#define P_SMEM (3 * P_STGU4 * 16)   // 98304 B

template<typename EPI>
__device__ __forceinline__ void gemm_core(
    const uint4* __restrict__ Ap, const uint4* __restrict__ Bp,
    int mtile, int ntile, uint4* gsm4, EPI epi)
{
    const int tid = threadIdx.x;
    const int wid = tid >> 5, lane = tid & 31;
    const uint32_t smb = smem_u32(gsm4);

    float acc[2][8][4];
    #pragma unroll
    for (int f = 0; f < 2; f++)
        #pragma unroll
        for (int g = 0; g < 8; g++)
            #pragma unroll
            for (int i = 0; i < 4; i++) acc[f][g][i] = 0.f;

    auto load_stage = [&](int t, int s) {
        const uint32_t abase = smb + (uint32_t)(s * P_STGU4) * 16;
        const uint32_t bbase = abase + 1024 * 16;
        const uint4* asrc = Ap + ((size_t)(mtile * 64 + 4 * t)) * 256;
        const uint4* bsrc = Bp + ((size_t)(ntile * 64 + 4 * t)) * 256;
        #pragma unroll
        for (int i = 0; i < 4; i++) {
            const int off = tid + i * 256;
            asm volatile("cp.async.cg.shared.global [%0], [%1], 16;"
                         :: "r"(abase + (uint32_t)off * 16), "l"(asrc + off));
            asm volatile("cp.async.cg.shared.global [%0], [%1], 16;"
                         :: "r"(bbase + (uint32_t)off * 16), "l"(bsrc + off));
        }
        asm volatile("cp.async.commit_group;" ::: "memory");
    };

    load_stage(0, 0);
    load_stage(1, 1);

    const int a_grp0 = (wid & 3) * 2;
    const int b_pair0 = (wid >> 2) * 4;

    int sidx = 0;
    for (int t = 0; t < 16; t++) {
        asm volatile("cp.async.wait_group 1;" ::: "memory");
        __syncthreads();

        if (t + 2 < 16) {
            int s2 = sidx + 2; if (s2 >= 3) s2 -= 3;
            load_stage(t + 2, s2);
        } else {
            asm volatile("cp.async.commit_group;" ::: "memory");
        }

        const uint4* As_ = gsm4 + sidx * P_STGU4;
        const uint4* Bs_ = As_ + 1024;
        #pragma unroll
        for (int kt = 0; kt < 4; kt++) {
            uint32_t af[2][4];
            #pragma unroll
            for (int f = 0; f < 2; f++) {
                uint4 a4 = As_[(kt * 8 + a_grp0 + f) * 32 + lane];
                af[f][0] = a4.x; af[f][1] = a4.y; af[f][2] = a4.z; af[f][3] = a4.w;
            }
            #pragma unroll
            for (int pl = 0; pl < 4; pl++) {
                uint4 b4 = Bs_[(kt * 8 + b_pair0 + pl) * 32 + lane];
                MMA_F16(acc[0][2 * pl],     af[0], b4.x, b4.y);
                MMA_F16(acc[0][2 * pl + 1], af[0], b4.z, b4.w);
                MMA_F16(acc[1][2 * pl],     af[1], b4.x, b4.y);
                MMA_F16(acc[1][2 * pl + 1], af[1], b4.z, b4.w);
            }
        }
        if (++sidx >= 3) sidx -= 3;
    }
    epi(acc);
}

// ---------------------------------------------------------------------------
// Merged projection GEMM (Q + KV). grid (24, 64).
// ---------------------------------------------------------------------------
__global__ void __launch_bounds__(256, 2) proj_k()
{
    extern __shared__ __align__(16) uint4 gsm4[];
    const int tid = threadIdx.x;
    const int wid = tid >> 5, lane = tid & 31;
    const int mtile = blockIdx.y;
    const int ntile = blockIdx.x;
    const bool isq = ntile < 8;
    const int nb = isq ? ntile : ntile - 8;
    const int m0 = mtile * 128;
    const int n0 = nb * 128;
    const int warp_row = (wid & 3) * 32;
    const int l4 = lane >> 2, lk = lane & 3;

    gemm_core((const uint4*)g_xph,
              isq ? (const uint4*)g_wqph : (const uint4*)g_wkvph,
              mtile, nb, gsm4,
        [&](float (&acc)[2][8][4]) {
            const int r0 = m0 + warp_row + l4;
            const int c0 = n0 + (wid >> 2) * 64 + lk * 2;
            #pragma unroll
            for (int f = 0; f < 2; f++) {
                #pragma unroll
                for (int g = 0; g < 8; g++) {
                    const int n = c0 + g * 8;
                    #pragma unroll
                    for (int half_ = 0; half_ < 2; half_++) {
                        const int m = r0 + f * 16 + half_ * 8;
                        const float vx = acc[f][g][half_ * 2 + 0];
                        const float vy = acc[f][g][half_ * 2 + 1];
                        const int b = m >> 11, nn = m & 2047;
                        if (isq) {
                            const int bh = (b << 4) + (n >> 6);
                            const int d = n & 63;
                            const int rowgrp = nn >> 4, l4q = nn & 7, rh = (nn >> 3) & 1;
                            const int kt = d >> 4, cc = d & 15;
                            const int lkq = (cc & 7) >> 1, hi = (cc >> 3) & 1;
                            const size_t idx = ((size_t)(bh * 128 + rowgrp) * 4 + kt) * 128
                                             + (l4q * 4 + lkq) * 4 + rh + 2 * hi;
                            reinterpret_cast<uint32_t*>(g_qph)[idx] =
                                h2u(vx * 0.125f, vy * 0.125f);
                        } else {
                            const int cfull = n & 1023;
                            const int h = cfull >> 6, d = cfull & 63;
                            const int bh = (b << 4) + h;
                            const int tile = nn >> 6, ctok = nn & 63;
                            if (n < 1024) {
                                // K: k=d (half2 pair), col=token
                                const int pair = ctok >> 4, l4b = ctok & 7, gsub = (ctok >> 3) & 1;
                                const int kt = d >> 4, cc = d & 15;
                                const int lkk = (cc & 7) >> 1, khi = (cc >> 3) & 1;
                                const size_t idx = ((size_t)(bh * 32 + tile) * 16 + kt * 4 + pair) * 128
                                                 + (l4b * 4 + lkk) * 4 + gsub * 2 + khi;
                                reinterpret_cast<uint32_t*>(g_kph)[idx] = h2u(vx, vy);
                            } else {
                                // V: k=token, col=d -> two half stores
                                const int ktok = ctok >> 4, cct = ctok & 15;
                                const int lkt = (cct & 7) >> 1, khit = (cct >> 3) & 1;
                                const int hpos = ctok & 1;
                                #pragma unroll
                                for (int e = 0; e < 2; e++) {
                                    const int dd = d + e;
                                    const int pairv = dd >> 4, l4v = dd & 7, gsv = (dd >> 3) & 1;
                                    const size_t idx = ((size_t)(bh * 32 + tile) * 16 + ktok * 4 + pairv) * 128
                                                     + (l4v * 4 + lkt) * 4 + gsv * 2 + khit;
                                    g_vph[idx * 2 + hpos] = __float2half_rn(e ? vy : vx);
                                }
                            }
                        }
                    }
                }
            }
        });
}

// ---------------------------------------------------------------------------
// Output GEMM: A = g_oph (packed by flash), B = g_woph. grid (8, 64).
// ---------------------------------------------------------------------------
__global__ void __launch_bounds__(256, 2)
outg_k(float* __restrict__ Cout, const float* __restrict__ bias)
{
    extern __shared__ __align__(16) uint4 gsm4[];
    const int tid = threadIdx.x;
    const int wid = tid >> 5, lane = tid & 31;
    const int mtile = blockIdx.y, ntile = blockIdx.x;
    const int m0 = mtile * 128, n0 = ntile * 128;
    const int warp_row = (wid & 3) * 32;
    const int l4 = lane >> 2, lk = lane & 3;

    gemm_core((const uint4*)g_oph, (const uint4*)g_woph, mtile, ntile, gsm4,
        [&](float (&acc)[2][8][4]) {
            const int r0 = m0 + warp_row + l4;
            const int c0 = n0 + (wid >> 2) * 64 + lk * 2;
            #pragma unroll
            for (int f = 0; f < 2; f++) {
                #pragma unroll
                for (int g = 0; g < 8; g++) {
                    const int n = c0 + g * 8;
                    #pragma unroll
                    for (int half_ = 0; half_ < 2; half_++) {
                        const int m = r0 + f * 16 + half_ * 8;
                        float2 v;
                        v.x = acc[f][g][half_ * 2 + 0] + bias[n];
                        v.y = acc[f][g][half_ * 2 + 1] + bias[n + 1];
                        *(float2*)&Cout[(size_t)m * DIM_ + n] = v;
                    }
                }
            }
        });
}

// ---------------------------------------------------------------------------
// Flash attention fp16: S C-frag == PV A-frag (register identity, no P smem).
// K/V tiles: 8KB each, cp.async double-buffered.
// ---------------------------------------------------------------------------
#define FL_BYTES (2048 * 16)   // 32768: K 2x512 uint4 + V 2x512 uint4

__global__ void __launch_bounds__(256, 2) flash2_k()
{
    extern __shared__ __align__(16) uint4 smv4[];
    const int tid = threadIdx.x;
    const int bh = blockIdx.y;
    const int rb = gridDim.x - 1 - blockIdx.x;
    const int m0 = rb * 128;

    const int wid = tid >> 5, lane = tid & 31;
    const int l4 = lane >> 2, lk = lane & 3;
    const int R0 = m0 + wid * 16;

    const uint32_t smb = smem_u32(smv4);

    // Q A-fragments: 4 LDG.128
    uint32_t aq[4][4];
    {
        const uint4* qsrc = (const uint4*)g_qph + ((size_t)(bh * 128 + (R0 >> 4))) * 128;
        #pragma unroll
        for (int kt = 0; kt < 4; kt++) {
            uint4 a4 = qsrc[kt * 32 + lane];
            aq[kt][0] = a4.x; aq[kt][1] = a4.y; aq[kt][2] = a4.z; aq[kt][3] = a4.w;
        }
    }

    float o[8][4];
    #pragma unroll
    for (int dg = 0; dg < 8; dg++)
        #pragma unroll
        for (int i = 0; i < 4; i++) o[dg][i] = 0.f;
    float mr0 = -1e30f, mr1 = -1e30f, lr0 = 0.f, lr1 = 0.f;

    const int ntiles = 2 * rb + 2;

    auto load_tile = [&](int t, int s) {
        const uint4* ksrc = (const uint4*)g_kph + ((size_t)(bh * 32 + t)) * 512;
        const uint4* vsrc = (const uint4*)g_vph + ((size_t)(bh * 32 + t)) * 512;
        const uint32_t kd = smb + (uint32_t)(s * 512) * 16;
        const uint32_t vd = smb + (uint32_t)(1024 + s * 512) * 16;
        #pragma unroll
        for (int i = 0; i < 2; i++) {
            const int off = tid + i * 256;
            asm volatile("cp.async.cg.shared.global [%0], [%1], 16;"
                         :: "r"(kd + (uint32_t)off * 16), "l"(ksrc + off));
            asm volatile("cp.async.cg.shared.global [%0], [%1], 16;"
                         :: "r"(vd + (uint32_t)off * 16), "l"(vsrc + off));
        }
    };

    load_tile(0, 0);
    asm volatile("cp.async.commit_group;" ::: "memory");
    load_tile(1, 1);
    asm volatile("cp.async.commit_group;" ::: "memory");

    const int row0 = R0 + l4;
    const int row1 = R0 + l4 + 8;

    for (int t = 0; t < ntiles; t++) {
        const int s = t & 1;
        asm volatile("cp.async.wait_group 1;" ::: "memory");
        __syncthreads();

        if (t * 64 <= R0 + 15) {
            const uint4* Ksm = smv4 + s * 512;
            const uint4* Vsm = smv4 + 1024 + s * 512;
            #pragma unroll
            for (int jc = 0; jc < 2; jc++) {
                const int j0c = t * 64 + jc * 32;
                if (j0c > R0 + 15) break;

                // ---- S = Q K^T ----
                float s4[4][4];
                #pragma unroll
                for (int jg = 0; jg < 4; jg++)
                    #pragma unroll
                    for (int i = 0; i < 4; i++) s4[jg][i] = 0.f;
                #pragma unroll
                for (int kt = 0; kt < 4; kt++) {
                    #pragma unroll
                    for (int pr = 0; pr < 2; pr++) {
                        uint4 b4 = Ksm[(kt * 4 + jc * 2 + pr) * 32 + lane];
                        MMA_F16(s4[2 * pr],     aq[kt], b4.x, b4.y);
                        MMA_F16(s4[2 * pr + 1], aq[kt], b4.z, b4.w);
                    }
                }

                if (j0c + 31 > R0) {
                    #pragma unroll
                    for (int jg = 0; jg < 4; jg++) {
                        const int jb = j0c + jg * 8 + 2 * lk;
                        if (jb     > row0) s4[jg][0] = -1e30f;
                        if (jb + 1 > row0) s4[jg][1] = -1e30f;
                        if (jb     > row1) s4[jg][2] = -1e30f;
                        if (jb + 1 > row1) s4[jg][3] = -1e30f;
                    }
                }

                float mx0 = -1e30f, mx1 = -1e30f;
                #pragma unroll
                for (int jg = 0; jg < 4; jg++) {
                    mx0 = fmaxf(mx0, fmaxf(s4[jg][0], s4[jg][1]));
                    mx1 = fmaxf(mx1, fmaxf(s4[jg][2], s4[jg][3]));
                }
                mx0 = fmaxf(mx0, __shfl_xor_sync(0xffffffffu, mx0, 1));
                mx0 = fmaxf(mx0, __shfl_xor_sync(0xffffffffu, mx0, 2));
                mx1 = fmaxf(mx1, __shfl_xor_sync(0xffffffffu, mx1, 1));
                mx1 = fmaxf(mx1, __shfl_xor_sync(0xffffffffu, mx1, 2));

                const float mn0 = fmaxf(mr0, mx0);
                const float mn1 = fmaxf(mr1, mx1);
                const float a0 = __expf(mr0 - mn0);
                const float a1 = __expf(mr1 - mn1);
                mr0 = mn0; mr1 = mn1;

                float sum0 = 0.f, sum1 = 0.f;
                float p[4][4];
                #pragma unroll
                for (int jg = 0; jg < 4; jg++) {
                    p[jg][0] = __expf(s4[jg][0] - mn0);
                    p[jg][1] = __expf(s4[jg][1] - mn0);
                    p[jg][2] = __expf(s4[jg][2] - mn1);
                    p[jg][3] = __expf(s4[jg][3] - mn1);
                    sum0 += p[jg][0] + p[jg][1];
                    sum1 += p[jg][2] + p[jg][3];
                }
                sum0 += __shfl_xor_sync(0xffffffffu, sum0, 1);
                sum0 += __shfl_xor_sync(0xffffffffu, sum0, 2);
                sum1 += __shfl_xor_sync(0xffffffffu, sum1, 1);
                sum1 += __shfl_xor_sync(0xffffffffu, sum1, 2);
                lr0 = lr0 * a0 + sum0;
                lr1 = lr1 * a1 + sum1;

                #pragma unroll
                for (int dg = 0; dg < 8; dg++) {
                    o[dg][0] *= a0; o[dg][1] *= a0;
                    o[dg][2] *= a1; o[dg][3] *= a1;
                }

                // ---- P A-fragments directly from registers ----
                uint32_t pa[2][4];
                #pragma unroll
                for (int kc = 0; kc < 2; kc++) {
                    pa[kc][0] = h2u(p[2 * kc][0],     p[2 * kc][1]);
                    pa[kc][1] = h2u(p[2 * kc][2],     p[2 * kc][3]);
                    pa[kc][2] = h2u(p[2 * kc + 1][0], p[2 * kc + 1][1]);
                    pa[kc][3] = h2u(p[2 * kc + 1][2], p[2 * kc + 1][3]);
                }

                // ---- O += P V ----
                #pragma unroll
                for (int kc = 0; kc < 2; kc++) {
                    #pragma unroll
                    for (int pd = 0; pd < 4; pd++) {
                        uint4 b4 = Vsm[((jc * 2 + kc) * 4 + pd) * 32 + lane];
                        MMA_F16(o[2 * pd],     pa[kc], b4.x, b4.y);
                        MMA_F16(o[2 * pd + 1], pa[kc], b4.z, b4.w);
                    }
                }
            }
        }
        __syncthreads();
        if (t + 2 < ntiles) load_tile(t + 2, s);
        asm volatile("cp.async.commit_group;" ::: "memory");
    }

    // ---- epilogue: O -> g_oph (A-frag pack, k=(h,d)) ----
    const float inv0 = 1.0f / lr0;
    const float inv1 = 1.0f / lr1;
    const int bq = bh >> 4, hq = bh & 15;
    #pragma unroll
    for (int dg = 0; dg < 8; dg++) {
        #pragma unroll
        for (int half_ = 0; half_ < 2; half_++) {
            const int row = half_ ? row1 : row0;
            const int m = (bq << 11) + row;
            const float v0 = (half_ ? o[dg][2] * inv1 : o[dg][0] * inv0);
            const float v1 = (half_ ? o[dg][3] * inv1 : o[dg][1] * inv0);
            const int col = dg * 8 + 2 * lk;
            const int k = (hq << 6) + col;
            const int mt = m >> 7, grp = (m >> 4) & 7, l4m = m & 7, rh = (m >> 3) & 1;
            const int kt = k >> 4, cc = k & 15;
            const int lkk = (cc & 7) >> 1, hi = (cc >> 3) & 1;
            const size_t idx = ((size_t)(mt * 64 + kt) * 8 + grp) * 128
                             + (l4m * 4 + lkk) * 4 + rh + 2 * hi;
            reinterpret_cast<uint32_t*>(g_oph)[idx] = h2u(v0, v1);
        }
    }
}

// ---------------------------------------------------------------------------
extern "C" void kernel_launch(void* const* d_in, const int* in_sizes, int n_in,
                              void* d_out, int out_size)
{
    const float* x   = (const float*)d_in[0];
    const float* Wq  = (const float*)d_in[1];
    const float* Wkv = (const float*)d_in[2];
    const float* Wo  = (const float*)d_in[3];
    const float* bo  = (const float*)d_in[4];
    float* out = (float*)d_out;

    static bool attr_done = false;
    if (!attr_done) {
        cudaFuncSetAttribute(proj_k,   cudaFuncAttributeMaxDynamicSharedMemorySize, P_SMEM);
        cudaFuncSetAttribute(outg_k,   cudaFuncAttributeMaxDynamicSharedMemorySize, P_SMEM);
        cudaFuncSetAttribute(flash2_k, cudaFuncAttributeMaxDynamicSharedMemorySize, FL_BYTES);
        attr_done = true;
    }

    dim3 blk(256);
    pack_all_k<<<6144, blk>>>(x, Wq, Wkv, Wo);
    proj_k<<<dim3(24, 64), blk, P_SMEM>>>();
    flash2_k<<<dim3(N_ / 128, B_ * H_), blk, FL_BYTES>>>();
    outg_k<<<dim3(8, 64), blk, P_SMEM>>>(out, bo);
}

// round 16
// speedup vs baseline: 2.6813x; 1.0232x over previous
#include <cuda_runtime.h>
#include <cuda_fp16.h>
#include <cstdint>
#include <math.h>

#define B_  4
#define H_  16
#define N_  2048
#define Dh_ 64
#define DIM_ 1024
#define M_  (B_*N_)          // 8192
#define ELEMS (B_*H_*N_*Dh_) // 8388608
#define NCTA 296             // 2 CTAs/SM x 148 SMs

// fp16 fragment-packed operands (u32 = half2 along k)
__device__ __align__(16) __half g_xph[M_ * DIM_];
__device__ __align__(16) __half g_wqph[DIM_ * DIM_];
__device__ __align__(16) __half g_wkvph[DIM_ * 2 * DIM_];
__device__ __align__(16) __half g_woph[DIM_ * DIM_];
__device__ __align__(16) __half g_qph[ELEMS];
__device__ __align__(16) __half g_kph[ELEMS];
__device__ __align__(16) __half g_vph[ELEMS];
__device__ __align__(16) __half g_oph[ELEMS];

__device__ __forceinline__ uint32_t h2u(float a, float b) {
    __half2 h = __floats2half2_rn(a, b);
    return *reinterpret_cast<uint32_t*>(&h);
}
__device__ __forceinline__ uint32_t smem_u32(const void* p) {
    uint32_t a;
    asm("{ .reg .u64 t; cvta.to.shared.u64 t, %1; cvt.u32.u64 %0, t; }"
        : "=r"(a) : "l"(p));
    return a;
}

#define MMA_F16(c, a, b0v, b1v) \
    asm volatile("mma.sync.aligned.m16n8k16.row.col.f32.f16.f16.f32 " \
        "{%0,%1,%2,%3},{%4,%5,%6,%7},{%8,%9},{%0,%1,%2,%3};" \
        : "+f"((c)[0]), "+f"((c)[1]), "+f"((c)[2]), "+f"((c)[3]) \
        : "r"((a)[0]), "r"((a)[1]), "r"((a)[2]), "r"((a)[3]), \
          "r"(b0v), "r"(b1v))

// ---------------------------------------------------------------------------
// Fused pack kernel (verbatim R15).
// ---------------------------------------------------------------------------
__global__ void __launch_bounds__(256) pack_all_k(
    const float* __restrict__ x, const float* __restrict__ Wq,
    const float* __restrict__ Wkv, const float* __restrict__ Wo)
{
    const int bb = blockIdx.x;
    if (bb < 4096) {
        const int t = bb * 256 + threadIdx.x;
        const int lane = t & 31, grp = (t >> 5) & 7;
        const int ktile = (t >> 8) & 63, mtile = t >> 14;
        const int l4 = lane >> 2, lk = lane & 3;
        const int r = mtile * 128 + grp * 16 + l4;
        const int kb = ktile * 16 + 2 * lk;
        const float* x0 = x + (size_t)r * DIM_ + kb;
        const float* x1 = x + (size_t)(r + 8) * DIM_ + kb;
        uint4 v;
        v.x = h2u(x0[0], x0[1]);
        v.y = h2u(x1[0], x1[1]);
        v.z = h2u(x0[8], x0[9]);
        v.w = h2u(x1[8], x1[9]);
        reinterpret_cast<uint4*>(g_xph)[t] = v;
    } else {
        const float* W;
        __half* dst;
        int Nc, t;
        if (bb < 4608)      { W = Wq;  dst = g_wqph;  Nc = DIM_;     t = (bb - 4096) * 256 + threadIdx.x; }
        else if (bb < 5632) { W = Wkv; dst = g_wkvph; Nc = 2 * DIM_; t = (bb - 4608) * 256 + threadIdx.x; }
        else                { W = Wo;  dst = g_woph;  Nc = DIM_;     t = (bb - 5632) * 256 + threadIdx.x; }
        const int lane = t & 31, pair = (t >> 5) & 7;
        const int ktile = (t >> 8) & 63, ntile = t >> 14;
        const int l4 = lane >> 2, lk = lane & 3;
        const int k = ktile * 16 + 2 * lk;
        const int c = ntile * 128 + pair * 16 + l4;
        uint4 v;
        v.x = h2u(W[(size_t)k * Nc + c],           W[(size_t)(k + 1) * Nc + c]);
        v.y = h2u(W[(size_t)(k + 8) * Nc + c],     W[(size_t)(k + 9) * Nc + c]);
        v.z = h2u(W[(size_t)k * Nc + c + 8],       W[(size_t)(k + 1) * Nc + c + 8]);
        v.w = h2u(W[(size_t)(k + 8) * Nc + c + 8], W[(size_t)(k + 9) * Nc + c + 8]);
        reinterpret_cast<uint4*>(dst)[t] = v;
    }
}

// ---------------------------------------------------------------------------
// fp16 GEMM core (verbatim R15 + entry __syncthreads for tile-reuse safety).
// ---------------------------------------------------------------------------
#define P_STGU4 2048
#define P_SMEM (3 * P_STGU4 * 16)   // 98304 B

template<typename EPI>
__device__ __forceinline__ void gemm_core(
    const uint4* __restrict__ Ap, const uint4* __restrict__ Bp,
    int mtile, int ntile, uint4* gsm4, EPI epi)
{
    const int tid = threadIdx.x;
    const int wid = tid >> 5, lane = tid & 31;
    const uint32_t smb = smem_u32(gsm4);

    __syncthreads();   // all warps done reading smem of previous tile

    float acc[2][8][4];
    #pragma unroll
    for (int f = 0; f < 2; f++)
        #pragma unroll
        for (int g = 0; g < 8; g++)
            #pragma unroll
            for (int i = 0; i < 4; i++) acc[f][g][i] = 0.f;

    auto load_stage = [&](int t, int s) {
        const uint32_t abase = smb + (uint32_t)(s * P_STGU4) * 16;
        const uint32_t bbase = abase + 1024 * 16;
        const uint4* asrc = Ap + ((size_t)(mtile * 64 + 4 * t)) * 256;
        const uint4* bsrc = Bp + ((size_t)(ntile * 64 + 4 * t)) * 256;
        #pragma unroll
        for (int i = 0; i < 4; i++) {
            const int off = tid + i * 256;
            asm volatile("cp.async.cg.shared.global [%0], [%1], 16;"
                         :: "r"(abase + (uint32_t)off * 16), "l"(asrc + off));
            asm volatile("cp.async.cg.shared.global [%0], [%1], 16;"
                         :: "r"(bbase + (uint32_t)off * 16), "l"(bsrc + off));
        }
        asm volatile("cp.async.commit_group;" ::: "memory");
    };

    load_stage(0, 0);
    load_stage(1, 1);

    const int a_grp0 = (wid & 3) * 2;
    const int b_pair0 = (wid >> 2) * 4;

    int sidx = 0;
    for (int t = 0; t < 16; t++) {
        asm volatile("cp.async.wait_group 1;" ::: "memory");
        __syncthreads();

        if (t + 2 < 16) {
            int s2 = sidx + 2; if (s2 >= 3) s2 -= 3;
            load_stage(t + 2, s2);
        } else {
            asm volatile("cp.async.commit_group;" ::: "memory");
        }

        const uint4* As_ = gsm4 + sidx * P_STGU4;
        const uint4* Bs_ = As_ + 1024;
        #pragma unroll
        for (int kt = 0; kt < 4; kt++) {
            uint32_t af[2][4];
            #pragma unroll
            for (int f = 0; f < 2; f++) {
                uint4 a4 = As_[(kt * 8 + a_grp0 + f) * 32 + lane];
                af[f][0] = a4.x; af[f][1] = a4.y; af[f][2] = a4.z; af[f][3] = a4.w;
            }
            #pragma unroll
            for (int pl = 0; pl < 4; pl++) {
                uint4 b4 = Bs_[(kt * 8 + b_pair0 + pl) * 32 + lane];
                MMA_F16(acc[0][2 * pl],     af[0], b4.x, b4.y);
                MMA_F16(acc[0][2 * pl + 1], af[0], b4.z, b4.w);
                MMA_F16(acc[1][2 * pl],     af[1], b4.x, b4.y);
                MMA_F16(acc[1][2 * pl + 1], af[1], b4.z, b4.w);
            }
        }
        if (++sidx >= 3) sidx -= 3;
    }
    epi(acc);
}

// ---------------------------------------------------------------------------
// Merged projection GEMM (Q + KV), persistent grid-stride over 1536 tiles.
// ---------------------------------------------------------------------------
__global__ void __launch_bounds__(256, 2) proj_k()
{
    extern __shared__ __align__(16) uint4 gsm4[];
    const int tid = threadIdx.x;
    const int wid = tid >> 5, lane = tid & 31;
    const int warp_row = (wid & 3) * 32;
    const int l4 = lane >> 2, lk = lane & 3;

    for (int tile = blockIdx.x; tile < 24 * 64; tile += gridDim.x) {
        const int mtile = tile / 24;
        const int ntile = tile % 24;
        const bool isq = ntile < 8;
        const int nb = isq ? ntile : ntile - 8;
        const int m0 = mtile * 128;
        const int n0 = nb * 128;

        gemm_core((const uint4*)g_xph,
                  isq ? (const uint4*)g_wqph : (const uint4*)g_wkvph,
                  mtile, nb, gsm4,
            [&](float (&acc)[2][8][4]) {
                const int r0 = m0 + warp_row + l4;
                const int c0 = n0 + (wid >> 2) * 64 + lk * 2;
                #pragma unroll
                for (int f = 0; f < 2; f++) {
                    #pragma unroll
                    for (int g = 0; g < 8; g++) {
                        const int n = c0 + g * 8;
                        #pragma unroll
                        for (int half_ = 0; half_ < 2; half_++) {
                            const int m = r0 + f * 16 + half_ * 8;
                            const float vx = acc[f][g][half_ * 2 + 0];
                            const float vy = acc[f][g][half_ * 2 + 1];
                            const int b = m >> 11, nn = m & 2047;
                            if (isq) {
                                const int bh = (b << 4) + (n >> 6);
                                const int d = n & 63;
                                const int rowgrp = nn >> 4, l4q = nn & 7, rh = (nn >> 3) & 1;
                                const int kt = d >> 4, cc = d & 15;
                                const int lkq = (cc & 7) >> 1, hi = (cc >> 3) & 1;
                                const size_t idx = ((size_t)(bh * 128 + rowgrp) * 4 + kt) * 128
                                                 + (l4q * 4 + lkq) * 4 + rh + 2 * hi;
                                reinterpret_cast<uint32_t*>(g_qph)[idx] =
                                    h2u(vx * 0.125f, vy * 0.125f);
                            } else {
                                const int cfull = n & 1023;
                                const int h = cfull >> 6, d = cfull & 63;
                                const int bh = (b << 4) + h;
                                const int tile64 = nn >> 6, ctok = nn & 63;
                                if (n < 1024) {
                                    const int pair = ctok >> 4, l4b = ctok & 7, gsub = (ctok >> 3) & 1;
                                    const int kt = d >> 4, cc = d & 15;
                                    const int lkk = (cc & 7) >> 1, khi = (cc >> 3) & 1;
                                    const size_t idx = ((size_t)(bh * 32 + tile64) * 16 + kt * 4 + pair) * 128
                                                     + (l4b * 4 + lkk) * 4 + gsub * 2 + khi;
                                    reinterpret_cast<uint32_t*>(g_kph)[idx] = h2u(vx, vy);
                                } else {
                                    const int ktok = ctok >> 4, cct = ctok & 15;
                                    const int lkt = (cct & 7) >> 1, khit = (cct >> 3) & 1;
                                    const int hpos = ctok & 1;
                                    #pragma unroll
                                    for (int e = 0; e < 2; e++) {
                                        const int dd = d + e;
                                        const int pairv = dd >> 4, l4v = dd & 7, gsv = (dd >> 3) & 1;
                                        const size_t idx = ((size_t)(bh * 32 + tile64) * 16 + ktok * 4 + pairv) * 128
                                                         + (l4v * 4 + lkt) * 4 + gsv * 2 + khit;
                                        g_vph[idx * 2 + hpos] = __float2half_rn(e ? vy : vx);
                                    }
                                }
                            }
                        }
                    }
                }
            });
    }
}

// ---------------------------------------------------------------------------
// Output GEMM, persistent grid-stride over 512 tiles.
// ---------------------------------------------------------------------------
__global__ void __launch_bounds__(256, 2)
outg_k(float* __restrict__ Cout, const float* __restrict__ bias)
{
    extern __shared__ __align__(16) uint4 gsm4[];
    const int tid = threadIdx.x;
    const int wid = tid >> 5, lane = tid & 31;
    const int warp_row = (wid & 3) * 32;
    const int l4 = lane >> 2, lk = lane & 3;

    for (int tile = blockIdx.x; tile < 8 * 64; tile += gridDim.x) {
        const int mtile = tile >> 3;
        const int ntile = tile & 7;
        const int m0 = mtile * 128, n0 = ntile * 128;

        gemm_core((const uint4*)g_oph, (const uint4*)g_woph, mtile, ntile, gsm4,
            [&](float (&acc)[2][8][4]) {
                const int r0 = m0 + warp_row + l4;
                const int c0 = n0 + (wid >> 2) * 64 + lk * 2;
                #pragma unroll
                for (int f = 0; f < 2; f++) {
                    #pragma unroll
                    for (int g = 0; g < 8; g++) {
                        const int n = c0 + g * 8;
                        #pragma unroll
                        for (int half_ = 0; half_ < 2; half_++) {
                            const int m = r0 + f * 16 + half_ * 8;
                            float2 v;
                            v.x = acc[f][g][half_ * 2 + 0] + bias[n];
                            v.y = acc[f][g][half_ * 2 + 1] + bias[n + 1];
                            *(float2*)&Cout[(size_t)m * DIM_ + n] = v;
                        }
                    }
                }
            });
    }
}

// ---------------------------------------------------------------------------
// Flash attention fp16, persistent grid-stride over 1024 (rb-desc, bh) items.
// ---------------------------------------------------------------------------
#define FL_BYTES (2048 * 16)   // 32768

__global__ void __launch_bounds__(256, 2) flash2_k()
{
    extern __shared__ __align__(16) uint4 smv4[];
    const int tid = threadIdx.x;
    const int wid = tid >> 5, lane = tid & 31;
    const int l4 = lane >> 2, lk = lane & 3;
    const uint32_t smb = smem_u32(smv4);

    for (int w = blockIdx.x; w < 1024; w += gridDim.x) {
        const int rb = 15 - (w >> 6);       // big tiles first
        const int bh = w & 63;
        const int m0 = rb * 128;
        const int R0 = m0 + wid * 16;

        asm volatile("cp.async.wait_group 0;" ::: "memory");
        __syncthreads();    // smem reuse across items

        uint32_t aq[4][4];
        {
            const uint4* qsrc = (const uint4*)g_qph + ((size_t)(bh * 128 + (R0 >> 4))) * 128;
            #pragma unroll
            for (int kt = 0; kt < 4; kt++) {
                uint4 a4 = qsrc[kt * 32 + lane];
                aq[kt][0] = a4.x; aq[kt][1] = a4.y; aq[kt][2] = a4.z; aq[kt][3] = a4.w;
            }
        }

        float o[8][4];
        #pragma unroll
        for (int dg = 0; dg < 8; dg++)
            #pragma unroll
            for (int i = 0; i < 4; i++) o[dg][i] = 0.f;
        float mr0 = -1e30f, mr1 = -1e30f, lr0 = 0.f, lr1 = 0.f;

        const int ntiles = 2 * rb + 2;

        auto load_tile = [&](int t, int s) {
            const uint4* ksrc = (const uint4*)g_kph + ((size_t)(bh * 32 + t)) * 512;
            const uint4* vsrc = (const uint4*)g_vph + ((size_t)(bh * 32 + t)) * 512;
            const uint32_t kd = smb + (uint32_t)(s * 512) * 16;
            const uint32_t vd = smb + (uint32_t)(1024 + s * 512) * 16;
            #pragma unroll
            for (int i = 0; i < 2; i++) {
                const int off = tid + i * 256;
                asm volatile("cp.async.cg.shared.global [%0], [%1], 16;"
                             :: "r"(kd + (uint32_t)off * 16), "l"(ksrc + off));
                asm volatile("cp.async.cg.shared.global [%0], [%1], 16;"
                             :: "r"(vd + (uint32_t)off * 16), "l"(vsrc + off));
            }
        };

        load_tile(0, 0);
        asm volatile("cp.async.commit_group;" ::: "memory");
        load_tile(1, 1);
        asm volatile("cp.async.commit_group;" ::: "memory");

        const int row0 = R0 + l4;
        const int row1 = R0 + l4 + 8;

        for (int t = 0; t < ntiles; t++) {
            const int s = t & 1;
            asm volatile("cp.async.wait_group 1;" ::: "memory");
            __syncthreads();

            if (t * 64 <= R0 + 15) {
                const uint4* Ksm = smv4 + s * 512;
                const uint4* Vsm = smv4 + 1024 + s * 512;
                #pragma unroll
                for (int jc = 0; jc < 2; jc++) {
                    const int j0c = t * 64 + jc * 32;
                    if (j0c > R0 + 15) break;

                    float s4[4][4];
                    #pragma unroll
                    for (int jg = 0; jg < 4; jg++)
                        #pragma unroll
                        for (int i = 0; i < 4; i++) s4[jg][i] = 0.f;
                    #pragma unroll
                    for (int kt = 0; kt < 4; kt++) {
                        #pragma unroll
                        for (int pr = 0; pr < 2; pr++) {
                            uint4 b4 = Ksm[(kt * 4 + jc * 2 + pr) * 32 + lane];
                            MMA_F16(s4[2 * pr],     aq[kt], b4.x, b4.y);
                            MMA_F16(s4[2 * pr + 1], aq[kt], b4.z, b4.w);
                        }
                    }

                    if (j0c + 31 > R0) {
                        #pragma unroll
                        for (int jg = 0; jg < 4; jg++) {
                            const int jb = j0c + jg * 8 + 2 * lk;
                            if (jb     > row0) s4[jg][0] = -1e30f;
                            if (jb + 1 > row0) s4[jg][1] = -1e30f;
                            if (jb     > row1) s4[jg][2] = -1e30f;
                            if (jb + 1 > row1) s4[jg][3] = -1e30f;
                        }
                    }

                    float mx0 = -1e30f, mx1 = -1e30f;
                    #pragma unroll
                    for (int jg = 0; jg < 4; jg++) {
                        mx0 = fmaxf(mx0, fmaxf(s4[jg][0], s4[jg][1]));
                        mx1 = fmaxf(mx1, fmaxf(s4[jg][2], s4[jg][3]));
                    }
                    mx0 = fmaxf(mx0, __shfl_xor_sync(0xffffffffu, mx0, 1));
                    mx0 = fmaxf(mx0, __shfl_xor_sync(0xffffffffu, mx0, 2));
                    mx1 = fmaxf(mx1, __shfl_xor_sync(0xffffffffu, mx1, 1));
                    mx1 = fmaxf(mx1, __shfl_xor_sync(0xffffffffu, mx1, 2));

                    const float mn0 = fmaxf(mr0, mx0);
                    const float mn1 = fmaxf(mr1, mx1);
                    const float a0 = __expf(mr0 - mn0);
                    const float a1 = __expf(mr1 - mn1);
                    mr0 = mn0; mr1 = mn1;

                    float sum0 = 0.f, sum1 = 0.f;
                    float p[4][4];
                    #pragma unroll
                    for (int jg = 0; jg < 4; jg++) {
                        p[jg][0] = __expf(s4[jg][0] - mn0);
                        p[jg][1] = __expf(s4[jg][1] - mn0);
                        p[jg][2] = __expf(s4[jg][2] - mn1);
                        p[jg][3] = __expf(s4[jg][3] - mn1);
                        sum0 += p[jg][0] + p[jg][1];
                        sum1 += p[jg][2] + p[jg][3];
                    }
                    sum0 += __shfl_xor_sync(0xffffffffu, sum0, 1);
                    sum0 += __shfl_xor_sync(0xffffffffu, sum0, 2);
                    sum1 += __shfl_xor_sync(0xffffffffu, sum1, 1);
                    sum1 += __shfl_xor_sync(0xffffffffu, sum1, 2);
                    lr0 = lr0 * a0 + sum0;
                    lr1 = lr1 * a1 + sum1;

                    #pragma unroll
                    for (int dg = 0; dg < 8; dg++) {
                        o[dg][0] *= a0; o[dg][1] *= a0;
                        o[dg][2] *= a1; o[dg][3] *= a1;
                    }

                    uint32_t pa[2][4];
                    #pragma unroll
                    for (int kc = 0; kc < 2; kc++) {
                        pa[kc][0] = h2u(p[2 * kc][0],     p[2 * kc][1]);
                        pa[kc][1] = h2u(p[2 * kc][2],     p[2 * kc][3]);
                        pa[kc][2] = h2u(p[2 * kc + 1][0], p[2 * kc + 1][1]);
                        pa[kc][3] = h2u(p[2 * kc + 1][2], p[2 * kc + 1][3]);
                    }

                    #pragma unroll
                    for (int kc = 0; kc < 2; kc++) {
                        #pragma unroll
                        for (int pd = 0; pd < 4; pd++) {
                            uint4 b4 = Vsm[((jc * 2 + kc) * 4 + pd) * 32 + lane];
                            MMA_F16(o[2 * pd],     pa[kc], b4.x, b4.y);
                            MMA_F16(o[2 * pd + 1], pa[kc], b4.z, b4.w);
                        }
                    }
                }
            }
            __syncthreads();
            if (t + 2 < ntiles) load_tile(t + 2, s);
            asm volatile("cp.async.commit_group;" ::: "memory");
        }

        // epilogue: O -> g_oph (A-frag pack)
        const float inv0 = 1.0f / lr0;
        const float inv1 = 1.0f / lr1;
        const int bq = bh >> 4, hq = bh & 15;
        #pragma unroll
        for (int dg = 0; dg < 8; dg++) {
            #pragma unroll
            for (int half_ = 0; half_ < 2; half_++) {
                const int row = half_ ? row1 : row0;
                const int m = (bq << 11) + row;
                const float v0 = (half_ ? o[dg][2] * inv1 : o[dg][0] * inv0);
                const float v1 = (half_ ? o[dg][3] * inv1 : o[dg][1] * inv0);
                const int col = dg * 8 + 2 * lk;
                const int k = (hq << 6) + col;
                const int mt = m >> 7, grp = (m >> 4) & 7, l4m = m & 7, rh = (m >> 3) & 1;
                const int kt = k >> 4, cc = k & 15;
                const int lkk = (cc & 7) >> 1, hi = (cc >> 3) & 1;
                const size_t idx = ((size_t)(mt * 64 + kt) * 8 + grp) * 128
                                 + (l4m * 4 + lkk) * 4 + rh + 2 * hi;
                reinterpret_cast<uint32_t*>(g_oph)[idx] = h2u(v0, v1);
            }
        }
    }
}

// ---------------------------------------------------------------------------
extern "C" void kernel_launch(void* const* d_in, const int* in_sizes, int n_in,
                              void* d_out, int out_size)
{
    const float* x   = (const float*)d_in[0];
    const float* Wq  = (const float*)d_in[1];
    const float* Wkv = (const float*)d_in[2];
    const float* Wo  = (const float*)d_in[3];
    const float* bo  = (const float*)d_in[4];
    float* out = (float*)d_out;

    static bool attr_done = false;
    if (!attr_done) {
        cudaFuncSetAttribute(proj_k,   cudaFuncAttributeMaxDynamicSharedMemorySize, P_SMEM);
        cudaFuncSetAttribute(outg_k,   cudaFuncAttributeMaxDynamicSharedMemorySize, P_SMEM);
        cudaFuncSetAttribute(flash2_k, cudaFuncAttributeMaxDynamicSharedMemorySize, FL_BYTES);
        attr_done = true;
    }

    dim3 blk(256);
    pack_all_k<<<6144, blk>>>(x, Wq, Wkv, Wo);
    proj_k<<<NCTA, blk, P_SMEM>>>();
    flash2_k<<<NCTA, blk, FL_BYTES>>>();
    outg_k<<<NCTA, blk, P_SMEM>>>(out, bo);
}